// round 1
// baseline (speedup 1.0000x reference)
#include <cuda_runtime.h>
#include <math.h>

#define BB   16            // batch
#define WWC  64            // channels
#define NX   64
#define NY   64
#define YHN  33            // rfft bins
#define TT   20            // time steps
#define NF   (NX*YHN)      // 2112 frequencies
#define BWN  (BB*WWC)      // 1024
#define TILE (NX*NY)       // 4096
#define LS   65            // smem line stride (bank-conflict-free)

// ---------------- device scratch (no runtime allocation allowed) ----------
static __device__ float  g_twr[64];
static __device__ float  g_twi[64];

static __device__ float  d_h [BWN*TILE];     // h state   [b][w][x][y]
static __device__ float  d_z [BWN*TILE];     // z gate
static __device__ float  d_g [BWN*TILE];     // r*h
static __device__ float2 d_A1 [BWN*YHN*NX];  // stage-1 fwd FFT out [bw][yh][x]
static __device__ float2 d_Hf [NF*BWN];      // freq-major [f][b*64+w]
static __device__ float2 d_F0 [NF*BWN];      // gemm out (z / nh)
static __device__ float2 d_F1 [NF*BWN];      // gemm out (r)
static __device__ float2 d_Ax0[BWN*YHN*NX];  // inv stage-1 out
static __device__ float2 d_Ax1[BWN*YHN*NX];
static __device__ float2 d_Wt [3][NF*WWC*WWC]; // transposed weights [f][w][o]

// ---------------- twiddles --------------------------------------------------
__global__ void k_init_tw() {
    int k = threadIdx.x;
    double a = 2.0 * 3.14159265358979323846 * (double)k / 64.0;
    g_twr[k] = (float)cos(a);
    g_twi[k] = (float)sin(a);
}

// serial 64-pt radix-2 DIT FFT on one smem "line" (thread-private line).
// sgn = -1 forward, +1 inverse (unnormalized).
__device__ __forceinline__ void fft64_line(float* sr, float* si, int line,
                                           float sgn, const float* twr, const float* twi) {
    // bit-reversal permutation
    #pragma unroll 1
    for (int n = 1; n < 64; n++) {
        int r = (int)(__brev((unsigned)n) >> 26);
        if (r > n) {
            float a = sr[n*LS+line]; sr[n*LS+line] = sr[r*LS+line]; sr[r*LS+line] = a;
            float b = si[n*LS+line]; si[n*LS+line] = si[r*LS+line]; si[r*LS+line] = b;
        }
    }
    #pragma unroll
    for (int s = 0; s < 6; s++) {
        int half  = 1 << s;
        int m     = half << 1;
        int tstep = 64 >> (s + 1);
        #pragma unroll 8
        for (int j = 0; j < 32; j++) {
            int k  = j & (half - 1);
            int g  = j >> s;
            int i1 = g * m + k;
            int i2 = i1 + half;
            float wr = twr[k * tstep];
            float wi = sgn * twi[k * tstep];
            float ur = sr[i1*LS+line], ui = si[i1*LS+line];
            float vr = sr[i2*LS+line], vi = si[i2*LS+line];
            float tr = vr * wr - vi * wi;
            float ti = vr * wi + vi * wr;
            sr[i1*LS+line] = ur + tr;  si[i1*LS+line] = ui + ti;
            sr[i2*LS+line] = ur - tr;  si[i2*LS+line] = ui - ti;
        }
    }
}

// ---------------- weight transpose: [i][o][f] -> [f][i*64+o] float2 ---------
__global__ void k_wt(const float* __restrict__ wr, const float* __restrict__ wi, int gate) {
    __shared__ float s_r[64*LS];
    __shared__ float s_i[64*LS];
    int f0  = blockIdx.x * 64;      // 33 f-tiles
    int io0 = blockIdx.y * 64;      // 64 io-tiles
    int lane = threadIdx.x & 63;
    int row  = threadIdx.x >> 6;    // 0..3
    for (int r = row; r < 64; r += 4) {
        s_r[r*LS + lane] = wr[(size_t)(io0 + r) * NF + f0 + lane];
        s_i[r*LS + lane] = wi[(size_t)(io0 + r) * NF + f0 + lane];
    }
    __syncthreads();
    float2* out = d_Wt[gate];
    for (int fl = row; fl < 64; fl += 4) {
        out[(size_t)(f0 + fl) * 4096 + io0 + lane] =
            make_float2(s_r[lane*LS + fl], s_i[lane*LS + fl]);
    }
}

// ---------------- h0 = x @ Wi + bi  (CIN=1) ---------------------------------
__global__ void k_init_h(const float* __restrict__ x, const float* __restrict__ Wi,
                         const float* __restrict__ bi) {
    int idx = blockIdx.x * 256 + threadIdx.x;   // over BWN*TILE
    int bw = idx >> 12;
    int xy = idx & 4095;
    int b = bw >> 6, w = bw & 63;
    d_h[idx] = x[b * TILE + xy] * Wi[w] + bi[w];
}

// ---------------- forward FFT stage 1: rows (along y), keep 33 bins ---------
__global__ void k_fwd1(int srcSel) {   // 0: d_h, 1: d_g
    __shared__ float sr[64*LS];
    __shared__ float si[64*LS];
    __shared__ float twr[64], twi[64];
    int bw = blockIdx.x;
    int lane = threadIdx.x;            // 64 threads
    twr[lane] = g_twr[lane]; twi[lane] = g_twi[lane];
    const float* tile = (srcSel ? d_g : d_h) + (size_t)bw * TILE;
    for (int x = 0; x < 64; x++) {     // lane = y
        sr[lane*LS + x] = tile[x*64 + lane];
        si[lane*LS + x] = 0.f;
    }
    __syncthreads();
    fft64_line(sr, si, lane, -1.f, twr, twi);   // line = x
    __syncthreads();
    float2* out = d_A1 + (size_t)bw * (YHN*64);
    for (int yh = 0; yh < YHN; yh++)
        out[yh*64 + lane] = make_float2(sr[yh*LS + lane], si[yh*LS + lane]);
}

// ---------------- forward FFT stage 2: columns (along x) --------------------
__global__ void k_fwd2() {
    __shared__ float sr[64*LS];
    __shared__ float si[64*LS];
    __shared__ float twr[64], twi[64];
    int yh = blockIdx.x;               // 33
    int bw0 = blockIdx.y * 64;         // 16 chunks
    int lane = threadIdx.x;
    twr[lane] = g_twr[lane]; twi[lane] = g_twi[lane];
    for (int l = 0; l < 64; l++) {     // lane = x
        float2 v = d_A1[(size_t)(bw0 + l) * (YHN*64) + yh*64 + lane];
        sr[lane*LS + l] = v.x;
        si[lane*LS + l] = v.y;
    }
    __syncthreads();
    fft64_line(sr, si, lane, -1.f, twr, twi);   // line = bw local
    __syncthreads();
    for (int x = 0; x < 64; x++)
        d_Hf[(size_t)(x*YHN + yh) * BWN + bw0 + lane] =
            make_float2(sr[x*LS + lane], si[x*LS + lane]);
}

// ---------------- per-frequency complex GEMM: O = H x W ---------------------
// pass 0: gate=blockIdx.y selects (Wt0 -> F0) / (Wt1 -> F1).  pass 1: Wt2 -> F0.
__global__ void k_gemm(int pass) {
    int f = blockIdx.x;
    int gate = blockIdx.y;
    const float2* Wt = (pass == 0) ? d_Wt[gate] : d_Wt[2];
    float2* O = (pass == 0 && gate == 1) ? d_F1 : d_F0;

    __shared__ __align__(16) float2 Hs[WWC*BB];  // [w][b]  8KB
    __shared__ float2 Ws[WWC*WWC];               // [w][o] 32KB
    int tid = threadIdx.x;                       // 128

    const float2* Hsrc = d_Hf + (size_t)f * BWN;
    for (int i = tid; i < BWN; i += 128) {
        int b = i >> 6, w = i & 63;
        Hs[w*BB + b] = Hsrc[i];
    }
    const float2* Wsrc = Wt + (size_t)f * (WWC*WWC);
    for (int i = tid; i < WWC*WWC; i += 128) Ws[i] = Wsrc[i];
    __syncthreads();

    int og = tid & 31;
    int bg = (tid >> 5) * 4;
    float ar[2][4], ai[2][4];
    #pragma unroll
    for (int o = 0; o < 2; o++)
        #pragma unroll
        for (int b = 0; b < 4; b++) { ar[o][b] = 0.f; ai[o][b] = 0.f; }

    #pragma unroll 4
    for (int w = 0; w < 64; w++) {
        float4 h01 = *reinterpret_cast<const float4*>(&Hs[w*BB + bg]);
        float4 h23 = *reinterpret_cast<const float4*>(&Hs[w*BB + bg + 2]);
        float2 w0 = Ws[w*64 + og];
        float2 w1 = Ws[w*64 + og + 32];
        float hr[4] = {h01.x, h01.z, h23.x, h23.z};
        float hi[4] = {h01.y, h01.w, h23.y, h23.w};
        #pragma unroll
        for (int b = 0; b < 4; b++) {
            ar[0][b] += hr[b]*w0.x - hi[b]*w0.y;
            ai[0][b] += hr[b]*w0.y + hi[b]*w0.x;
            ar[1][b] += hr[b]*w1.x - hi[b]*w1.y;
            ai[1][b] += hr[b]*w1.y + hi[b]*w1.x;
        }
    }
    #pragma unroll
    for (int oi = 0; oi < 2; oi++) {
        int o = og + oi*32;
        #pragma unroll
        for (int b = 0; b < 4; b++)
            O[(size_t)f * BWN + (bg + b)*64 + o] = make_float2(ar[oi][b], ai[oi][b]);
    }
}

// ---------------- inverse FFT stage 1: along x ------------------------------
__global__ void k_inv1() {
    __shared__ float sr[64*LS];
    __shared__ float si[64*LS];
    __shared__ float twr[64], twi[64];
    int yh = blockIdx.x;
    int bw0 = blockIdx.y * 64;
    const float2* F = blockIdx.z ? d_F1 : d_F0;
    float2* A = blockIdx.z ? d_Ax1 : d_Ax0;
    int lane = threadIdx.x;
    twr[lane] = g_twr[lane]; twi[lane] = g_twi[lane];
    for (int x = 0; x < 64; x++) {     // lane = bw local
        float2 v = F[(size_t)(x*YHN + yh) * BWN + bw0 + lane];
        sr[x*LS + lane] = v.x;
        si[x*LS + lane] = v.y;
    }
    __syncthreads();
    fft64_line(sr, si, lane, +1.f, twr, twi);   // inverse along x, unnormalized
    __syncthreads();
    for (int l = 0; l < 64; l++)       // lane = x
        A[(size_t)(bw0 + l) * (YHN*64) + yh*64 + lane] =
            make_float2(sr[lane*LS + l], si[lane*LS + l]);
}

// ---------------- inverse FFT stage 2: along y (c2r) + GRU pointwise --------
// variant 0: z = sigmoid(v)
// variant 1: g = sigmoid(v) * h
// variant 2: h = (1-z)*h + z*tanh(v)
__global__ void k_inv2(int variant) {
    __shared__ float sr[64*LS];
    __shared__ float si[64*LS];
    __shared__ float twr[64], twi[64];
    int bo = blockIdx.x;
    int var = (variant < 0) ? (int)blockIdx.y : variant;  // -1: z/r combined via blockIdx.y
    const float2* A = (var == 1) ? d_Ax1 : d_Ax0;
    int lane = threadIdx.x;                 // lane = x = line
    twr[lane] = g_twr[lane]; twi[lane] = g_twi[lane];
    const float2* src = A + (size_t)bo * (YHN*64);
    #pragma unroll 1
    for (int yh = 0; yh < YHN; yh++) {
        float2 v = src[yh*64 + lane];
        sr[yh*LS + lane] = v.x;
        si[yh*LS + lane] = v.y;
    }
    // Hermitian extension along y-frequency (thread-private line)
    #pragma unroll 1
    for (int k = 33; k < 64; k++) {
        sr[k*LS + lane] =  sr[(64 - k)*LS + lane];
        si[k*LS + lane] = -si[(64 - k)*LS + lane];
    }
    fft64_line(sr, si, lane, +1.f, twr, twi);   // inverse along y
    __syncthreads();
    const float scale = 1.f / 4096.f;
    size_t base = (size_t)bo * TILE;
    for (int x = 0; x < 64; x++) {              // lane = y
        float v = sr[lane*LS + x] * scale;
        size_t idx = base + x*64 + lane;
        if (var == 0) {
            d_z[idx] = 1.f / (1.f + __expf(-v));
        } else if (var == 1) {
            float r = 1.f / (1.f + __expf(-v));
            d_g[idx] = r * d_h[idx];
        } else {
            float nh = tanhf(v);
            float h = d_h[idx];
            float z = d_z[idx];
            d_h[idx] = h + z * (nh - h);
        }
    }
}

// ---------------- out mapping: y = h @ Wo + bo ------------------------------
__global__ void k_out(const float* __restrict__ Wo, const float* __restrict__ bo,
                      float* __restrict__ out, int t) {
    int b = blockIdx.x;
    int xy = blockIdx.y * 256 + threadIdx.x;
    float acc = bo[0];
    const float* hb = d_h + (size_t)(b*64) * TILE + xy;
    #pragma unroll 8
    for (int w = 0; w < 64; w++)
        acc += hb[(size_t)w * TILE] * __ldg(&Wo[w]);
    out[(size_t)(b*TT + t) * TILE + xy] = acc;
}

// ---------------- launch ------------------------------------------------------
extern "C" void kernel_launch(void* const* d_in, const int* in_sizes, int n_in,
                              void* d_out, int out_size) {
    // input order per setup_inputs dict:
    // x, num_time_steps, Wi, bi, Wo, bo, Wz_r, Wz_i, Wr_r, Wr_i, Wh_r, Wh_i
    int iX = 0, iWi = 2, iBi = 3, iWo = 4, iBo = 5, iWz = 6;
    if (n_in == 11) { iWi = 1; iBi = 2; iWo = 3; iBo = 4; iWz = 5; } // no scalar variant

    const float* x    = (const float*)d_in[iX];
    const float* Wi   = (const float*)d_in[iWi];
    const float* bi   = (const float*)d_in[iBi];
    const float* Wo   = (const float*)d_in[iWo];
    const float* bo   = (const float*)d_in[iBo];
    const float* Wz_r = (const float*)d_in[iWz + 0];
    const float* Wz_i = (const float*)d_in[iWz + 1];
    const float* Wr_r = (const float*)d_in[iWz + 2];
    const float* Wr_i = (const float*)d_in[iWz + 3];
    const float* Wh_r = (const float*)d_in[iWz + 4];
    const float* Wh_i = (const float*)d_in[iWz + 5];
    float* out = (float*)d_out;

    k_init_tw<<<1, 64>>>();
    dim3 wtg(33, 64);
    k_wt<<<wtg, 256>>>(Wz_r, Wz_i, 0);
    k_wt<<<wtg, 256>>>(Wr_r, Wr_i, 1);
    k_wt<<<wtg, 256>>>(Wh_r, Wh_i, 2);
    k_init_h<<<(BWN*TILE)/256, 256>>>(x, Wi, bi);

    for (int t = 0; t < TT; t++) {
        // ---- z, r gates ----
        k_fwd1<<<BWN, 64>>>(0);                       // FFT rows of h
        k_fwd2<<<dim3(YHN, 16), 64>>>();              // FFT cols -> Hf
        k_gemm<<<dim3(NF, 2), 128>>>(0);              // z -> F0, r -> F1
        k_inv1<<<dim3(YHN, 16, 2), 64>>>();           // inverse x
        k_inv2<<<dim3(BWN, 2), 64>>>(-1);             // z -> d_z, g = r*h -> d_g
        // ---- candidate nh ----
        k_fwd1<<<BWN, 64>>>(1);                       // FFT rows of g
        k_fwd2<<<dim3(YHN, 16), 64>>>();
        k_gemm<<<dim3(NF, 1), 128>>>(1);              // nh -> F0
        k_inv1<<<dim3(YHN, 16, 1), 64>>>();
        k_inv2<<<BWN, 64>>>(2);                       // h update
        // ---- output ----
        k_out<<<dim3(BB, TILE/256), 256>>>(Wo, bo, out, t);
    }
}

// round 2
// speedup vs baseline: 1.3603x; 1.3603x over previous
#include <cuda_runtime.h>
#include <math.h>

#define BB   16
#define WWC  64
#define TT   20
#define YHN  33
#define NF   2112          // 64 * 33
#define BWN  1024          // BB * WWC
#define TILE 4096
#define LSC  65            // smem line stride

// ---------------- device scratch ------------------------------------------
static __device__ float  d_h [BWN*TILE];
static __device__ float  d_z [BWN*TILE];
static __device__ float  d_g [BWN*TILE];
static __device__ float2 d_A1 [(size_t)BWN*YHN*64];   // [bw][k][x]
static __device__ float2 d_Hf [(size_t)NF*BWN];       // [f][bw]
static __device__ float2 d_F0 [(size_t)NF*BWN];
static __device__ float2 d_F1 [(size_t)NF*BWN];
static __device__ float2 d_Ax0[(size_t)BWN*YHN*64];   // [bw][k][x]
static __device__ float2 d_Ax1[(size_t)BWN*YHN*64];
static __device__ float2 d_Wt [3][(size_t)NF*WWC*WWC]; // [f][w*64+o]

// ---------------- compile-time twiddles ------------------------------------
__device__ __host__ constexpr float TWQ_(int i) {
    constexpr float q[17] = {
        1.000000000f, 0.995184727f, 0.980785280f, 0.956940336f,
        0.923879533f, 0.881921264f, 0.831469612f, 0.773010453f,
        0.707106781f, 0.634393284f, 0.555570233f, 0.471396737f,
        0.382683432f, 0.290284677f, 0.195090322f, 0.098017140f, 0.f };
    return q[i];
}
__device__ __host__ constexpr float twcos(int j) {   // cos(2*pi*j/64)
    j &= 63;
    if (j <= 16) return TWQ_(j);
    if (j <= 32) return -TWQ_(32 - j);
    if (j <= 48) return -TWQ_(j - 32);
    return TWQ_(64 - j);
}
__device__ __host__ constexpr float twsin(int j) {   // sin(2*pi*j/64)
    return twcos(j + 48);
}
__device__ __host__ constexpr int bitrev6(int n) {
    return ((n&1)<<5)|((n&2)<<3)|((n&4)<<1)|((n&8)>>1)|((n&16)>>3)|((n&32)>>5);
}

// fully unrolled 64-pt radix-2 DIT FFT on register arrays.
// SGN = -1 forward, +1 inverse (unnormalized).
template<int SGN>
__device__ __forceinline__ void fft64r(float* xr, float* xi) {
    #pragma unroll
    for (int n = 1; n < 64; n++) {
        int r = bitrev6(n);
        if (r > n) {
            float a = xr[n]; xr[n] = xr[r]; xr[r] = a;
            float b = xi[n]; xi[n] = xi[r]; xi[r] = b;
        }
    }
    #pragma unroll
    for (int s = 0; s < 6; s++) {
        const int half = 1 << s;
        #pragma unroll
        for (int j = 0; j < 32; j++) {
            const int k  = j & (half - 1);
            const int g  = j >> s;
            const int i1 = g * (half << 1) + k;
            const int i2 = i1 + half;
            const float wr = twcos(k << (5 - s));
            const float wi = (float)SGN * twsin(k << (5 - s));
            float vr = xr[i2], vi = xi[i2];
            float tr = vr * wr - vi * wi;
            float ti = vr * wi + vi * wr;
            float ur = xr[i1], ui = xi[i1];
            xr[i1] = ur + tr;  xi[i1] = ui + ti;
            xr[i2] = ur - tr;  xi[i2] = ui - ti;
        }
    }
}

// ---------------- weight transpose: [i][o][f] -> [f][i*64+o] ----------------
__global__ void k_wt(const float* __restrict__ wr, const float* __restrict__ wi, int gate) {
    __shared__ float s_r[64*LSC];
    __shared__ float s_i[64*LSC];
    int f0  = blockIdx.x * 64;
    int io0 = blockIdx.y * 64;
    int lane = threadIdx.x & 63;
    int row  = threadIdx.x >> 6;
    #pragma unroll
    for (int r = row; r < 64; r += 4) {
        s_r[r*LSC + lane] = wr[(size_t)(io0 + r) * NF + f0 + lane];
        s_i[r*LSC + lane] = wi[(size_t)(io0 + r) * NF + f0 + lane];
    }
    __syncthreads();
    float2* out = d_Wt[gate];
    #pragma unroll
    for (int fl = row; fl < 64; fl += 4) {
        out[(size_t)(f0 + fl) * 4096 + io0 + lane] =
            make_float2(s_r[lane*LSC + fl], s_i[lane*LSC + fl]);
    }
}

// ---------------- h0 = x @ Wi + bi (CIN=1) ----------------------------------
__global__ void k_init_h(const float* __restrict__ x, const float* __restrict__ Wi,
                         const float* __restrict__ bi) {
    int idx = blockIdx.x * 256 + threadIdx.x;
    int bw = idx >> 12;
    int xy = idx & 4095;
    int b = bw >> 6, w = bw & 63;
    d_h[idx] = x[b * TILE + xy] * Wi[w] + bi[w];
}

// ---------------- forward FFT stage 1: along y (keep 33 bins) ---------------
__global__ void k_fwd1(int srcSel) {
    __shared__ float sx[64*LSC];
    int bw = blockIdx.x, t = threadIdx.x;   // 64 threads
    const float* tile = (srcSel ? d_g : d_h) + (size_t)bw * TILE;
    #pragma unroll
    for (int i = 0; i < 64; i++)
        sx[i*LSC + t] = tile[i*64 + t];          // coalesced, conflict-free
    __syncthreads();
    float xr[64], xi[64];
    #pragma unroll
    for (int y = 0; y < 64; y++) { xr[y] = sx[t*LSC + y]; xi[y] = 0.f; }
    fft64r<-1>(xr, xi);
    float2* out = d_A1 + (size_t)bw * YHN * 64;
    #pragma unroll
    for (int k = 0; k < YHN; k++)
        out[k*64 + t] = make_float2(xr[k], xi[k]);   // 512B coalesced per k
}

// ---------------- forward FFT stage 2: along x -> Hf[f][bw] -----------------
__global__ void k_fwd2() {
    __shared__ float sr[64*LSC], si[64*LSC];
    int k = blockIdx.x;               // 0..32
    int bw0 = blockIdx.y * 64;
    int t = threadIdx.x;
    #pragma unroll 8
    for (int j = 0; j < 64; j++) {    // coalesced over t (x)
        float2 v = d_A1[((size_t)(bw0 + j) * YHN + k) * 64 + t];
        sr[j*LSC + t] = v.x; si[j*LSC + t] = v.y;
    }
    __syncthreads();
    float xr[64], xi[64];
    #pragma unroll
    for (int x = 0; x < 64; x++) { xr[x] = sr[t*LSC + x]; xi[x] = si[t*LSC + x]; }
    fft64r<-1>(xr, xi);
    #pragma unroll
    for (int x = 0; x < 64; x++)      // coalesced over t (bw)
        d_Hf[((size_t)x * YHN + k) * BWN + bw0 + t] = make_float2(xr[x], xi[x]);
}

// ---------------- per-frequency complex GEMM --------------------------------
__global__ void k_gemm(int pass) {
    int f = blockIdx.x;
    int gate = blockIdx.y;
    const float2* Wt = (pass == 0) ? d_Wt[gate] : d_Wt[2];
    float2* O = (pass == 0 && gate == 1) ? d_F1 : d_F0;

    __shared__ __align__(16) float2 Hs[WWC*BB];
    __shared__ __align__(16) float2 Ws[WWC*WWC];
    int tid = threadIdx.x;            // 128

    const float2* Hsrc = d_Hf + (size_t)f * BWN;
    #pragma unroll
    for (int i = tid; i < BWN; i += 128) {
        int b = i >> 6, w = i & 63;
        Hs[w*BB + b] = Hsrc[i];
    }
    const float4* Wsrc = reinterpret_cast<const float4*>(Wt + (size_t)f * (WWC*WWC));
    float4* Wdst = reinterpret_cast<float4*>(Ws);
    #pragma unroll
    for (int i = tid; i < WWC*WWC/2; i += 128) Wdst[i] = Wsrc[i];
    __syncthreads();

    int og = tid & 31;
    int bg = (tid >> 5) * 4;
    float ar[2][4], ai[2][4];
    #pragma unroll
    for (int o = 0; o < 2; o++)
        #pragma unroll
        for (int b = 0; b < 4; b++) { ar[o][b] = 0.f; ai[o][b] = 0.f; }

    #pragma unroll 4
    for (int w = 0; w < 64; w++) {
        float4 h01 = *reinterpret_cast<const float4*>(&Hs[w*BB + bg]);
        float4 h23 = *reinterpret_cast<const float4*>(&Hs[w*BB + bg + 2]);
        float2 w0 = Ws[w*64 + og];
        float2 w1 = Ws[w*64 + og + 32];
        float hr[4] = {h01.x, h01.z, h23.x, h23.z};
        float hi[4] = {h01.y, h01.w, h23.y, h23.w};
        #pragma unroll
        for (int b = 0; b < 4; b++) {
            ar[0][b] += hr[b]*w0.x - hi[b]*w0.y;
            ai[0][b] += hr[b]*w0.y + hi[b]*w0.x;
            ar[1][b] += hr[b]*w1.x - hi[b]*w1.y;
            ai[1][b] += hr[b]*w1.y + hi[b]*w1.x;
        }
    }
    #pragma unroll
    for (int oi = 0; oi < 2; oi++) {
        int o = og + oi*32;
        #pragma unroll
        for (int b = 0; b < 4; b++)
            O[(size_t)f * BWN + (bg + b)*64 + o] = make_float2(ar[oi][b], ai[oi][b]);
    }
}

// ---------------- inverse FFT stage 1: along x ------------------------------
__global__ void k_inv1() {
    __shared__ float sr[64*LSC], si[64*LSC];
    int k = blockIdx.x;
    int bw0 = blockIdx.y * 64;
    int t = threadIdx.x;
    const float2* F = blockIdx.z ? d_F1 : d_F0;
    float2* A = blockIdx.z ? d_Ax1 : d_Ax0;
    float xr[64], xi[64];
    #pragma unroll 8
    for (int x = 0; x < 64; x++) {    // coalesced over t (bw)
        float2 v = F[((size_t)x * YHN + k) * BWN + bw0 + t];
        xr[x] = v.x; xi[x] = v.y;
    }
    fft64r<1>(xr, xi);
    #pragma unroll
    for (int x = 0; x < 64; x++) { sr[t*LSC + x] = xr[x]; si[t*LSC + x] = xi[x]; }
    __syncthreads();
    #pragma unroll 8
    for (int j = 0; j < 64; j++)      // coalesced over t (x)
        A[((size_t)(bw0 + j) * YHN + k) * 64 + t] =
            make_float2(sr[j*LSC + t], si[j*LSC + t]);
}

// ---------------- inverse FFT stage 2: along y (c2r) + GRU pointwise --------
// var 0: z = sigmoid(v);  var 1: g = sigmoid(v)*h;  var 2: h = (1-z)h + z*tanh(v)
__global__ void k_inv2(int variant) {
    __shared__ float sr[YHN*LSC], si[YHN*LSC];
    __shared__ float so[64*LSC];
    int bw = blockIdx.x;
    int var = (variant < 0) ? (int)blockIdx.y : variant;
    int t = threadIdx.x;
    const float2* A = (var == 1 ? d_Ax1 : d_Ax0) + (size_t)bw * YHN * 64;
    #pragma unroll
    for (int i = 0; i < YHN; i++) {   // coalesced
        float2 v = A[i*64 + t];
        sr[i*LSC + t] = v.x; si[i*LSC + t] = v.y;
    }
    __syncthreads();
    float xr[64], xi[64];
    #pragma unroll
    for (int kk = 0; kk < YHN; kk++) { xr[kk] = sr[kk*LSC + t]; xi[kk] = si[kk*LSC + t]; }
    #pragma unroll
    for (int kk = YHN; kk < 64; kk++) { xr[kk] = xr[64-kk]; xi[kk] = -xi[64-kk]; }
    fft64r<1>(xr, xi);
    #pragma unroll
    for (int y = 0; y < 64; y++) so[t*LSC + y] = xr[y];
    __syncthreads();
    const float sc = 1.f / 4096.f;
    size_t base = (size_t)bw * TILE;
    #pragma unroll 4
    for (int i = 0; i < 64; i++) {    // coalesced
        float v = so[i*LSC + t] * sc;
        size_t idx = base + i*64 + t;
        if (var == 0) {
            d_z[idx] = 1.f / (1.f + __expf(-v));
        } else if (var == 1) {
            d_g[idx] = d_h[idx] / (1.f + __expf(-v));
        } else {
            float nh = tanhf(v);
            float h = d_h[idx];
            float z = d_z[idx];
            d_h[idx] = h + z * (nh - h);
        }
    }
}

// ---------------- out mapping: y = h @ Wo + bo ------------------------------
__global__ void k_out(const float* __restrict__ Wo, const float* __restrict__ bo,
                      float* __restrict__ out, int t) {
    int b = blockIdx.x;
    int xy = blockIdx.y * 256 + threadIdx.x;
    float acc = bo[0];
    const float* hb = d_h + (size_t)(b*64) * TILE + xy;
    #pragma unroll 8
    for (int w = 0; w < 64; w++)
        acc += hb[(size_t)w * TILE] * __ldg(&Wo[w]);
    out[(size_t)(b*TT + t) * TILE + xy] = acc;
}

// ---------------- launch -----------------------------------------------------
extern "C" void kernel_launch(void* const* d_in, const int* in_sizes, int n_in,
                              void* d_out, int out_size) {
    int iX = 0, iWi = 2, iBi = 3, iWo = 4, iBo = 5, iWz = 6;
    if (n_in == 11) { iWi = 1; iBi = 2; iWo = 3; iBo = 4; iWz = 5; }

    const float* x    = (const float*)d_in[iX];
    const float* Wi   = (const float*)d_in[iWi];
    const float* bi   = (const float*)d_in[iBi];
    const float* Wo   = (const float*)d_in[iWo];
    const float* bo   = (const float*)d_in[iBo];
    const float* Wz_r = (const float*)d_in[iWz + 0];
    const float* Wz_i = (const float*)d_in[iWz + 1];
    const float* Wr_r = (const float*)d_in[iWz + 2];
    const float* Wr_i = (const float*)d_in[iWz + 3];
    const float* Wh_r = (const float*)d_in[iWz + 4];
    const float* Wh_i = (const float*)d_in[iWz + 5];
    float* out = (float*)d_out;

    dim3 wtg(33, 64);
    k_wt<<<wtg, 256>>>(Wz_r, Wz_i, 0);
    k_wt<<<wtg, 256>>>(Wr_r, Wr_i, 1);
    k_wt<<<wtg, 256>>>(Wh_r, Wh_i, 2);
    k_init_h<<<(BWN*TILE)/256, 256>>>(x, Wi, bi);

    for (int t = 0; t < TT; t++) {
        // ---- z, r gates ----
        k_fwd1<<<BWN, 64>>>(0);
        k_fwd2<<<dim3(YHN, 16), 64>>>();
        k_gemm<<<dim3(NF, 2), 128>>>(0);
        k_inv1<<<dim3(YHN, 16, 2), 64>>>();
        k_inv2<<<dim3(BWN, 2), 64>>>(-1);
        // ---- candidate nh ----
        k_fwd1<<<BWN, 64>>>(1);
        k_fwd2<<<dim3(YHN, 16), 64>>>();
        k_gemm<<<dim3(NF, 1), 128>>>(1);
        k_inv1<<<dim3(YHN, 16, 1), 64>>>();
        k_inv2<<<BWN, 64>>>(2);
        // ---- output ----
        k_out<<<dim3(BB, TILE/256), 256>>>(Wo, bo, out, t);
    }
}

// round 3
// speedup vs baseline: 1.4903x; 1.0956x over previous
#include <cuda_runtime.h>
#include <math.h>

#define BB   16
#define WWC  64
#define TT   20
#define YHN  33
#define NF   2112          // 64 * 33
#define BWN  1024          // BB * WWC
#define TILE 4096
#define HS_LS 18           // Hs smem stride (even -> 8B aligned, 2-way max conflict)

typedef unsigned long long u64x;

// ---------------- device scratch ------------------------------------------
static __device__ float  d_h [BWN*TILE];
static __device__ float  d_z [BWN*TILE];
static __device__ float2 d_A1 [(size_t)BWN*YHN*64];    // [bw][k][x]
static __device__ float2 d_Hf [(size_t)NF*BWN];        // [f=(x*33+k)][bw]
static __device__ float2 d_F0 [(size_t)NF*BWN];
static __device__ float2 d_F1 [(size_t)NF*BWN];
static __device__ float2 d_Ax0[(size_t)BWN*YHN*64];    // [bw][k][x]
static __device__ float2 d_Ax1[(size_t)BWN*YHN*64];
static __device__ float2 d_Wt [3][(size_t)NF*WWC*WWC]; // [f][w*64+o]

// ---------------- f32x2 packed helpers --------------------------------------
__device__ __forceinline__ u64x pk2(float lo, float hi) {
    u64x r; asm("mov.b64 %0,{%1,%2};" : "=l"(r) : "f"(lo), "f"(hi)); return r;
}
__device__ __forceinline__ void upk2(u64x v, float& lo, float& hi) {
    asm("mov.b64 {%0,%1},%2;" : "=f"(lo), "=f"(hi) : "l"(v));
}
#define FMA2(a,b,c) asm("fma.rn.f32x2 %0,%1,%2,%0;" : "+l"(c) : "l"(a), "l"(b))

// ---------------- compile-time twiddles ------------------------------------
__device__ __host__ constexpr float TWQ_(int i) {
    constexpr float q[17] = {
        1.000000000f, 0.995184727f, 0.980785280f, 0.956940336f,
        0.923879533f, 0.881921264f, 0.831469612f, 0.773010453f,
        0.707106781f, 0.634393284f, 0.555570233f, 0.471396737f,
        0.382683432f, 0.290284677f, 0.195090322f, 0.098017140f, 0.f };
    return q[i];
}
__device__ __host__ constexpr float twcos(int j) {
    j &= 63;
    if (j <= 16) return TWQ_(j);
    if (j <= 32) return -TWQ_(32 - j);
    if (j <= 48) return -TWQ_(j - 32);
    return TWQ_(64 - j);
}
__device__ __host__ constexpr float twsin(int j) { return twcos(j + 48); }
__device__ __host__ constexpr int bitrev6(int n) {
    return ((n&1)<<5)|((n&2)<<3)|((n&4)<<1)|((n&8)>>1)|((n&16)>>3)|((n&32)>>5);
}

// fully unrolled 64-pt radix-2 DIT FFT on register arrays (SGN=-1 fwd, +1 inv)
template<int SGN>
__device__ __forceinline__ void fft64r(float* xr, float* xi) {
    #pragma unroll
    for (int n = 1; n < 64; n++) {
        int r = bitrev6(n);
        if (r > n) {
            float a = xr[n]; xr[n] = xr[r]; xr[r] = a;
            float b = xi[n]; xi[n] = xi[r]; xi[r] = b;
        }
    }
    #pragma unroll
    for (int s = 0; s < 6; s++) {
        const int half = 1 << s;
        #pragma unroll
        for (int j = 0; j < 32; j++) {
            const int k  = j & (half - 1);
            const int g  = j >> s;
            const int i1 = g * (half << 1) + k;
            const int i2 = i1 + half;
            const float wr = twcos(k << (5 - s));
            const float wi = (float)SGN * twsin(k << (5 - s));
            float vr = xr[i2], vi = xi[i2];
            float tr = vr * wr - vi * wi;
            float ti = vr * wi + vi * wr;
            float ur = xr[i1], ui = xi[i1];
            xr[i1] = ur + tr;  xi[i1] = ui + ti;
            xr[i2] = ur - tr;  xi[i2] = ui - ti;
        }
    }
}

__device__ __forceinline__ float sigm(float v) { return 1.f / (1.f + __expf(-v)); }
__device__ __forceinline__ float ftanh(float v) { return 2.f / (1.f + __expf(-2.f*v)) - 1.f; }

// ---------------- weight transpose: [i][o][f] -> [f][i*64+o] ----------------
__global__ void k_wt_all(const float* __restrict__ p0r, const float* __restrict__ p0i,
                         const float* __restrict__ p1r, const float* __restrict__ p1i,
                         const float* __restrict__ p2r, const float* __restrict__ p2i) {
    __shared__ float s_r[64*65];
    __shared__ float s_i[64*65];
    int gate = blockIdx.z;
    const float* wr = gate == 0 ? p0r : (gate == 1 ? p1r : p2r);
    const float* wi = gate == 0 ? p0i : (gate == 1 ? p1i : p2i);
    int f0  = blockIdx.x * 64;
    int io0 = blockIdx.y * 64;
    int lane = threadIdx.x & 63;
    int row  = threadIdx.x >> 6;
    #pragma unroll
    for (int r = row; r < 64; r += 4) {
        s_r[r*65 + lane] = wr[(size_t)(io0 + r) * NF + f0 + lane];
        s_i[r*65 + lane] = wi[(size_t)(io0 + r) * NF + f0 + lane];
    }
    __syncthreads();
    float2* out = d_Wt[gate];
    #pragma unroll
    for (int fl = row; fl < 64; fl += 4) {
        out[(size_t)(f0 + fl) * 4096 + io0 + lane] =
            make_float2(s_r[lane*65 + fl], s_i[lane*65 + fl]);
    }
}

// ---------------- h0 = x @ Wi + bi (CIN=1) ----------------------------------
__global__ void k_init_h(const float* __restrict__ x, const float* __restrict__ Wi,
                         const float* __restrict__ bi) {
    int idx = blockIdx.x * 256 + threadIdx.x;
    int bw = idx >> 12;
    int xy = idx & 4095;
    int b = bw >> 6, w = bw & 63;
    d_h[idx] = x[b * TILE + xy] * Wi[w] + bi[w];
}

// ---------------- prologue: y-FFT of h (thread t = x, dense row read) --------
__global__ void k_fwd1() {
    int bw = blockIdx.x, t = threadIdx.x;       // 64 threads
    const float4* row = reinterpret_cast<const float4*>(d_h + (size_t)bw * TILE + t*64);
    float xr[64], xi[64];
    #pragma unroll
    for (int j = 0; j < 16; j++) {
        float4 v = row[j];
        xr[j*4+0]=v.x; xr[j*4+1]=v.y; xr[j*4+2]=v.z; xr[j*4+3]=v.w;
    }
    #pragma unroll
    for (int y = 0; y < 64; y++) xi[y] = 0.f;
    fft64r<-1>(xr, xi);
    float2* out = d_A1 + (size_t)bw * YHN * 64;
    #pragma unroll
    for (int k = 0; k < YHN; k++)
        out[k*64 + t] = make_float2(xr[k], xi[k]);   // coalesced
}

// ---------------- x-FFT: d_A1[bw][k][x] -> d_Hf[f][bw] ----------------------
__global__ void k_fwd2() {
    int k = blockIdx.x;                // 0..32
    int bw = blockIdx.y * 64 + threadIdx.x;
    float xr[64], xi[64];
    const float4* src = reinterpret_cast<const float4*>(d_A1 + ((size_t)bw*YHN + k)*64);
    #pragma unroll
    for (int j = 0; j < 32; j++) {     // dense 512B per-thread row
        float4 v = src[j];
        xr[j*2] = v.x; xi[j*2] = v.y; xr[j*2+1] = v.z; xi[j*2+1] = v.w;
    }
    fft64r<-1>(xr, xi);
    int t = threadIdx.x, bw0 = blockIdx.y * 64;
    #pragma unroll
    for (int x = 0; x < 64; x++)       // coalesced over t
        d_Hf[((size_t)x*YHN + k)*BWN + bw0 + t] = make_float2(xr[x], xi[x]);
}

// ---------------- per-frequency complex GEMM (packed f32x2) -----------------
__global__ void k_gemm(int pass) {
    int f = blockIdx.x;
    int gate = blockIdx.y;
    const float2* Wt = (pass == 0) ? d_Wt[gate] : d_Wt[2];
    float2* O = (pass == 0 && gate == 1) ? d_F1 : d_F0;

    __shared__ __align__(16) float Hsr[64*HS_LS];
    __shared__ __align__(16) float Hsi[64*HS_LS];
    __shared__ __align__(16) float2 Ws[64*64];
    int tid = threadIdx.x;             // 128

    const float2* Hsrc = d_Hf + (size_t)f * BWN;
    #pragma unroll
    for (int i = tid; i < BWN; i += 128) {
        float2 v = Hsrc[i];
        int b = i >> 6, w = i & 63;
        Hsr[w*HS_LS + b] = v.x;
        Hsi[w*HS_LS + b] = v.y;
    }
    const float4* Wsrc = reinterpret_cast<const float4*>(Wt + (size_t)f * 4096);
    float4* Wdst = reinterpret_cast<float4*>(Ws);
    #pragma unroll
    for (int i = tid; i < 2048; i += 128) Wdst[i] = Wsrc[i];
    __syncthreads();

    int og = tid & 31;
    int bg = (tid >> 5) * 4;           // 4 batches = 2 packed pairs
    u64x ar[2][2] = {{0,0},{0,0}};
    u64x ai[2][2] = {{0,0},{0,0}};

    #pragma unroll 8
    for (int w = 0; w < 64; w++) {
        u64x hr0 = *reinterpret_cast<const u64x*>(&Hsr[w*HS_LS + bg]);
        u64x hr1 = *reinterpret_cast<const u64x*>(&Hsr[w*HS_LS + bg + 2]);
        u64x hi0 = *reinterpret_cast<const u64x*>(&Hsi[w*HS_LS + bg]);
        u64x hi1 = *reinterpret_cast<const u64x*>(&Hsi[w*HS_LS + bg + 2]);
        float2 w0 = Ws[w*64 + og];
        float2 w1 = Ws[w*64 + og + 32];
        {
            u64x wr2 = pk2(w0.x, w0.x), wi2 = pk2(w0.y, w0.y), ni2 = pk2(-w0.y, -w0.y);
            FMA2(hr0, wr2, ar[0][0]); FMA2(hi0, ni2, ar[0][0]);
            FMA2(hr1, wr2, ar[0][1]); FMA2(hi1, ni2, ar[0][1]);
            FMA2(hr0, wi2, ai[0][0]); FMA2(hi0, wr2, ai[0][0]);
            FMA2(hr1, wi2, ai[0][1]); FMA2(hi1, wr2, ai[0][1]);
        }
        {
            u64x wr2 = pk2(w1.x, w1.x), wi2 = pk2(w1.y, w1.y), ni2 = pk2(-w1.y, -w1.y);
            FMA2(hr0, wr2, ar[1][0]); FMA2(hi0, ni2, ar[1][0]);
            FMA2(hr1, wr2, ar[1][1]); FMA2(hi1, ni2, ar[1][1]);
            FMA2(hr0, wi2, ai[1][0]); FMA2(hi0, wr2, ai[1][0]);
            FMA2(hr1, wi2, ai[1][1]); FMA2(hi1, wr2, ai[1][1]);
        }
    }
    #pragma unroll
    for (int oi = 0; oi < 2; oi++) {
        int o = og + oi*32;
        #pragma unroll
        for (int p = 0; p < 2; p++) {
            float r0, r1, i0, i1;
            upk2(ar[oi][p], r0, r1);
            upk2(ai[oi][p], i0, i1);
            O[(size_t)f * BWN + (bg + 2*p + 0)*64 + o] = make_float2(r0, i0);
            O[(size_t)f * BWN + (bg + 2*p + 1)*64 + o] = make_float2(r1, i1);
        }
    }
}

// ---------------- inverse x-FFT: d_F[f][bw] -> d_Ax[bw][k][x] ----------------
__global__ void k_inv1() {
    int k = blockIdx.x;
    int bw0 = blockIdx.y * 64;
    int t = threadIdx.x;
    const float2* F = blockIdx.z ? d_F1 : d_F0;
    float2* A = blockIdx.z ? d_Ax1 : d_Ax0;
    float xr[64], xi[64];
    #pragma unroll
    for (int x = 0; x < 64; x++) {     // coalesced over t
        float2 v = F[((size_t)x*YHN + k)*BWN + bw0 + t];
        xr[x] = v.x; xi[x] = v.y;
    }
    fft64r<1>(xr, xi);
    float4* dst = reinterpret_cast<float4*>(A + ((size_t)(bw0 + t)*YHN + k)*64);
    #pragma unroll
    for (int j = 0; j < 32; j++)       // dense 512B per-thread row
        dst[j] = make_float4(xr[j*2], xi[j*2], xr[j*2+1], xi[j*2+1]);
}

// ---------------- fused: z = sig(iFFT), g = sig(iFFT_r)*h, y-FFT(g) ----------
__global__ void k_fused_zr() {
    int bw = blockIdx.x, t = threadIdx.x;   // t = x
    float xr[64], xi[64];
    const float sc = 1.f / 4096.f;
    // ---- z gate ----
    const float2* A0 = d_Ax0 + (size_t)bw * YHN * 64;
    #pragma unroll
    for (int k = 0; k < YHN; k++) { float2 v = A0[k*64 + t]; xr[k] = v.x; xi[k] = v.y; }
    #pragma unroll
    for (int k = YHN; k < 64; k++) { xr[k] = xr[64-k]; xi[k] = -xi[64-k]; }
    fft64r<1>(xr, xi);
    float4* zrow = reinterpret_cast<float4*>(d_z + (size_t)bw * TILE + t*64);
    #pragma unroll
    for (int j = 0; j < 16; j++)
        zrow[j] = make_float4(sigm(xr[j*4]*sc),   sigm(xr[j*4+1]*sc),
                              sigm(xr[j*4+2]*sc), sigm(xr[j*4+3]*sc));
    // ---- r gate -> g = r*h -> forward y-FFT ----
    const float2* A1 = d_Ax1 + (size_t)bw * YHN * 64;
    #pragma unroll
    for (int k = 0; k < YHN; k++) { float2 v = A1[k*64 + t]; xr[k] = v.x; xi[k] = v.y; }
    #pragma unroll
    for (int k = YHN; k < 64; k++) { xr[k] = xr[64-k]; xi[k] = -xi[64-k]; }
    fft64r<1>(xr, xi);
    const float4* hrow = reinterpret_cast<const float4*>(d_h + (size_t)bw * TILE + t*64);
    #pragma unroll
    for (int j = 0; j < 16; j++) {
        float4 h4 = hrow[j];
        xr[j*4+0] = h4.x * sigm(xr[j*4+0]*sc);
        xr[j*4+1] = h4.y * sigm(xr[j*4+1]*sc);
        xr[j*4+2] = h4.z * sigm(xr[j*4+2]*sc);
        xr[j*4+3] = h4.w * sigm(xr[j*4+3]*sc);
    }
    #pragma unroll
    for (int y = 0; y < 64; y++) xi[y] = 0.f;
    fft64r<-1>(xr, xi);
    float2* out = d_A1 + (size_t)bw * YHN * 64;
    #pragma unroll
    for (int k = 0; k < YHN; k++)
        out[k*64 + t] = make_float2(xr[k], xi[k]);
}

// ---------------- fused: h = (1-z)h + z*tanh(iFFT), y-FFT(h) -----------------
__global__ void k_fused_h(int last) {
    int bw = blockIdx.x, t = threadIdx.x;
    float xr[64], xi[64];
    const float sc = 1.f / 4096.f;
    const float2* A0 = d_Ax0 + (size_t)bw * YHN * 64;
    #pragma unroll
    for (int k = 0; k < YHN; k++) { float2 v = A0[k*64 + t]; xr[k] = v.x; xi[k] = v.y; }
    #pragma unroll
    for (int k = YHN; k < 64; k++) { xr[k] = xr[64-k]; xi[k] = -xi[64-k]; }
    fft64r<1>(xr, xi);
    float4* hrow = reinterpret_cast<float4*>(d_h + (size_t)bw * TILE + t*64);
    const float4* zrow = reinterpret_cast<const float4*>(d_z + (size_t)bw * TILE + t*64);
    #pragma unroll
    for (int j = 0; j < 16; j++) {
        float4 h4 = hrow[j];
        float4 z4 = zrow[j];
        float n0 = ftanh(xr[j*4+0]*sc), n1 = ftanh(xr[j*4+1]*sc);
        float n2 = ftanh(xr[j*4+2]*sc), n3 = ftanh(xr[j*4+3]*sc);
        h4.x += z4.x * (n0 - h4.x);
        h4.y += z4.y * (n1 - h4.y);
        h4.z += z4.z * (n2 - h4.z);
        h4.w += z4.w * (n3 - h4.w);
        hrow[j] = h4;
        xr[j*4+0] = h4.x; xr[j*4+1] = h4.y; xr[j*4+2] = h4.z; xr[j*4+3] = h4.w;
    }
    if (!last) {
        #pragma unroll
        for (int y = 0; y < 64; y++) xi[y] = 0.f;
        fft64r<-1>(xr, xi);
        float2* out = d_A1 + (size_t)bw * YHN * 64;
        #pragma unroll
        for (int k = 0; k < YHN; k++)
            out[k*64 + t] = make_float2(xr[k], xi[k]);
    }
}

// ---------------- out mapping: y = h @ Wo + bo ------------------------------
__global__ void k_out(const float* __restrict__ Wo, const float* __restrict__ bo,
                      float* __restrict__ out, int t) {
    int b = blockIdx.x;
    int xy = blockIdx.y * 256 + threadIdx.x;
    float acc = bo[0];
    const float* hb = d_h + (size_t)(b*64) * TILE + xy;
    #pragma unroll 8
    for (int w = 0; w < 64; w++)
        acc += hb[(size_t)w * TILE] * __ldg(&Wo[w]);
    out[(size_t)(b*TT + t) * TILE + xy] = acc;
}

// ---------------- launch -----------------------------------------------------
extern "C" void kernel_launch(void* const* d_in, const int* in_sizes, int n_in,
                              void* d_out, int out_size) {
    int iX = 0, iWi = 2, iBi = 3, iWo = 4, iBo = 5, iWz = 6;
    if (n_in == 11) { iWi = 1; iBi = 2; iWo = 3; iBo = 4; iWz = 5; }

    const float* x    = (const float*)d_in[iX];
    const float* Wi   = (const float*)d_in[iWi];
    const float* bi   = (const float*)d_in[iBi];
    const float* Wo   = (const float*)d_in[iWo];
    const float* bo   = (const float*)d_in[iBo];
    float* out = (float*)d_out;

    k_wt_all<<<dim3(33, 64, 3), 256>>>((const float*)d_in[iWz+0], (const float*)d_in[iWz+1],
                                       (const float*)d_in[iWz+2], (const float*)d_in[iWz+3],
                                       (const float*)d_in[iWz+4], (const float*)d_in[iWz+5]);
    k_init_h<<<(BWN*TILE)/256, 256>>>(x, Wi, bi);
    k_fwd1<<<BWN, 64>>>();
    k_fwd2<<<dim3(YHN, 16), 64>>>();

    for (int t = 0; t < TT; t++) {
        k_gemm<<<dim3(NF, 2), 128>>>(0);           // z -> F0, r -> F1
        k_inv1<<<dim3(YHN, 16, 2), 64>>>();
        k_fused_zr<<<BWN, 64>>>();                 // z, g = r*h, y-FFT(g)
        k_fwd2<<<dim3(YHN, 16), 64>>>();           // x-FFT(g) -> Hf
        k_gemm<<<dim3(NF, 1), 128>>>(1);           // nh -> F0
        k_inv1<<<dim3(YHN, 16, 1), 64>>>();
        k_fused_h<<<BWN, 64>>>(t == TT-1);         // h update (+ y-FFT for next step)
        if (t < TT-1) k_fwd2<<<dim3(YHN, 16), 64>>>();
        k_out<<<dim3(BB, TILE/256), 256>>>(Wo, bo, out, t);
    }
}

// round 5
// speedup vs baseline: 1.7618x; 1.1821x over previous
#include <cuda_runtime.h>
#include <math.h>

#define BB   16
#define WWC  64
#define TT   20
#define YHN  33
#define NF   2112          // 64 * 33
#define BWN  1024          // BB * WWC
#define TILE 4096
#define HS_LS 18

typedef unsigned long long u64x;

// ---------------- device scratch ------------------------------------------
static __device__ float  d_h [BWN*TILE];
static __device__ float  d_z [BWN*TILE];
static __device__ float2 d_A1 [(size_t)BWN*YHN*64];    // [bw][k][x]
static __device__ float2 d_Hf [(size_t)NF*BWN];        // [f=(x*33+k)][bw]
static __device__ float2 d_F0 [(size_t)NF*BWN];
static __device__ float2 d_F1 [(size_t)NF*BWN];
static __device__ float2 d_Ax0[(size_t)BWN*YHN*64];    // [bw][k][x]
static __device__ float2 d_Ax1[(size_t)BWN*YHN*64];
static __device__ float2 d_Wt [3][(size_t)NF*WWC*WWC]; // [f][w*64+o]

// ---------------- f32x2 packed helpers --------------------------------------
__device__ __forceinline__ u64x pk2(float lo, float hi) {
    u64x r; asm("mov.b64 %0,{%1,%2};" : "=l"(r) : "f"(lo), "f"(hi)); return r;
}
__device__ __forceinline__ void upk2(u64x v, float& lo, float& hi) {
    asm("mov.b64 {%0,%1},%2;" : "=f"(lo), "=f"(hi) : "l"(v));
}
#define FMA2(a,b,c) asm("fma.rn.f32x2 %0,%1,%2,%0;" : "+l"(c) : "l"(a), "l"(b))

// ---------------- compile-time twiddles (units of 2*pi/64) ------------------
__device__ __host__ constexpr float TWQ_(int i) {
    constexpr float q[17] = {
        1.000000000f, 0.995184727f, 0.980785280f, 0.956940336f,
        0.923879533f, 0.881921264f, 0.831469612f, 0.773010453f,
        0.707106781f, 0.634393284f, 0.555570233f, 0.471396737f,
        0.382683432f, 0.290284677f, 0.195090322f, 0.098017140f, 0.f };
    return q[i];
}
__device__ __host__ constexpr float twcos(int j) {
    j &= 63;
    if (j <= 16) return TWQ_(j);
    if (j <= 32) return -TWQ_(32 - j);
    if (j <= 48) return -TWQ_(j - 32);
    return TWQ_(64 - j);
}
__device__ __host__ constexpr float twsin(int j) { return twcos(j + 48); }
__device__ __host__ constexpr int bitrev5(int n) {
    return ((n&1)<<4)|((n&2)<<2)|(n&4)|((n&8)>>2)|((n&16)>>4);
}

// fully unrolled 32-pt radix-2 DIT FFT on register arrays (SGN=-1 fwd, +1 inv)
template<int SGN>
__device__ __forceinline__ void fft32r(float* xr, float* xi) {
    #pragma unroll
    for (int n = 1; n < 32; n++) {
        int r = bitrev5(n);
        if (r > n) {
            float a = xr[n]; xr[n] = xr[r]; xr[r] = a;
            float b = xi[n]; xi[n] = xi[r]; xi[r] = b;
        }
    }
    #pragma unroll
    for (int s = 0; s < 5; s++) {
        const int half = 1 << s;
        #pragma unroll
        for (int j = 0; j < 16; j++) {
            const int k  = j & (half - 1);
            const int g  = j >> s;
            const int i1 = g * (half << 1) + k;
            const int i2 = i1 + half;
            const float wr = twcos(k << (5 - s));           // W32^k = W64^(2k)
            const float wi = (float)SGN * twsin(k << (5 - s));
            float vr = xr[i2], vi = xi[i2];
            float tr = vr * wr - vi * wi;
            float ti = vr * wi + vi * wr;
            float ur = xr[i1], ui = xi[i1];
            xr[i1] = ur + tr;  xi[i1] = ui + ti;
            xr[i2] = ur - tr;  xi[i2] = ui - ti;
        }
    }
}

__device__ __forceinline__ float sigm(float v) { return 1.f / (1.f + __expf(-v)); }
__device__ __forceinline__ float ftanh(float v) { return 2.f / (1.f + __expf(-2.f*v)) - 1.f; }

// ---- inverse: X[0..32] (coalesced over t) -> packed real pair seq (zr,zi) --
// numpy irfft semantics: Im(X[0]) and Im(X[32]) are dropped (they contribute
// only to the imaginary part of the Hermitian-extended inverse transform).
__device__ __forceinline__ void irfft_build(const float2* __restrict__ A, int t,
                                            float* zr, float* zi) {
    float2 x0  = A[t];
    float2 x32 = A[32*64 + t];
    float2 x16 = A[16*64 + t];
    // k = 0: Xe0 = (Re X0 + Re X32)/2, Xo0 = (Re X0 - Re X32)/2 (imags dropped)
    zr[0] = 0.5f*(x0.x + x32.x);
    zi[0] = 0.5f*(x0.x - x32.x);
    zr[16] = x16.x;  zi[16] = -x16.y;
    #pragma unroll
    for (int k = 1; k < 16; k++) {
        const int q = 32 - k;
        float2 a = A[k*64 + t];
        float2 b = A[q*64 + t];
        float Sr = 0.5f*(a.x + b.x), Si = 0.5f*(a.y - b.y);
        float Dr = 0.5f*(a.x - b.x), Di = 0.5f*(a.y + b.y);
        const float c = twcos(k), s = twsin(k);
        float XoR = c*Dr - s*Di;
        float XoI = c*Di + s*Dr;
        zr[k] = Sr - XoI;  zi[k] = Si + XoR;
        zr[q] = Sr + XoI;  zi[q] = XoR - Si;
    }
    fft32r<1>(zr, zi);
}

// ---- forward: packed real pair seq -> X[0..32] stored coalesced over t -----
__device__ __forceinline__ void rfft_store(float2* __restrict__ out, int t,
                                           float* zr, float* zi) {
    fft32r<-1>(zr, zi);
    out[0*64 + t]  = make_float2(zr[0] + zi[0], 0.f);
    out[32*64 + t] = make_float2(zr[0] - zi[0], 0.f);
    out[16*64 + t] = make_float2(zr[16], -zi[16]);
    #pragma unroll
    for (int k = 1; k < 16; k++) {
        const int q = 32 - k;
        float XeR = 0.5f*(zr[k] + zr[q]), XeI = 0.5f*(zi[k] - zi[q]);
        float XoR = 0.5f*(zi[k] + zi[q]), XoI = 0.5f*(zr[q] - zr[k]);
        const float c = twcos(k), s = twsin(k);
        float wXoR = c*XoR + s*XoI;
        float wXoI = c*XoI - s*XoR;
        out[k*64 + t] = make_float2(XeR + wXoR, XeI + wXoI);
        out[q*64 + t] = make_float2(XeR - wXoR, -(XeI - wXoI));
    }
}

// ---------------- weight transpose: [i][o][f] -> [f][i*64+o] ----------------
__global__ void k_wt_all(const float* __restrict__ p0r, const float* __restrict__ p0i,
                         const float* __restrict__ p1r, const float* __restrict__ p1i,
                         const float* __restrict__ p2r, const float* __restrict__ p2i) {
    __shared__ float s_r[64*65];
    __shared__ float s_i[64*65];
    int gate = blockIdx.z;
    const float* wr = gate == 0 ? p0r : (gate == 1 ? p1r : p2r);
    const float* wi = gate == 0 ? p0i : (gate == 1 ? p1i : p2i);
    int f0  = blockIdx.x * 64;
    int io0 = blockIdx.y * 64;
    int lane = threadIdx.x & 63;
    int row  = threadIdx.x >> 6;
    #pragma unroll
    for (int r = row; r < 64; r += 4) {
        s_r[r*65 + lane] = wr[(size_t)(io0 + r) * NF + f0 + lane];
        s_i[r*65 + lane] = wi[(size_t)(io0 + r) * NF + f0 + lane];
    }
    __syncthreads();
    float2* out = d_Wt[gate];
    #pragma unroll
    for (int fl = row; fl < 64; fl += 4) {
        out[(size_t)(f0 + fl) * 4096 + io0 + lane] =
            make_float2(s_r[lane*65 + fl], s_i[lane*65 + fl]);
    }
}

// ---------------- h0 = x @ Wi + bi (CIN=1) ----------------------------------
__global__ void k_init_h(const float* __restrict__ x, const float* __restrict__ Wi,
                         const float* __restrict__ bi) {
    int idx = blockIdx.x * 256 + threadIdx.x;
    int bw = idx >> 12;
    int xy = idx & 4095;
    int b = bw >> 6, w = bw & 63;
    d_h[idx] = x[b * TILE + xy] * Wi[w] + bi[w];
}

// ---------------- prologue: y-rfft of h -------------------------------------
__global__ void k_fwd1() {
    int bw = blockIdx.x, t = threadIdx.x;      // 64 threads, t = x
    const float4* row = reinterpret_cast<const float4*>(d_h + (size_t)bw * TILE + t*64);
    float zr[32], zi[32];
    #pragma unroll
    for (int j = 0; j < 16; j++) {
        float4 v = row[j];
        zr[2*j] = v.x; zi[2*j] = v.y; zr[2*j+1] = v.z; zi[2*j+1] = v.w;
    }
    rfft_store(d_A1 + (size_t)bw * YHN * 64, t, zr, zi);
}

// ---------------- x-FFT (pair-split DIF): d_A1[bw][k][x] -> d_Hf[f][bw] ------
__global__ void k_fwd2() {
    int k = blockIdx.x;                         // 0..32
    int lane = threadIdx.x & 31;
    int wid  = threadIdx.x >> 5;                // 4 warps
    bool lo = (lane < 16);
    int bw = blockIdx.y * 64 + wid * 16 + (lane & 15);

    float ar[32], ai[32];
    const float4* src = reinterpret_cast<const float4*>(d_A1 + ((size_t)bw*YHN + k)*64)
                        + (lo ? 0 : 16);
    #pragma unroll
    for (int j = 0; j < 16; j++) {
        float4 v = src[j];
        ar[2*j] = v.x; ai[2*j] = v.y; ar[2*j+1] = v.z; ai[2*j+1] = v.w;
    }
    // DIF cross stage via lane-pair exchange (xor 16)
    #pragma unroll
    for (int n = 0; n < 32; n++) {
        float br = __shfl_xor_sync(0xffffffffu, ar[n], 16);
        float bi = __shfl_xor_sync(0xffffffffu, ai[n], 16);
        if (lo) {                              // u = a + b
            ar[n] += br;  ai[n] += bi;
        } else {                               // v = (a - b) * W64^n, W=e^{-i}
            float dr = br - ar[n], di = bi - ai[n];
            const float c = twcos(n), s = twsin(n);
            ar[n] = dr*c + di*s;
            ai[n] = di*c - dr*s;
        }
    }
    fft32r<-1>(ar, ai);
    int xb = lo ? 0 : 1;
    #pragma unroll
    for (int m = 0; m < 32; m++)               // coalesced over bw lanes
        d_Hf[((size_t)(2*m + xb)*YHN + k)*BWN + bw] = make_float2(ar[m], ai[m]);
}

// ---------------- per-frequency complex GEMM (packed f32x2) -----------------
__global__ void k_gemm(int pass) {
    int f = blockIdx.x;
    int gate = blockIdx.y;
    const float2* Wt = (pass == 0) ? d_Wt[gate] : d_Wt[2];
    float2* O = (pass == 0 && gate == 1) ? d_F1 : d_F0;

    __shared__ __align__(16) float Hsr[64*HS_LS];
    __shared__ __align__(16) float Hsi[64*HS_LS];
    __shared__ __align__(16) float2 Ws[64*64];
    int tid = threadIdx.x;             // 128

    const float2* Hsrc = d_Hf + (size_t)f * BWN;
    #pragma unroll
    for (int i = tid; i < BWN; i += 128) {
        float2 v = Hsrc[i];
        int b = i >> 6, w = i & 63;
        Hsr[w*HS_LS + b] = v.x;
        Hsi[w*HS_LS + b] = v.y;
    }
    const float4* Wsrc = reinterpret_cast<const float4*>(Wt + (size_t)f * 4096);
    float4* Wdst = reinterpret_cast<float4*>(Ws);
    #pragma unroll
    for (int i = tid; i < 2048; i += 128) Wdst[i] = Wsrc[i];
    __syncthreads();

    int og = tid & 31;
    int bg = (tid >> 5) * 4;
    u64x ar[2][2] = {{0,0},{0,0}};
    u64x ai[2][2] = {{0,0},{0,0}};

    #pragma unroll 8
    for (int w = 0; w < 64; w++) {
        u64x hr0 = *reinterpret_cast<const u64x*>(&Hsr[w*HS_LS + bg]);
        u64x hr1 = *reinterpret_cast<const u64x*>(&Hsr[w*HS_LS + bg + 2]);
        u64x hi0 = *reinterpret_cast<const u64x*>(&Hsi[w*HS_LS + bg]);
        u64x hi1 = *reinterpret_cast<const u64x*>(&Hsi[w*HS_LS + bg + 2]);
        float2 w0 = Ws[w*64 + og];
        float2 w1 = Ws[w*64 + og + 32];
        {
            u64x wr2 = pk2(w0.x, w0.x), wi2 = pk2(w0.y, w0.y), ni2 = pk2(-w0.y, -w0.y);
            FMA2(hr0, wr2, ar[0][0]); FMA2(hi0, ni2, ar[0][0]);
            FMA2(hr1, wr2, ar[0][1]); FMA2(hi1, ni2, ar[0][1]);
            FMA2(hr0, wi2, ai[0][0]); FMA2(hi0, wr2, ai[0][0]);
            FMA2(hr1, wi2, ai[0][1]); FMA2(hi1, wr2, ai[0][1]);
        }
        {
            u64x wr2 = pk2(w1.x, w1.x), wi2 = pk2(w1.y, w1.y), ni2 = pk2(-w1.y, -w1.y);
            FMA2(hr0, wr2, ar[1][0]); FMA2(hi0, ni2, ar[1][0]);
            FMA2(hr1, wr2, ar[1][1]); FMA2(hi1, ni2, ar[1][1]);
            FMA2(hr0, wi2, ai[1][0]); FMA2(hi0, wr2, ai[1][0]);
            FMA2(hr1, wi2, ai[1][1]); FMA2(hi1, wr2, ai[1][1]);
        }
    }
    #pragma unroll
    for (int oi = 0; oi < 2; oi++) {
        int o = og + oi*32;
        #pragma unroll
        for (int p = 0; p < 2; p++) {
            float r0, r1, i0, i1;
            upk2(ar[oi][p], r0, r1);
            upk2(ai[oi][p], i0, i1);
            O[(size_t)f * BWN + (bg + 2*p + 0)*64 + o] = make_float2(r0, i0);
            O[(size_t)f * BWN + (bg + 2*p + 1)*64 + o] = make_float2(r1, i1);
        }
    }
}

// ---------------- inverse x-FFT (pair-split DIT): d_F[f][bw] -> d_Ax --------
__global__ void k_inv1() {
    int k = blockIdx.x;
    int lane = threadIdx.x & 31;
    int wid  = threadIdx.x >> 5;
    bool lo = (lane < 16);
    int bw = blockIdx.y * 64 + wid * 16 + (lane & 15);
    const float2* F = blockIdx.z ? d_F1 : d_F0;
    float2* A = blockIdx.z ? d_Ax1 : d_Ax0;

    float ar[32], ai[32];
    int xoff = lo ? 0 : 1;                      // lo: even bins, hi: odd bins
    #pragma unroll
    for (int m = 0; m < 32; m++) {
        float2 v = F[((size_t)(2*m + xoff)*YHN + k)*BWN + bw];
        ar[m] = v.x; ai[m] = v.y;
    }
    fft32r<1>(ar, ai);
    // DIT cross stage: x[m] = A + W^m B; x[m+32] = A - W^m B  (W = e^{+i})
    #pragma unroll
    for (int m = 0; m < 32; m++) {
        float br = __shfl_xor_sync(0xffffffffu, ar[m], 16);
        float bi = __shfl_xor_sync(0xffffffffu, ai[m], 16);
        const float c = twcos(m), s = twsin(m);
        if (lo) {                               // own=A, recv=B
            float tr = br*c - bi*s;
            float ti = br*s + bi*c;
            ar[m] += tr;  ai[m] += ti;
        } else {                                // own=B, recv=A
            float tr = ar[m]*c - ai[m]*s;
            float ti = ar[m]*s + ai[m]*c;
            ar[m] = br - tr;  ai[m] = bi - ti;
        }
    }
    float4* dst = reinterpret_cast<float4*>(A + ((size_t)bw*YHN + k)*64) + (lo ? 0 : 16);
    #pragma unroll
    for (int j = 0; j < 16; j++)
        dst[j] = make_float4(ar[2*j], ai[2*j], ar[2*j+1], ai[2*j+1]);
}

// ---------------- fused: z = sig(irfft), g = sig(irfft_r)*h, y-rfft(g) ------
__global__ void k_fused_zr() {
    int bw = blockIdx.x, t = threadIdx.x;       // 64 threads, t = x
    const float sc = 1.f / 2048.f;
    float zr[32], zi[32];
    // ---- z gate ----
    irfft_build(d_Ax0 + (size_t)bw * YHN * 64, t, zr, zi);
    float4* zrow = reinterpret_cast<float4*>(d_z + (size_t)bw * TILE + t*64);
    #pragma unroll
    for (int j = 0; j < 16; j++)
        zrow[j] = make_float4(sigm(zr[2*j]*sc),   sigm(zi[2*j]*sc),
                              sigm(zr[2*j+1]*sc), sigm(zi[2*j+1]*sc));
    // ---- r gate -> g = r*h -> forward y-rfft ----
    irfft_build(d_Ax1 + (size_t)bw * YHN * 64, t, zr, zi);
    const float4* hrow = reinterpret_cast<const float4*>(d_h + (size_t)bw * TILE + t*64);
    #pragma unroll
    for (int j = 0; j < 16; j++) {
        float4 h4 = hrow[j];
        zr[2*j]   = h4.x * sigm(zr[2*j]*sc);
        zi[2*j]   = h4.y * sigm(zi[2*j]*sc);
        zr[2*j+1] = h4.z * sigm(zr[2*j+1]*sc);
        zi[2*j+1] = h4.w * sigm(zi[2*j+1]*sc);
    }
    rfft_store(d_A1 + (size_t)bw * YHN * 64, t, zr, zi);
}

// ---------------- fused: h = (1-z)h + z*tanh(irfft), y-rfft(h) ---------------
__global__ void k_fused_h(int last) {
    int bw = blockIdx.x, t = threadIdx.x;
    const float sc = 1.f / 2048.f;
    float zr[32], zi[32];
    irfft_build(d_Ax0 + (size_t)bw * YHN * 64, t, zr, zi);
    float4* hrow = reinterpret_cast<float4*>(d_h + (size_t)bw * TILE + t*64);
    const float4* zrow = reinterpret_cast<const float4*>(d_z + (size_t)bw * TILE + t*64);
    #pragma unroll
    for (int j = 0; j < 16; j++) {
        float4 h4 = hrow[j];
        float4 z4 = zrow[j];
        float n0 = ftanh(zr[2*j]*sc),   n1 = ftanh(zi[2*j]*sc);
        float n2 = ftanh(zr[2*j+1]*sc), n3 = ftanh(zi[2*j+1]*sc);
        h4.x += z4.x * (n0 - h4.x);
        h4.y += z4.y * (n1 - h4.y);
        h4.z += z4.z * (n2 - h4.z);
        h4.w += z4.w * (n3 - h4.w);
        hrow[j] = h4;
        zr[2*j] = h4.x; zi[2*j] = h4.y; zr[2*j+1] = h4.z; zi[2*j+1] = h4.w;
    }
    if (!last)
        rfft_store(d_A1 + (size_t)bw * YHN * 64, t, zr, zi);
}

// ---------------- out mapping: y = h @ Wo + bo ------------------------------
__global__ void k_out(const float* __restrict__ Wo, const float* __restrict__ bo,
                      float* __restrict__ out, int t) {
    int b = blockIdx.x;
    int xy = blockIdx.y * 256 + threadIdx.x;
    float acc = bo[0];
    const float* hb = d_h + (size_t)(b*64) * TILE + xy;
    #pragma unroll 8
    for (int w = 0; w < 64; w++)
        acc += hb[(size_t)w * TILE] * __ldg(&Wo[w]);
    out[(size_t)(b*TT + t) * TILE + xy] = acc;
}

// ---------------- launch -----------------------------------------------------
extern "C" void kernel_launch(void* const* d_in, const int* in_sizes, int n_in,
                              void* d_out, int out_size) {
    int iX = 0, iWi = 2, iBi = 3, iWo = 4, iBo = 5, iWz = 6;
    if (n_in == 11) { iWi = 1; iBi = 2; iWo = 3; iBo = 4; iWz = 5; }

    const float* x    = (const float*)d_in[iX];
    const float* Wi   = (const float*)d_in[iWi];
    const float* bi   = (const float*)d_in[iBi];
    const float* Wo   = (const float*)d_in[iWo];
    const float* bo   = (const float*)d_in[iBo];
    float* out = (float*)d_out;

    k_wt_all<<<dim3(33, 64, 3), 256>>>((const float*)d_in[iWz+0], (const float*)d_in[iWz+1],
                                       (const float*)d_in[iWz+2], (const float*)d_in[iWz+3],
                                       (const float*)d_in[iWz+4], (const float*)d_in[iWz+5]);
    k_init_h<<<(BWN*TILE)/256, 256>>>(x, Wi, bi);
    k_fwd1<<<BWN, 64>>>();
    k_fwd2<<<dim3(YHN, 16), 128>>>();

    for (int t = 0; t < TT; t++) {
        k_gemm<<<dim3(NF, 2), 128>>>(0);           // z -> F0, r -> F1
        k_inv1<<<dim3(YHN, 16, 2), 128>>>();
        k_fused_zr<<<BWN, 64>>>();                 // z, g = r*h, y-rfft(g)
        k_fwd2<<<dim3(YHN, 16), 128>>>();          // x-FFT(g) -> Hf
        k_gemm<<<dim3(NF, 1), 128>>>(1);           // nh -> F0
        k_inv1<<<dim3(YHN, 16, 1), 128>>>();
        k_fused_h<<<BWN, 64>>>(t == TT-1);         // h update (+ y-rfft next)
        if (t < TT-1) k_fwd2<<<dim3(YHN, 16), 128>>>();
        k_out<<<dim3(BB, TILE/256), 256>>>(Wo, bo, out, t);
    }
}

// round 6
// speedup vs baseline: 1.8930x; 1.0745x over previous
#include <cuda_runtime.h>
#include <cuda_fp16.h>
#include <math.h>

#define BB   16
#define WWC  64
#define TT   20
#define YHN  33
#define NF   2112          // 64 * 33
#define BWN  1024          // BB * WWC
#define TILE 4096
#define HS_LS 18

typedef unsigned long long u64x;

// ---------------- device scratch ------------------------------------------
static __device__ float  d_h [BWN*TILE];
static __device__ float  d_z [BWN*TILE];
static __device__ float2 d_A1 [(size_t)BWN*YHN*64];    // [bw][k][x]
static __device__ float2 d_Hf [(size_t)NF*BWN];        // [f=(x*33+k)][bw]
static __device__ float2 d_F0 [(size_t)NF*BWN];
static __device__ float2 d_F1 [(size_t)NF*BWN];
static __device__ float2 d_Ax0[(size_t)BWN*YHN*64];    // [bw][k][x]
static __device__ float2 d_Ax1[(size_t)BWN*YHN*64];
static __device__ __half2 d_Wt [3][(size_t)NF*WWC*WWC]; // [f][w*64+o] fp16 (r,i)

// ---------------- f32x2 packed helpers --------------------------------------
__device__ __forceinline__ u64x pk2(float lo, float hi) {
    u64x r; asm("mov.b64 %0,{%1,%2};" : "=l"(r) : "f"(lo), "f"(hi)); return r;
}
__device__ __forceinline__ void upk2(u64x v, float& lo, float& hi) {
    asm("mov.b64 {%0,%1},%2;" : "=f"(lo), "=f"(hi) : "l"(v));
}
#define FMA2(a,b,c) asm("fma.rn.f32x2 %0,%1,%2,%0;" : "+l"(c) : "l"(a), "l"(b))

// ---------------- compile-time twiddles (units of 2*pi/64) ------------------
__device__ __host__ constexpr float TWQ_(int i) {
    constexpr float q[17] = {
        1.000000000f, 0.995184727f, 0.980785280f, 0.956940336f,
        0.923879533f, 0.881921264f, 0.831469612f, 0.773010453f,
        0.707106781f, 0.634393284f, 0.555570233f, 0.471396737f,
        0.382683432f, 0.290284677f, 0.195090322f, 0.098017140f, 0.f };
    return q[i];
}
__device__ __host__ constexpr float twcos(int j) {
    j &= 63;
    if (j <= 16) return TWQ_(j);
    if (j <= 32) return -TWQ_(32 - j);
    if (j <= 48) return -TWQ_(j - 32);
    return TWQ_(64 - j);
}
__device__ __host__ constexpr float twsin(int j) { return twcos(j + 48); }
__device__ __host__ constexpr int bitrev5(int n) {
    return ((n&1)<<4)|((n&2)<<2)|(n&4)|((n&8)>>2)|((n&16)>>4);
}

// fully unrolled 32-pt radix-2 DIT FFT on register arrays (SGN=-1 fwd, +1 inv)
template<int SGN>
__device__ __forceinline__ void fft32r(float* xr, float* xi) {
    #pragma unroll
    for (int n = 1; n < 32; n++) {
        int r = bitrev5(n);
        if (r > n) {
            float a = xr[n]; xr[n] = xr[r]; xr[r] = a;
            float b = xi[n]; xi[n] = xi[r]; xi[r] = b;
        }
    }
    #pragma unroll
    for (int s = 0; s < 5; s++) {
        const int half = 1 << s;
        #pragma unroll
        for (int j = 0; j < 16; j++) {
            const int k  = j & (half - 1);
            const int g  = j >> s;
            const int i1 = g * (half << 1) + k;
            const int i2 = i1 + half;
            const float wr = twcos(k << (5 - s));
            const float wi = (float)SGN * twsin(k << (5 - s));
            float vr = xr[i2], vi = xi[i2];
            float tr = vr * wr - vi * wi;
            float ti = vr * wi + vi * wr;
            float ur = xr[i1], ui = xi[i1];
            xr[i1] = ur + tr;  xi[i1] = ui + ti;
            xr[i2] = ur - tr;  xi[i2] = ui - ti;
        }
    }
}

__device__ __forceinline__ float sigm(float v) { return 1.f / (1.f + __expf(-v)); }
__device__ __forceinline__ float ftanh(float v) { return 2.f / (1.f + __expf(-2.f*v)) - 1.f; }

// ---- inverse: X[0..32] (coalesced over t) -> packed real pair seq (zr,zi) --
__device__ __forceinline__ void irfft_build(const float2* __restrict__ A, int t,
                                            float* zr, float* zi) {
    float2 x0  = A[t];
    float2 x32 = A[32*64 + t];
    float2 x16 = A[16*64 + t];
    zr[0] = 0.5f*(x0.x + x32.x);
    zi[0] = 0.5f*(x0.x - x32.x);
    zr[16] = x16.x;  zi[16] = -x16.y;
    #pragma unroll
    for (int k = 1; k < 16; k++) {
        const int q = 32 - k;
        float2 a = A[k*64 + t];
        float2 b = A[q*64 + t];
        float Sr = 0.5f*(a.x + b.x), Si = 0.5f*(a.y - b.y);
        float Dr = 0.5f*(a.x - b.x), Di = 0.5f*(a.y + b.y);
        const float c = twcos(k), s = twsin(k);
        float XoR = c*Dr - s*Di;
        float XoI = c*Di + s*Dr;
        zr[k] = Sr - XoI;  zi[k] = Si + XoR;
        zr[q] = Sr + XoI;  zi[q] = XoR - Si;
    }
    fft32r<1>(zr, zi);
}

// ---- forward: packed real pair seq -> X[0..32] stored coalesced over t -----
__device__ __forceinline__ void rfft_store(float2* __restrict__ out, int t,
                                           float* zr, float* zi) {
    fft32r<-1>(zr, zi);
    out[0*64 + t]  = make_float2(zr[0] + zi[0], 0.f);
    out[32*64 + t] = make_float2(zr[0] - zi[0], 0.f);
    out[16*64 + t] = make_float2(zr[16], -zi[16]);
    #pragma unroll
    for (int k = 1; k < 16; k++) {
        const int q = 32 - k;
        float XeR = 0.5f*(zr[k] + zr[q]), XeI = 0.5f*(zi[k] - zi[q]);
        float XoR = 0.5f*(zi[k] + zi[q]), XoI = 0.5f*(zr[q] - zr[k]);
        const float c = twcos(k), s = twsin(k);
        float wXoR = c*XoR + s*XoI;
        float wXoI = c*XoI - s*XoR;
        out[k*64 + t] = make_float2(XeR + wXoR, XeI + wXoI);
        out[q*64 + t] = make_float2(XeR - wXoR, -(XeI - wXoI));
    }
}

// ---------------- weight transpose: [i][o][f] -> [f][i*64+o] fp16 -----------
__global__ void k_wt_all(const float* __restrict__ p0r, const float* __restrict__ p0i,
                         const float* __restrict__ p1r, const float* __restrict__ p1i,
                         const float* __restrict__ p2r, const float* __restrict__ p2i) {
    __shared__ float s_r[64*65];
    __shared__ float s_i[64*65];
    int gate = blockIdx.z;
    const float* wr = gate == 0 ? p0r : (gate == 1 ? p1r : p2r);
    const float* wi = gate == 0 ? p0i : (gate == 1 ? p1i : p2i);
    int f0  = blockIdx.x * 64;
    int io0 = blockIdx.y * 64;
    int lane = threadIdx.x & 63;
    int row  = threadIdx.x >> 6;
    #pragma unroll
    for (int r = row; r < 64; r += 4) {
        s_r[r*65 + lane] = wr[(size_t)(io0 + r) * NF + f0 + lane];
        s_i[r*65 + lane] = wi[(size_t)(io0 + r) * NF + f0 + lane];
    }
    __syncthreads();
    __half2* out = d_Wt[gate];
    #pragma unroll
    for (int fl = row; fl < 64; fl += 4) {
        out[(size_t)(f0 + fl) * 4096 + io0 + lane] =
            __floats2half2_rn(s_r[lane*65 + fl], s_i[lane*65 + fl]);
    }
}

// ---------------- h0 = x @ Wi + bi (CIN=1) ----------------------------------
__global__ void k_init_h(const float* __restrict__ x, const float* __restrict__ Wi,
                         const float* __restrict__ bi) {
    int idx = blockIdx.x * 256 + threadIdx.x;
    int bw = idx >> 12;
    int xy = idx & 4095;
    int b = bw >> 6, w = bw & 63;
    d_h[idx] = x[b * TILE + xy] * Wi[w] + bi[w];
}

// ---------------- prologue: y-rfft of h -------------------------------------
__global__ void k_fwd1() {
    int bw = blockIdx.x, t = threadIdx.x;      // 64 threads, t = x
    const float4* row = reinterpret_cast<const float4*>(d_h + (size_t)bw * TILE + t*64);
    float zr[32], zi[32];
    #pragma unroll
    for (int j = 0; j < 16; j++) {
        float4 v = row[j];
        zr[2*j] = v.x; zi[2*j] = v.y; zr[2*j+1] = v.z; zi[2*j+1] = v.w;
    }
    rfft_store(d_A1 + (size_t)bw * YHN * 64, t, zr, zi);
}

// ---------------- x-FFT (pair-split DIF): d_A1[bw][k][x] -> d_Hf[f][bw] ------
__global__ void k_fwd2() {
    int k = blockIdx.x;                         // 0..32
    int lane = threadIdx.x & 31;
    int wid  = threadIdx.x >> 5;                // 4 warps
    bool lo = (lane < 16);
    int bw = blockIdx.y * 64 + wid * 16 + (lane & 15);

    float ar[32], ai[32];
    const float4* src = reinterpret_cast<const float4*>(d_A1 + ((size_t)bw*YHN + k)*64)
                        + (lo ? 0 : 16);
    #pragma unroll
    for (int j = 0; j < 16; j++) {
        float4 v = src[j];
        ar[2*j] = v.x; ai[2*j] = v.y; ar[2*j+1] = v.z; ai[2*j+1] = v.w;
    }
    #pragma unroll
    for (int n = 0; n < 32; n++) {
        float br = __shfl_xor_sync(0xffffffffu, ar[n], 16);
        float bi = __shfl_xor_sync(0xffffffffu, ai[n], 16);
        if (lo) {
            ar[n] += br;  ai[n] += bi;
        } else {
            float dr = br - ar[n], di = bi - ai[n];
            const float c = twcos(n), s = twsin(n);
            ar[n] = dr*c + di*s;
            ai[n] = di*c - dr*s;
        }
    }
    fft32r<-1>(ar, ai);
    int xb = lo ? 0 : 1;
    #pragma unroll
    for (int m = 0; m < 32; m++)
        d_Hf[((size_t)(2*m + xb)*YHN + k)*BWN + bw] = make_float2(ar[m], ai[m]);
}

// ---------------- per-frequency complex GEMM (fp16 weights, fp32 accum) -----
// pass 0: in-block gate loop {Wz->F0, Wr->F1}. pass 1: Wh->F0.
__global__ void k_gemm(int pass) {
    int f = blockIdx.x;

    __shared__ __align__(16) float Hsr[64*HS_LS];
    __shared__ __align__(16) float Hsi[64*HS_LS];
    __shared__ __align__(16) __half2 Ws[64*64];    // 16KB
    int tid = threadIdx.x;             // 128

    const float2* Hsrc = d_Hf + (size_t)f * BWN;
    #pragma unroll
    for (int i = tid; i < BWN; i += 128) {
        float2 v = Hsrc[i];
        int b = i >> 6, w = i & 63;
        Hsr[w*HS_LS + b] = v.x;
        Hsi[w*HS_LS + b] = v.y;
    }

    int og = tid & 31;
    int bg = (tid >> 5) * 4;
    const int ngates = (pass == 0) ? 2 : 1;

    for (int g = 0; g < ngates; g++) {
        const __half2* Wt = (pass == 0) ? d_Wt[g] : d_Wt[2];
        float2* O = (pass == 0 && g == 1) ? d_F1 : d_F0;

        __syncthreads();   // H ready (g=0) / previous gate's compute done (g=1)
        const float4* Wsrc = reinterpret_cast<const float4*>(Wt + (size_t)f * 4096);
        float4* Wdst = reinterpret_cast<float4*>(Ws);
        #pragma unroll
        for (int i = tid; i < 1024; i += 128) Wdst[i] = Wsrc[i];
        __syncthreads();

        u64x ar[2][2] = {{0,0},{0,0}};
        u64x ai[2][2] = {{0,0},{0,0}};

        #pragma unroll 8
        for (int w = 0; w < 64; w++) {
            u64x hr0 = *reinterpret_cast<const u64x*>(&Hsr[w*HS_LS + bg]);
            u64x hr1 = *reinterpret_cast<const u64x*>(&Hsr[w*HS_LS + bg + 2]);
            u64x hi0 = *reinterpret_cast<const u64x*>(&Hsi[w*HS_LS + bg]);
            u64x hi1 = *reinterpret_cast<const u64x*>(&Hsi[w*HS_LS + bg + 2]);
            float2 w0 = __half22float2(Ws[w*64 + og]);
            float2 w1 = __half22float2(Ws[w*64 + og + 32]);
            {
                u64x wr2 = pk2(w0.x, w0.x), wi2 = pk2(w0.y, w0.y), ni2 = pk2(-w0.y, -w0.y);
                FMA2(hr0, wr2, ar[0][0]); FMA2(hi0, ni2, ar[0][0]);
                FMA2(hr1, wr2, ar[0][1]); FMA2(hi1, ni2, ar[0][1]);
                FMA2(hr0, wi2, ai[0][0]); FMA2(hi0, wr2, ai[0][0]);
                FMA2(hr1, wi2, ai[0][1]); FMA2(hi1, wr2, ai[0][1]);
            }
            {
                u64x wr2 = pk2(w1.x, w1.x), wi2 = pk2(w1.y, w1.y), ni2 = pk2(-w1.y, -w1.y);
                FMA2(hr0, wr2, ar[1][0]); FMA2(hi0, ni2, ar[1][0]);
                FMA2(hr1, wr2, ar[1][1]); FMA2(hi1, ni2, ar[1][1]);
                FMA2(hr0, wi2, ai[1][0]); FMA2(hi0, wr2, ai[1][0]);
                FMA2(hr1, wi2, ai[1][1]); FMA2(hi1, wr2, ai[1][1]);
            }
        }
        #pragma unroll
        for (int oi = 0; oi < 2; oi++) {
            int o = og + oi*32;
            #pragma unroll
            for (int p = 0; p < 2; p++) {
                float r0, r1, i0, i1;
                upk2(ar[oi][p], r0, r1);
                upk2(ai[oi][p], i0, i1);
                O[(size_t)f * BWN + (bg + 2*p + 0)*64 + o] = make_float2(r0, i0);
                O[(size_t)f * BWN + (bg + 2*p + 1)*64 + o] = make_float2(r1, i1);
            }
        }
    }
}

// ---------------- inverse x-FFT (pair-split DIT): d_F[f][bw] -> d_Ax --------
__global__ void k_inv1() {
    int k = blockIdx.x;
    int lane = threadIdx.x & 31;
    int wid  = threadIdx.x >> 5;
    bool lo = (lane < 16);
    int bw = blockIdx.y * 64 + wid * 16 + (lane & 15);
    const float2* F = blockIdx.z ? d_F1 : d_F0;
    float2* A = blockIdx.z ? d_Ax1 : d_Ax0;

    float ar[32], ai[32];
    int xoff = lo ? 0 : 1;
    #pragma unroll
    for (int m = 0; m < 32; m++) {
        float2 v = F[((size_t)(2*m + xoff)*YHN + k)*BWN + bw];
        ar[m] = v.x; ai[m] = v.y;
    }
    fft32r<1>(ar, ai);
    #pragma unroll
    for (int m = 0; m < 32; m++) {
        float br = __shfl_xor_sync(0xffffffffu, ar[m], 16);
        float bi = __shfl_xor_sync(0xffffffffu, ai[m], 16);
        const float c = twcos(m), s = twsin(m);
        if (lo) {
            float tr = br*c - bi*s;
            float ti = br*s + bi*c;
            ar[m] += tr;  ai[m] += ti;
        } else {
            float tr = ar[m]*c - ai[m]*s;
            float ti = ar[m]*s + ai[m]*c;
            ar[m] = br - tr;  ai[m] = bi - ti;
        }
    }
    float4* dst = reinterpret_cast<float4*>(A + ((size_t)bw*YHN + k)*64) + (lo ? 0 : 16);
    #pragma unroll
    for (int j = 0; j < 16; j++)
        dst[j] = make_float4(ar[2*j], ai[2*j], ar[2*j+1], ai[2*j+1]);
}

// ---------------- fused: z = sig(irfft), g = sig(irfft_r)*h, y-rfft(g) ------
__global__ void k_fused_zr() {
    int bw = blockIdx.x, t = threadIdx.x;
    const float sc = 1.f / 2048.f;
    float zr[32], zi[32];
    irfft_build(d_Ax0 + (size_t)bw * YHN * 64, t, zr, zi);
    float4* zrow = reinterpret_cast<float4*>(d_z + (size_t)bw * TILE + t*64);
    #pragma unroll
    for (int j = 0; j < 16; j++)
        zrow[j] = make_float4(sigm(zr[2*j]*sc),   sigm(zi[2*j]*sc),
                              sigm(zr[2*j+1]*sc), sigm(zi[2*j+1]*sc));
    irfft_build(d_Ax1 + (size_t)bw * YHN * 64, t, zr, zi);
    const float4* hrow = reinterpret_cast<const float4*>(d_h + (size_t)bw * TILE + t*64);
    #pragma unroll
    for (int j = 0; j < 16; j++) {
        float4 h4 = hrow[j];
        zr[2*j]   = h4.x * sigm(zr[2*j]*sc);
        zi[2*j]   = h4.y * sigm(zi[2*j]*sc);
        zr[2*j+1] = h4.z * sigm(zr[2*j+1]*sc);
        zi[2*j+1] = h4.w * sigm(zi[2*j+1]*sc);
    }
    rfft_store(d_A1 + (size_t)bw * YHN * 64, t, zr, zi);
}

// ---------------- fused: h = (1-z)h + z*tanh(irfft), y-rfft(h) ---------------
__global__ void k_fused_h(int last) {
    int bw = blockIdx.x, t = threadIdx.x;
    const float sc = 1.f / 2048.f;
    float zr[32], zi[32];
    irfft_build(d_Ax0 + (size_t)bw * YHN * 64, t, zr, zi);
    float4* hrow = reinterpret_cast<float4*>(d_h + (size_t)bw * TILE + t*64);
    const float4* zrow = reinterpret_cast<const float4*>(d_z + (size_t)bw * TILE + t*64);
    #pragma unroll
    for (int j = 0; j < 16; j++) {
        float4 h4 = hrow[j];
        float4 z4 = zrow[j];
        float n0 = ftanh(zr[2*j]*sc),   n1 = ftanh(zi[2*j]*sc);
        float n2 = ftanh(zr[2*j+1]*sc), n3 = ftanh(zi[2*j+1]*sc);
        h4.x += z4.x * (n0 - h4.x);
        h4.y += z4.y * (n1 - h4.y);
        h4.z += z4.z * (n2 - h4.z);
        h4.w += z4.w * (n3 - h4.w);
        hrow[j] = h4;
        zr[2*j] = h4.x; zi[2*j] = h4.y; zr[2*j+1] = h4.z; zi[2*j+1] = h4.w;
    }
    if (!last)
        rfft_store(d_A1 + (size_t)bw * YHN * 64, t, zr, zi);
}

// ---------------- out mapping: y = h @ Wo + bo ------------------------------
__global__ void k_out(const float* __restrict__ Wo, const float* __restrict__ bo,
                      float* __restrict__ out, int t) {
    int b = blockIdx.x;
    int xy = blockIdx.y * 256 + threadIdx.x;
    float acc = bo[0];
    const float* hb = d_h + (size_t)(b*64) * TILE + xy;
    #pragma unroll 8
    for (int w = 0; w < 64; w++)
        acc += hb[(size_t)w * TILE] * __ldg(&Wo[w]);
    out[(size_t)(b*TT + t) * TILE + xy] = acc;
}

// ---------------- launch -----------------------------------------------------
extern "C" void kernel_launch(void* const* d_in, const int* in_sizes, int n_in,
                              void* d_out, int out_size) {
    int iX = 0, iWi = 2, iBi = 3, iWo = 4, iBo = 5, iWz = 6;
    if (n_in == 11) { iWi = 1; iBi = 2; iWo = 3; iBo = 4; iWz = 5; }

    const float* x    = (const float*)d_in[iX];
    const float* Wi   = (const float*)d_in[iWi];
    const float* bi   = (const float*)d_in[iBi];
    const float* Wo   = (const float*)d_in[iWo];
    const float* bo   = (const float*)d_in[iBo];
    float* out = (float*)d_out;

    k_wt_all<<<dim3(33, 64, 3), 256>>>((const float*)d_in[iWz+0], (const float*)d_in[iWz+1],
                                       (const float*)d_in[iWz+2], (const float*)d_in[iWz+3],
                                       (const float*)d_in[iWz+4], (const float*)d_in[iWz+5]);
    k_init_h<<<(BWN*TILE)/256, 256>>>(x, Wi, bi);
    k_fwd1<<<BWN, 64>>>();
    k_fwd2<<<dim3(YHN, 16), 128>>>();

    for (int t = 0; t < TT; t++) {
        k_gemm<<<NF, 128>>>(0);                    // z -> F0, r -> F1
        k_inv1<<<dim3(YHN, 16, 2), 128>>>();
        k_fused_zr<<<BWN, 64>>>();                 // z, g = r*h, y-rfft(g)
        k_fwd2<<<dim3(YHN, 16), 128>>>();          // x-FFT(g) -> Hf
        k_gemm<<<NF, 128>>>(1);                    // nh -> F0
        k_inv1<<<dim3(YHN, 16, 1), 128>>>();
        k_fused_h<<<BWN, 64>>>(t == TT-1);         // h update (+ y-rfft next)
        if (t < TT-1) k_fwd2<<<dim3(YHN, 16), 128>>>();
        k_out<<<dim3(BB, TILE/256), 256>>>(Wo, bo, out, t);
    }
}

// round 7
// speedup vs baseline: 1.9735x; 1.0426x over previous
#include <cuda_runtime.h>
#include <cuda_fp16.h>
#include <math.h>

#define BB   16
#define WWC  64
#define TT   20
#define YHN  33
#define NF   2112          // 64 * 33
#define BWN  1024          // BB * WWC
#define TILE 4096
#define HS_LS 18

typedef unsigned long long u64x;

// ---------------- device scratch ------------------------------------------
static __device__ float  d_h [BWN*TILE];
static __device__ float  d_z [BWN*TILE];
static __device__ __align__(16) __half2 d_A1 [(size_t)BWN*YHN*64];   // [bw][k][x]
static __device__ __align__(16) __half2 d_Hf [(size_t)NF*BWN];       // [f][bw]
static __device__ __align__(16) __half2 d_F0 [(size_t)NF*BWN];
static __device__ __align__(16) __half2 d_F1 [(size_t)NF*BWN];
static __device__ __align__(16) __half2 d_Ax0[(size_t)BWN*YHN*64];   // [bw][k][x]
static __device__ __align__(16) __half2 d_Ax1[(size_t)BWN*YHN*64];
static __device__ __align__(16) __half2 d_Wt [3][(size_t)NF*WWC*WWC]; // [f][w*64+o]

// ---------------- f32x2 packed helpers --------------------------------------
__device__ __forceinline__ u64x pk2(float lo, float hi) {
    u64x r; asm("mov.b64 %0,{%1,%2};" : "=l"(r) : "f"(lo), "f"(hi)); return r;
}
__device__ __forceinline__ void upk2(u64x v, float& lo, float& hi) {
    asm("mov.b64 {%0,%1},%2;" : "=f"(lo), "=f"(hi) : "l"(v));
}
#define FMA2(a,b,c) asm("fma.rn.f32x2 %0,%1,%2,%0;" : "+l"(c) : "l"(a), "l"(b))

// ---------------- compile-time twiddles (units of 2*pi/64) ------------------
__device__ __host__ constexpr float TWQ_(int i) {
    constexpr float q[17] = {
        1.000000000f, 0.995184727f, 0.980785280f, 0.956940336f,
        0.923879533f, 0.881921264f, 0.831469612f, 0.773010453f,
        0.707106781f, 0.634393284f, 0.555570233f, 0.471396737f,
        0.382683432f, 0.290284677f, 0.195090322f, 0.098017140f, 0.f };
    return q[i];
}
__device__ __host__ constexpr float twcos(int j) {
    j &= 63;
    if (j <= 16) return TWQ_(j);
    if (j <= 32) return -TWQ_(32 - j);
    if (j <= 48) return -TWQ_(j - 32);
    return TWQ_(64 - j);
}
__device__ __host__ constexpr float twsin(int j) { return twcos(j + 48); }
__device__ __host__ constexpr int bitrev5(int n) {
    return ((n&1)<<4)|((n&2)<<2)|(n&4)|((n&8)>>2)|((n&16)>>4);
}

// fully unrolled 32-pt radix-2 DIT FFT on register arrays (SGN=-1 fwd, +1 inv)
template<int SGN>
__device__ __forceinline__ void fft32r(float* xr, float* xi) {
    #pragma unroll
    for (int n = 1; n < 32; n++) {
        int r = bitrev5(n);
        if (r > n) {
            float a = xr[n]; xr[n] = xr[r]; xr[r] = a;
            float b = xi[n]; xi[n] = xi[r]; xi[r] = b;
        }
    }
    #pragma unroll
    for (int s = 0; s < 5; s++) {
        const int half = 1 << s;
        #pragma unroll
        for (int j = 0; j < 16; j++) {
            const int k  = j & (half - 1);
            const int g  = j >> s;
            const int i1 = g * (half << 1) + k;
            const int i2 = i1 + half;
            const float wr = twcos(k << (5 - s));
            const float wi = (float)SGN * twsin(k << (5 - s));
            float vr = xr[i2], vi = xi[i2];
            float tr = vr * wr - vi * wi;
            float ti = vr * wi + vi * wr;
            float ur = xr[i1], ui = xi[i1];
            xr[i1] = ur + tr;  xi[i1] = ui + ti;
            xr[i2] = ur - tr;  xi[i2] = ui - ti;
        }
    }
}

__device__ __forceinline__ float sigm(float v) { return 1.f / (1.f + __expf(-v)); }
__device__ __forceinline__ float ftanh(float v) { return 2.f / (1.f + __expf(-2.f*v)) - 1.f; }

// ---- inverse: X[0..32] (half2, coalesced over t) -> packed real pair seq ---
__device__ __forceinline__ void irfft_build(const __half2* __restrict__ A, int t,
                                            float* zr, float* zi) {
    float2 x0  = __half22float2(A[t]);
    float2 x32 = __half22float2(A[32*64 + t]);
    float2 x16 = __half22float2(A[16*64 + t]);
    zr[0] = 0.5f*(x0.x + x32.x);
    zi[0] = 0.5f*(x0.x - x32.x);
    zr[16] = x16.x;  zi[16] = -x16.y;
    #pragma unroll
    for (int k = 1; k < 16; k++) {
        const int q = 32 - k;
        float2 a = __half22float2(A[k*64 + t]);
        float2 b = __half22float2(A[q*64 + t]);
        float Sr = 0.5f*(a.x + b.x), Si = 0.5f*(a.y - b.y);
        float Dr = 0.5f*(a.x - b.x), Di = 0.5f*(a.y + b.y);
        const float c = twcos(k), s = twsin(k);
        float XoR = c*Dr - s*Di;
        float XoI = c*Di + s*Dr;
        zr[k] = Sr - XoI;  zi[k] = Si + XoR;
        zr[q] = Sr + XoI;  zi[q] = XoR - Si;
    }
    fft32r<1>(zr, zi);
}

// ---- forward: packed real pair seq -> X[0..32] half2, coalesced over t -----
__device__ __forceinline__ void rfft_store(__half2* __restrict__ out, int t,
                                           float* zr, float* zi) {
    fft32r<-1>(zr, zi);
    out[0*64 + t]  = __floats2half2_rn(zr[0] + zi[0], 0.f);
    out[32*64 + t] = __floats2half2_rn(zr[0] - zi[0], 0.f);
    out[16*64 + t] = __floats2half2_rn(zr[16], -zi[16]);
    #pragma unroll
    for (int k = 1; k < 16; k++) {
        const int q = 32 - k;
        float XeR = 0.5f*(zr[k] + zr[q]), XeI = 0.5f*(zi[k] - zi[q]);
        float XoR = 0.5f*(zi[k] + zi[q]), XoI = 0.5f*(zr[q] - zr[k]);
        const float c = twcos(k), s = twsin(k);
        float wXoR = c*XoR + s*XoI;
        float wXoI = c*XoI - s*XoR;
        out[k*64 + t] = __floats2half2_rn(XeR + wXoR, XeI + wXoI);
        out[q*64 + t] = __floats2half2_rn(XeR - wXoR, -(XeI - wXoI));
    }
}

// ---------------- weight transpose: [i][o][f] -> [f][i*64+o] fp16 -----------
__global__ void k_wt_all(const float* __restrict__ p0r, const float* __restrict__ p0i,
                         const float* __restrict__ p1r, const float* __restrict__ p1i,
                         const float* __restrict__ p2r, const float* __restrict__ p2i) {
    __shared__ float s_r[64*65];
    __shared__ float s_i[64*65];
    int gate = blockIdx.z;
    const float* wr = gate == 0 ? p0r : (gate == 1 ? p1r : p2r);
    const float* wi = gate == 0 ? p0i : (gate == 1 ? p1i : p2i);
    int f0  = blockIdx.x * 64;
    int io0 = blockIdx.y * 64;
    int lane = threadIdx.x & 63;
    int row  = threadIdx.x >> 6;
    #pragma unroll
    for (int r = row; r < 64; r += 4) {
        s_r[r*65 + lane] = wr[(size_t)(io0 + r) * NF + f0 + lane];
        s_i[r*65 + lane] = wi[(size_t)(io0 + r) * NF + f0 + lane];
    }
    __syncthreads();
    __half2* out = d_Wt[gate];
    #pragma unroll
    for (int fl = row; fl < 64; fl += 4) {
        out[(size_t)(f0 + fl) * 4096 + io0 + lane] =
            __floats2half2_rn(s_r[lane*65 + fl], s_i[lane*65 + fl]);
    }
}

// ---------------- h0 = x @ Wi + bi (CIN=1) ----------------------------------
__global__ void k_init_h(const float* __restrict__ x, const float* __restrict__ Wi,
                         const float* __restrict__ bi) {
    int idx = blockIdx.x * 256 + threadIdx.x;
    int bw = idx >> 12;
    int xy = idx & 4095;
    int b = bw >> 6, w = bw & 63;
    d_h[idx] = x[b * TILE + xy] * Wi[w] + bi[w];
}

// ---------------- prologue: y-rfft of h -------------------------------------
__global__ void k_fwd1() {
    int bw = blockIdx.x, t = threadIdx.x;      // 64 threads, t = x
    const float4* row = reinterpret_cast<const float4*>(d_h + (size_t)bw * TILE + t*64);
    float zr[32], zi[32];
    #pragma unroll
    for (int j = 0; j < 16; j++) {
        float4 v = row[j];
        zr[2*j] = v.x; zi[2*j] = v.y; zr[2*j+1] = v.z; zi[2*j+1] = v.w;
    }
    rfft_store(d_A1 + (size_t)bw * YHN * 64, t, zr, zi);
}

// ---------------- x-FFT (pair-split DIF): d_A1[bw][k][x] -> d_Hf[f][bw] ------
__global__ void k_fwd2() {
    int k = blockIdx.x;                         // 0..32
    int lane = threadIdx.x & 31;
    int wid  = threadIdx.x >> 5;                // 4 warps
    bool lo = (lane < 16);
    int bw = blockIdx.y * 64 + wid * 16 + (lane & 15);

    float ar[32], ai[32];
    const uint4* src = reinterpret_cast<const uint4*>(d_A1 + ((size_t)bw*YHN + k)*64)
                       + (lo ? 0 : 8);          // uint4 = 4 complex half2
    #pragma unroll
    for (int j = 0; j < 8; j++) {
        uint4 v = src[j];
        float2 c0 = __half22float2(*reinterpret_cast<__half2*>(&v.x));
        float2 c1 = __half22float2(*reinterpret_cast<__half2*>(&v.y));
        float2 c2 = __half22float2(*reinterpret_cast<__half2*>(&v.z));
        float2 c3 = __half22float2(*reinterpret_cast<__half2*>(&v.w));
        ar[4*j+0] = c0.x; ai[4*j+0] = c0.y;
        ar[4*j+1] = c1.x; ai[4*j+1] = c1.y;
        ar[4*j+2] = c2.x; ai[4*j+2] = c2.y;
        ar[4*j+3] = c3.x; ai[4*j+3] = c3.y;
    }
    #pragma unroll
    for (int n = 0; n < 32; n++) {
        float br = __shfl_xor_sync(0xffffffffu, ar[n], 16);
        float bi = __shfl_xor_sync(0xffffffffu, ai[n], 16);
        if (lo) {
            ar[n] += br;  ai[n] += bi;
        } else {
            float dr = br - ar[n], di = bi - ai[n];
            const float c = twcos(n), s = twsin(n);
            ar[n] = dr*c + di*s;
            ai[n] = di*c - dr*s;
        }
    }
    fft32r<-1>(ar, ai);
    int xb = lo ? 0 : 1;
    #pragma unroll
    for (int m = 0; m < 32; m++)
        d_Hf[((size_t)(2*m + xb)*YHN + k)*BWN + bw] = __floats2half2_rn(ar[m], ai[m]);
}

// ---------------- per-frequency complex GEMM (fp16 weights, fp32 accum) -----
// pass 0: in-block gate loop {Wz->F0, Wr->F1}. pass 1: Wh->F0.
__global__ void k_gemm(int pass) {
    int f = blockIdx.x;

    __shared__ __align__(16) float Hsr[64*HS_LS];
    __shared__ __align__(16) float Hsi[64*HS_LS];
    __shared__ __align__(16) __half2 Ws[64*64];    // 16KB
    int tid = threadIdx.x;             // 128

    const __half2* Hsrc = d_Hf + (size_t)f * BWN;
    #pragma unroll
    for (int i = tid; i < BWN; i += 128) {
        float2 v = __half22float2(Hsrc[i]);
        int b = i >> 6, w = i & 63;
        Hsr[w*HS_LS + b] = v.x;
        Hsi[w*HS_LS + b] = v.y;
    }

    int og = tid & 31;
    int bg = (tid >> 5) * 4;
    const int ngates = (pass == 0) ? 2 : 1;

    for (int g = 0; g < ngates; g++) {
        const __half2* Wt = (pass == 0) ? d_Wt[g] : d_Wt[2];
        __half2* O = (pass == 0 && g == 1) ? d_F1 : d_F0;

        __syncthreads();
        const float4* Wsrc = reinterpret_cast<const float4*>(Wt + (size_t)f * 4096);
        float4* Wdst = reinterpret_cast<float4*>(Ws);
        #pragma unroll
        for (int i = tid; i < 1024; i += 128) Wdst[i] = Wsrc[i];
        __syncthreads();

        u64x ar[2][2] = {{0,0},{0,0}};
        u64x ai[2][2] = {{0,0},{0,0}};

        #pragma unroll 8
        for (int w = 0; w < 64; w++) {
            u64x hr0 = *reinterpret_cast<const u64x*>(&Hsr[w*HS_LS + bg]);
            u64x hr1 = *reinterpret_cast<const u64x*>(&Hsr[w*HS_LS + bg + 2]);
            u64x hi0 = *reinterpret_cast<const u64x*>(&Hsi[w*HS_LS + bg]);
            u64x hi1 = *reinterpret_cast<const u64x*>(&Hsi[w*HS_LS + bg + 2]);
            float2 w0 = __half22float2(Ws[w*64 + og]);
            float2 w1 = __half22float2(Ws[w*64 + og + 32]);
            {
                u64x wr2 = pk2(w0.x, w0.x), wi2 = pk2(w0.y, w0.y), ni2 = pk2(-w0.y, -w0.y);
                FMA2(hr0, wr2, ar[0][0]); FMA2(hi0, ni2, ar[0][0]);
                FMA2(hr1, wr2, ar[0][1]); FMA2(hi1, ni2, ar[0][1]);
                FMA2(hr0, wi2, ai[0][0]); FMA2(hi0, wr2, ai[0][0]);
                FMA2(hr1, wi2, ai[0][1]); FMA2(hi1, wr2, ai[0][1]);
            }
            {
                u64x wr2 = pk2(w1.x, w1.x), wi2 = pk2(w1.y, w1.y), ni2 = pk2(-w1.y, -w1.y);
                FMA2(hr0, wr2, ar[1][0]); FMA2(hi0, ni2, ar[1][0]);
                FMA2(hr1, wr2, ar[1][1]); FMA2(hi1, ni2, ar[1][1]);
                FMA2(hr0, wi2, ai[1][0]); FMA2(hi0, wr2, ai[1][0]);
                FMA2(hr1, wi2, ai[1][1]); FMA2(hi1, wr2, ai[1][1]);
            }
        }
        #pragma unroll
        for (int oi = 0; oi < 2; oi++) {
            int o = og + oi*32;
            #pragma unroll
            for (int p = 0; p < 2; p++) {
                float r0, r1, i0, i1;
                upk2(ar[oi][p], r0, r1);
                upk2(ai[oi][p], i0, i1);
                O[(size_t)f * BWN + (bg + 2*p + 0)*64 + o] = __floats2half2_rn(r0, i0);
                O[(size_t)f * BWN + (bg + 2*p + 1)*64 + o] = __floats2half2_rn(r1, i1);
            }
        }
    }
}

// ---------------- inverse x-FFT (pair-split DIT): d_F[f][bw] -> d_Ax --------
__global__ void k_inv1() {
    int k = blockIdx.x;
    int lane = threadIdx.x & 31;
    int wid  = threadIdx.x >> 5;
    bool lo = (lane < 16);
    int bw = blockIdx.y * 64 + wid * 16 + (lane & 15);
    const __half2* F = blockIdx.z ? d_F1 : d_F0;
    __half2* A = blockIdx.z ? d_Ax1 : d_Ax0;

    float ar[32], ai[32];
    int xoff = lo ? 0 : 1;
    #pragma unroll
    for (int m = 0; m < 32; m++) {
        float2 v = __half22float2(F[((size_t)(2*m + xoff)*YHN + k)*BWN + bw]);
        ar[m] = v.x; ai[m] = v.y;
    }
    fft32r<1>(ar, ai);
    #pragma unroll
    for (int m = 0; m < 32; m++) {
        float br = __shfl_xor_sync(0xffffffffu, ar[m], 16);
        float bi = __shfl_xor_sync(0xffffffffu, ai[m], 16);
        const float c = twcos(m), s = twsin(m);
        if (lo) {
            float tr = br*c - bi*s;
            float ti = br*s + bi*c;
            ar[m] += tr;  ai[m] += ti;
        } else {
            float tr = ar[m]*c - ai[m]*s;
            float ti = ar[m]*s + ai[m]*c;
            ar[m] = br - tr;  ai[m] = bi - ti;
        }
    }
    uint2* dst = reinterpret_cast<uint2*>(A + ((size_t)bw*YHN + k)*64) + (lo ? 0 : 16);
    #pragma unroll
    for (int j = 0; j < 16; j++) {
        __half2 h0 = __floats2half2_rn(ar[2*j],   ai[2*j]);
        __half2 h1 = __floats2half2_rn(ar[2*j+1], ai[2*j+1]);
        uint2 u;
        u.x = *reinterpret_cast<unsigned int*>(&h0);
        u.y = *reinterpret_cast<unsigned int*>(&h1);
        dst[j] = u;
    }
}

// ---------------- fused: z = sig(irfft), g = sig(irfft_r)*h, y-rfft(g) ------
__global__ void k_fused_zr() {
    int bw = blockIdx.x, t = threadIdx.x;
    const float sc = 1.f / 2048.f;
    float zr[32], zi[32];
    irfft_build(d_Ax0 + (size_t)bw * YHN * 64, t, zr, zi);
    float4* zrow = reinterpret_cast<float4*>(d_z + (size_t)bw * TILE + t*64);
    #pragma unroll
    for (int j = 0; j < 16; j++)
        zrow[j] = make_float4(sigm(zr[2*j]*sc),   sigm(zi[2*j]*sc),
                              sigm(zr[2*j+1]*sc), sigm(zi[2*j+1]*sc));
    irfft_build(d_Ax1 + (size_t)bw * YHN * 64, t, zr, zi);
    const float4* hrow = reinterpret_cast<const float4*>(d_h + (size_t)bw * TILE + t*64);
    #pragma unroll
    for (int j = 0; j < 16; j++) {
        float4 h4 = hrow[j];
        zr[2*j]   = h4.x * sigm(zr[2*j]*sc);
        zi[2*j]   = h4.y * sigm(zi[2*j]*sc);
        zr[2*j+1] = h4.z * sigm(zr[2*j+1]*sc);
        zi[2*j+1] = h4.w * sigm(zi[2*j+1]*sc);
    }
    rfft_store(d_A1 + (size_t)bw * YHN * 64, t, zr, zi);
}

// ---------------- fused: h = (1-z)h + z*tanh(irfft), y-rfft(h) ---------------
__global__ void k_fused_h(int last) {
    int bw = blockIdx.x, t = threadIdx.x;
    const float sc = 1.f / 2048.f;
    float zr[32], zi[32];
    irfft_build(d_Ax0 + (size_t)bw * YHN * 64, t, zr, zi);
    float4* hrow = reinterpret_cast<float4*>(d_h + (size_t)bw * TILE + t*64);
    const float4* zrow = reinterpret_cast<const float4*>(d_z + (size_t)bw * TILE + t*64);
    #pragma unroll
    for (int j = 0; j < 16; j++) {
        float4 h4 = hrow[j];
        float4 z4 = zrow[j];
        float n0 = ftanh(zr[2*j]*sc),   n1 = ftanh(zi[2*j]*sc);
        float n2 = ftanh(zr[2*j+1]*sc), n3 = ftanh(zi[2*j+1]*sc);
        h4.x += z4.x * (n0 - h4.x);
        h4.y += z4.y * (n1 - h4.y);
        h4.z += z4.z * (n2 - h4.z);
        h4.w += z4.w * (n3 - h4.w);
        hrow[j] = h4;
        zr[2*j] = h4.x; zi[2*j] = h4.y; zr[2*j+1] = h4.z; zi[2*j+1] = h4.w;
    }
    if (!last)
        rfft_store(d_A1 + (size_t)bw * YHN * 64, t, zr, zi);
}

// ---------------- out mapping: y = h @ Wo + bo ------------------------------
__global__ void k_out(const float* __restrict__ Wo, const float* __restrict__ bo,
                      float* __restrict__ out, int t) {
    int b = blockIdx.x;
    int xy = blockIdx.y * 256 + threadIdx.x;
    float acc = bo[0];
    const float* hb = d_h + (size_t)(b*64) * TILE + xy;
    #pragma unroll 8
    for (int w = 0; w < 64; w++)
        acc += hb[(size_t)w * TILE] * __ldg(&Wo[w]);
    out[(size_t)(b*TT + t) * TILE + xy] = acc;
}

// ---------------- launch -----------------------------------------------------
extern "C" void kernel_launch(void* const* d_in, const int* in_sizes, int n_in,
                              void* d_out, int out_size) {
    int iX = 0, iWi = 2, iBi = 3, iWo = 4, iBo = 5, iWz = 6;
    if (n_in == 11) { iWi = 1; iBi = 2; iWo = 3; iBo = 4; iWz = 5; }

    const float* x    = (const float*)d_in[iX];
    const float* Wi   = (const float*)d_in[iWi];
    const float* bi   = (const float*)d_in[iBi];
    const float* Wo   = (const float*)d_in[iWo];
    const float* bo   = (const float*)d_in[iBo];
    float* out = (float*)d_out;

    k_wt_all<<<dim3(33, 64, 3), 256>>>((const float*)d_in[iWz+0], (const float*)d_in[iWz+1],
                                       (const float*)d_in[iWz+2], (const float*)d_in[iWz+3],
                                       (const float*)d_in[iWz+4], (const float*)d_in[iWz+5]);
    k_init_h<<<(BWN*TILE)/256, 256>>>(x, Wi, bi);
    k_fwd1<<<BWN, 64>>>();
    k_fwd2<<<dim3(YHN, 16), 128>>>();

    for (int t = 0; t < TT; t++) {
        k_gemm<<<NF, 128>>>(0);                    // z -> F0, r -> F1
        k_inv1<<<dim3(YHN, 16, 2), 128>>>();
        k_fused_zr<<<BWN, 64>>>();                 // z, g = r*h, y-rfft(g)
        k_fwd2<<<dim3(YHN, 16), 128>>>();          // x-FFT(g) -> Hf
        k_gemm<<<NF, 128>>>(1);                    // nh -> F0
        k_inv1<<<dim3(YHN, 16, 1), 128>>>();
        k_fused_h<<<BWN, 64>>>(t == TT-1);         // h update (+ y-rfft next)
        if (t < TT-1) k_fwd2<<<dim3(YHN, 16), 128>>>();
        k_out<<<dim3(BB, TILE/256), 256>>>(Wo, bo, out, t);
    }
}

// round 8
// speedup vs baseline: 2.7471x; 1.3920x over previous
#include <cuda_runtime.h>
#include <cuda_fp16.h>
#include <math.h>

#define BB   16
#define WWC  64
#define TT   20
#define YHN  33
#define NF   2112          // 64 * 33
#define BWN  1024          // BB * WWC
#define TILE 4096
#define HS_LS 18

typedef unsigned long long u64x;

// ---------------- device scratch ------------------------------------------
static __device__ float  d_h [BWN*TILE];
static __device__ __align__(16) __half2 d_A1 [(size_t)BWN*YHN*64];   // [bw][k][x]
static __device__ __align__(16) __half2 d_Hf [(size_t)NF*BWN];       // [f][bw]
static __device__ __align__(16) __half2 d_F0 [(size_t)NF*BWN];
static __device__ __align__(16) __half2 d_F1 [(size_t)NF*BWN];
static __device__ __align__(16) __half2 d_Ax0[(size_t)BWN*YHN*64];   // [bw][k][x]
static __device__ __align__(16) __half2 d_Ax1[(size_t)BWN*YHN*64];
static __device__ __align__(16) __half2 d_Wt [3][(size_t)NF*WWC*WWC]; // [f][w*64+o]

// ---------------- f32x2 packed helpers --------------------------------------
__device__ __forceinline__ u64x pk2(float lo, float hi) {
    u64x r; asm("mov.b64 %0,{%1,%2};" : "=l"(r) : "f"(lo), "f"(hi)); return r;
}
__device__ __forceinline__ void upk2(u64x v, float& lo, float& hi) {
    asm("mov.b64 {%0,%1},%2;" : "=f"(lo), "=f"(hi) : "l"(v));
}
#define FMA2(a,b,c) asm("fma.rn.f32x2 %0,%1,%2,%0;" : "+l"(c) : "l"(a), "l"(b))

// ---------------- compile-time twiddles (units of 2*pi/64) ------------------
__device__ __host__ constexpr float TWQ_(int i) {
    constexpr float q[17] = {
        1.000000000f, 0.995184727f, 0.980785280f, 0.956940336f,
        0.923879533f, 0.881921264f, 0.831469612f, 0.773010453f,
        0.707106781f, 0.634393284f, 0.555570233f, 0.471396737f,
        0.382683432f, 0.290284677f, 0.195090322f, 0.098017140f, 0.f };
    return q[i];
}
__device__ __host__ constexpr float twcos(int j) {
    j &= 63;
    if (j <= 16) return TWQ_(j);
    if (j <= 32) return -TWQ_(32 - j);
    if (j <= 48) return -TWQ_(j - 32);
    return TWQ_(64 - j);
}
__device__ __host__ constexpr float twsin(int j) { return twcos(j + 48); }
__device__ __host__ constexpr int brevN(int n, int bits) {
    int r = 0;
    for (int b = 0; b < bits; b++) r |= ((n >> b) & 1) << (bits - 1 - b);
    return r;
}

// fully unrolled 2^LOGN-pt radix-2 DIT FFT on registers (SGN=-1 fwd, +1 inv)
// twiddle exponent in W64 units = k << (5 - s)  (valid for N = 16/32/64)
template<int SGN, int LOGN>
__device__ __forceinline__ void fftreg(float* xr, float* xi) {
    const int N = 1 << LOGN;
    #pragma unroll
    for (int n = 1; n < N; n++) {
        const int r = brevN(n, LOGN);
        if (r > n) {
            float a = xr[n]; xr[n] = xr[r]; xr[r] = a;
            float b = xi[n]; xi[n] = xi[r]; xi[r] = b;
        }
    }
    #pragma unroll
    for (int s = 0; s < LOGN; s++) {
        const int half = 1 << s;
        #pragma unroll
        for (int j = 0; j < N/2; j++) {
            const int k  = j & (half - 1);
            const int g  = j >> s;
            const int i1 = g * (half << 1) + k;
            const int i2 = i1 + half;
            const float wr = twcos(k << (5 - s));
            const float wi = (float)SGN * twsin(k << (5 - s));
            float vr = xr[i2], vi = xi[i2];
            float tr = vr * wr - vi * wi;
            float ti = vr * wi + vi * wr;
            float ur = xr[i1], ui = xi[i1];
            xr[i1] = ur + tr;  xi[i1] = ui + ti;
            xr[i2] = ur - tr;  xi[i2] = ui - ti;
        }
    }
}

__device__ __forceinline__ float sigm(float v) { return 1.f / (1.f + __expf(-v)); }
__device__ __forceinline__ float ftanh(float v) { return 2.f / (1.f + __expf(-2.f*v)) - 1.f; }
__device__ __forceinline__ float2 h2f(__half2 h) { return __half22float2(h); }

// ================= 2-way split packed real-FFT pipeline ======================
// line = one x (64 y-samples). 2 threads/line: half=0 -> even Z bins / y 0..31,
// half=1 -> odd Z bins / y 32..63. Partner exchange = shfl_xor 16.

// inverse: X[0..32] (half2, coalesced over t) -> 16 packed samples per thread
__device__ __forceinline__ void irfft_build2(const __half2* __restrict__ A,
                                             int t, int half, float* zr, float* zi) {
    if (!half) {
        float2 x0  = h2f(A[t]);
        float2 x32 = h2f(A[32*64 + t]);
        float2 x16 = h2f(A[16*64 + t]);
        zr[0] = 0.5f*(x0.x + x32.x);   zi[0] = 0.5f*(x0.x - x32.x);   // Z[0]
        zr[8] = x16.x;                 zi[8] = -x16.y;                // Z[16]
        #pragma unroll
        for (int k = 2; k <= 14; k += 2) {
            float2 a = h2f(A[k*64 + t]);
            float2 b = h2f(A[(32-k)*64 + t]);
            float Sr = 0.5f*(a.x + b.x), Si = 0.5f*(a.y - b.y);
            float Dr = 0.5f*(a.x - b.x), Di = 0.5f*(a.y + b.y);
            const float c = twcos(k), s = twsin(k);
            float XoR = c*Dr - s*Di;
            float XoI = c*Di + s*Dr;
            zr[k/2]    = Sr - XoI;  zi[k/2]    = Si + XoR;   // Z[k]
            zr[16-k/2] = Sr + XoI;  zi[16-k/2] = XoR - Si;   // Z[32-k]
        }
    } else {
        #pragma unroll
        for (int k = 1; k <= 15; k += 2) {
            float2 a = h2f(A[k*64 + t]);
            float2 b = h2f(A[(32-k)*64 + t]);
            float Sr = 0.5f*(a.x + b.x), Si = 0.5f*(a.y - b.y);
            float Dr = 0.5f*(a.x - b.x), Di = 0.5f*(a.y + b.y);
            const float c = twcos(k), s = twsin(k);
            float XoR = c*Dr - s*Di;
            float XoI = c*Di + s*Dr;
            zr[(k-1)/2]      = Sr - XoI;  zi[(k-1)/2]      = Si + XoR; // Z[k]
            zr[15-(k-1)/2]   = Sr + XoI;  zi[15-(k-1)/2]   = XoR - Si; // Z[32-k]
        }
    }
    fftreg<1,4>(zr, zi);
    // DIT cross: z[j] = A + W32^{+j} B ; z[16+j] = A - W32^{j} B
    #pragma unroll
    for (int j = 0; j < 16; j++) {
        float br = __shfl_xor_sync(0xffffffffu, zr[j], 16);
        float bi = __shfl_xor_sync(0xffffffffu, zi[j], 16);
        const float c = twcos(2*j), s = twsin(2*j);
        if (!half) { zr[j] += br*c - bi*s;  zi[j] += br*s + bi*c; }
        else {
            float tr = zr[j]*c - zi[j]*s, ti = zr[j]*s + zi[j]*c;
            zr[j] = br - tr;  zi[j] = bi - ti;
        }
    }
}

// forward: 16 packed samples per thread -> X[0..32] half2, coalesced over t
__device__ __forceinline__ void rfft_store2(__half2* __restrict__ out,
                                            int t, int half, float* zr, float* zi) {
    // DIF cross: u = z[j]+z[16+j] (lo) ; t = (z[j]-z[16+j])·W32^{-j} (hi)
    #pragma unroll
    for (int j = 0; j < 16; j++) {
        float br = __shfl_xor_sync(0xffffffffu, zr[j], 16);
        float bi = __shfl_xor_sync(0xffffffffu, zi[j], 16);
        if (!half) { zr[j] += br;  zi[j] += bi; }
        else {
            float dr = br - zr[j], di = bi - zi[j];
            const float c = twcos(2*j), s = twsin(2*j);
            zr[j] = dr*c + di*s;
            zi[j] = di*c - dr*s;
        }
    }
    fftreg<-1,4>(zr, zi);
    if (!half) {   // even Z bins: E[m] = Z[2m]
        out[0*64 + t]  = __floats2half2_rn(zr[0] + zi[0], 0.f);
        out[32*64 + t] = __floats2half2_rn(zr[0] - zi[0], 0.f);
        out[16*64 + t] = __floats2half2_rn(zr[8], -zi[8]);
        #pragma unroll
        for (int k = 2; k <= 14; k += 2) {
            const int m = k/2, mq = 16 - k/2;
            float XeR = 0.5f*(zr[m] + zr[mq]), XeI = 0.5f*(zi[m] - zi[mq]);
            float XoR = 0.5f*(zi[m] + zi[mq]), XoI = 0.5f*(zr[mq] - zr[m]);
            const float c = twcos(k), s = twsin(k);
            float wXoR = c*XoR + s*XoI;
            float wXoI = c*XoI - s*XoR;
            out[k*64 + t]      = __floats2half2_rn(XeR + wXoR, XeI + wXoI);
            out[(32-k)*64 + t] = __floats2half2_rn(XeR - wXoR, -(XeI - wXoI));
        }
    } else {       // odd Z bins: O[m] = Z[2m+1]
        #pragma unroll
        for (int k = 1; k <= 15; k += 2) {
            const int m = (k-1)/2, mq = 15 - (k-1)/2;
            float XeR = 0.5f*(zr[m] + zr[mq]), XeI = 0.5f*(zi[m] - zi[mq]);
            float XoR = 0.5f*(zi[m] + zi[mq]), XoI = 0.5f*(zr[mq] - zr[m]);
            const float c = twcos(k), s = twsin(k);
            float wXoR = c*XoR + s*XoI;
            float wXoI = c*XoI - s*XoR;
            out[k*64 + t]      = __floats2half2_rn(XeR + wXoR, XeI + wXoI);
            out[(32-k)*64 + t] = __floats2half2_rn(XeR - wXoR, -(XeI - wXoI));
        }
    }
}

// ---- single-thread forward rfft (prologue only) ----------------------------
__device__ __forceinline__ void rfft_store1(__half2* __restrict__ out, int t,
                                            float* zr, float* zi) {
    fftreg<-1,5>(zr, zi);
    out[0*64 + t]  = __floats2half2_rn(zr[0] + zi[0], 0.f);
    out[32*64 + t] = __floats2half2_rn(zr[0] - zi[0], 0.f);
    out[16*64 + t] = __floats2half2_rn(zr[16], -zi[16]);
    #pragma unroll
    for (int k = 1; k < 16; k++) {
        const int q = 32 - k;
        float XeR = 0.5f*(zr[k] + zr[q]), XeI = 0.5f*(zi[k] - zi[q]);
        float XoR = 0.5f*(zi[k] + zi[q]), XoI = 0.5f*(zr[q] - zr[k]);
        const float c = twcos(k), s = twsin(k);
        float wXoR = c*XoR + s*XoI;
        float wXoI = c*XoI - s*XoR;
        out[k*64 + t] = __floats2half2_rn(XeR + wXoR, XeI + wXoI);
        out[q*64 + t] = __floats2half2_rn(XeR - wXoR, -(XeI - wXoI));
    }
}

// ---------------- weight transpose: [i][o][f] -> [f][i*64+o] fp16 -----------
__global__ void k_wt_all(const float* __restrict__ p0r, const float* __restrict__ p0i,
                         const float* __restrict__ p1r, const float* __restrict__ p1i,
                         const float* __restrict__ p2r, const float* __restrict__ p2i) {
    __shared__ float s_r[64*65];
    __shared__ float s_i[64*65];
    int gate = blockIdx.z;
    const float* wr = gate == 0 ? p0r : (gate == 1 ? p1r : p2r);
    const float* wi = gate == 0 ? p0i : (gate == 1 ? p1i : p2i);
    int f0  = blockIdx.x * 64;
    int io0 = blockIdx.y * 64;
    int lane = threadIdx.x & 63;
    int row  = threadIdx.x >> 6;
    #pragma unroll
    for (int r = row; r < 64; r += 4) {
        s_r[r*65 + lane] = wr[(size_t)(io0 + r) * NF + f0 + lane];
        s_i[r*65 + lane] = wi[(size_t)(io0 + r) * NF + f0 + lane];
    }
    __syncthreads();
    __half2* out = d_Wt[gate];
    #pragma unroll
    for (int fl = row; fl < 64; fl += 4) {
        out[(size_t)(f0 + fl) * 4096 + io0 + lane] =
            __floats2half2_rn(s_r[lane*65 + fl], s_i[lane*65 + fl]);
    }
}

// ---------------- h0 = x @ Wi + bi (CIN=1) ----------------------------------
__global__ void k_init_h(const float* __restrict__ x, const float* __restrict__ Wi,
                         const float* __restrict__ bi) {
    int idx = blockIdx.x * 256 + threadIdx.x;
    int bw = idx >> 12;
    int xy = idx & 4095;
    int b = bw >> 6, w = bw & 63;
    d_h[idx] = x[b * TILE + xy] * Wi[w] + bi[w];
}

// ---------------- prologue: y-rfft of h (runs once) --------------------------
__global__ void k_fwd1() {
    int bw = blockIdx.x, t = threadIdx.x;      // 64 threads, t = x
    const float4* row = reinterpret_cast<const float4*>(d_h + (size_t)bw * TILE + t*64);
    float zr[32], zi[32];
    #pragma unroll
    for (int j = 0; j < 16; j++) {
        float4 v = row[j];
        zr[2*j] = v.x; zi[2*j] = v.y; zr[2*j+1] = v.z; zi[2*j+1] = v.w;
    }
    rfft_store1(d_A1 + (size_t)bw * YHN * 64, t, zr, zi);
}

// ---------------- x-FFT (4-way DIF): d_A1[bw][k][x] -> d_Hf[f][bw] -----------
__global__ void k_fwd2() {
    int k = blockIdx.x;                         // 0..32
    int lane = threadIdx.x & 31;
    int wid  = threadIdx.x >> 5;                // 4 warps
    int q = lane >> 3;                          // quarter 0..3
    int r = lane & 7;
    int bw = blockIdx.y * 32 + wid * 8 + r;
    bool qlo1 = (q < 2);
    bool qodd = (q & 1);

    float ar[16], ai[16];
    const uint4* src = reinterpret_cast<const uint4*>(
        d_A1 + ((size_t)bw*YHN + k)*64 + 16*q);
    #pragma unroll
    for (int j = 0; j < 4; j++) {
        uint4 v = src[j];
        float2 c0 = h2f(*reinterpret_cast<__half2*>(&v.x));
        float2 c1 = h2f(*reinterpret_cast<__half2*>(&v.y));
        float2 c2 = h2f(*reinterpret_cast<__half2*>(&v.z));
        float2 c3 = h2f(*reinterpret_cast<__half2*>(&v.w));
        ar[4*j+0] = c0.x; ai[4*j+0] = c0.y;
        ar[4*j+1] = c1.x; ai[4*j+1] = c1.y;
        ar[4*j+2] = c2.x; ai[4*j+2] = c2.y;
        ar[4*j+3] = c3.x; ai[4*j+3] = c3.y;
    }
    // stage A (dist 32, xor16): hi: (a-b)·W64^{16(q&1)+j}
    #pragma unroll
    for (int j = 0; j < 16; j++) {
        float br = __shfl_xor_sync(0xffffffffu, ar[j], 16);
        float bi = __shfl_xor_sync(0xffffffffu, ai[j], 16);
        if (qlo1) { ar[j] += br;  ai[j] += bi; }
        else {
            float dr = br - ar[j], di = bi - ai[j];
            const float cj = twcos(j), sj = twsin(j);
            float c = qodd ? -sj : cj;
            float s = qodd ?  cj : sj;
            ar[j] = dr*c + di*s;
            ai[j] = di*c - dr*s;
        }
    }
    // stage B (dist 16, xor8): hi: (a-b)·W64^{2j}
    #pragma unroll
    for (int j = 0; j < 16; j++) {
        float br = __shfl_xor_sync(0xffffffffu, ar[j], 8);
        float bi = __shfl_xor_sync(0xffffffffu, ai[j], 8);
        if (!qodd) { ar[j] += br;  ai[j] += bi; }
        else {
            float dr = br - ar[j], di = bi - ai[j];
            const float c = twcos(2*j), s = twsin(2*j);
            ar[j] = dr*c + di*s;
            ai[j] = di*c - dr*s;
        }
    }
    fftreg<-1,4>(ar, ai);
    int cq = ((q & 1) << 1) | (q >> 1);         // [0,2,1,3]
    #pragma unroll
    for (int m = 0; m < 16; m++)
        d_Hf[((size_t)(4*m + cq)*YHN + k)*BWN + bw] = __floats2half2_rn(ar[m], ai[m]);
}

// ---------------- per-frequency complex GEMM (fp16 weights, fp32 accum) -----
__global__ void k_gemm(int pass) {
    int f = blockIdx.x;

    __shared__ __align__(16) float Hsr[64*HS_LS];
    __shared__ __align__(16) float Hsi[64*HS_LS];
    __shared__ __align__(16) __half2 Ws[64*64];
    int tid = threadIdx.x;             // 128

    const __half2* Hsrc = d_Hf + (size_t)f * BWN;
    #pragma unroll
    for (int i = tid; i < BWN; i += 128) {
        float2 v = h2f(Hsrc[i]);
        int b = i >> 6, w = i & 63;
        Hsr[w*HS_LS + b] = v.x;
        Hsi[w*HS_LS + b] = v.y;
    }

    int og = tid & 31;
    int bg = (tid >> 5) * 4;
    const int ngates = (pass == 0) ? 2 : 1;

    for (int g = 0; g < ngates; g++) {
        const __half2* Wt = (pass == 0) ? d_Wt[g] : d_Wt[2];
        __half2* O = (pass == 0 && g == 1) ? d_F1 : d_F0;

        __syncthreads();
        const float4* Wsrc = reinterpret_cast<const float4*>(Wt + (size_t)f * 4096);
        float4* Wdst = reinterpret_cast<float4*>(Ws);
        #pragma unroll
        for (int i = tid; i < 1024; i += 128) Wdst[i] = Wsrc[i];
        __syncthreads();

        u64x ar[2][2] = {{0,0},{0,0}};
        u64x ai[2][2] = {{0,0},{0,0}};

        #pragma unroll 8
        for (int w = 0; w < 64; w++) {
            u64x hr0 = *reinterpret_cast<const u64x*>(&Hsr[w*HS_LS + bg]);
            u64x hr1 = *reinterpret_cast<const u64x*>(&Hsr[w*HS_LS + bg + 2]);
            u64x hi0 = *reinterpret_cast<const u64x*>(&Hsi[w*HS_LS + bg]);
            u64x hi1 = *reinterpret_cast<const u64x*>(&Hsi[w*HS_LS + bg + 2]);
            float2 w0 = h2f(Ws[w*64 + og]);
            float2 w1 = h2f(Ws[w*64 + og + 32]);
            {
                u64x wr2 = pk2(w0.x, w0.x), wi2 = pk2(w0.y, w0.y), ni2 = pk2(-w0.y, -w0.y);
                FMA2(hr0, wr2, ar[0][0]); FMA2(hi0, ni2, ar[0][0]);
                FMA2(hr1, wr2, ar[0][1]); FMA2(hi1, ni2, ar[0][1]);
                FMA2(hr0, wi2, ai[0][0]); FMA2(hi0, wr2, ai[0][0]);
                FMA2(hr1, wi2, ai[0][1]); FMA2(hi1, wr2, ai[0][1]);
            }
            {
                u64x wr2 = pk2(w1.x, w1.x), wi2 = pk2(w1.y, w1.y), ni2 = pk2(-w1.y, -w1.y);
                FMA2(hr0, wr2, ar[1][0]); FMA2(hi0, ni2, ar[1][0]);
                FMA2(hr1, wr2, ar[1][1]); FMA2(hi1, ni2, ar[1][1]);
                FMA2(hr0, wi2, ai[1][0]); FMA2(hi0, wr2, ai[1][0]);
                FMA2(hr1, wi2, ai[1][1]); FMA2(hi1, wr2, ai[1][1]);
            }
        }
        #pragma unroll
        for (int oi = 0; oi < 2; oi++) {
            int o = og + oi*32;
            #pragma unroll
            for (int p = 0; p < 2; p++) {
                float r0, r1, i0, i1;
                upk2(ar[oi][p], r0, r1);
                upk2(ai[oi][p], i0, i1);
                O[(size_t)f * BWN + (bg + 2*p + 0)*64 + o] = __floats2half2_rn(r0, i0);
                O[(size_t)f * BWN + (bg + 2*p + 1)*64 + o] = __floats2half2_rn(r1, i1);
            }
        }
    }
}

// ---------------- inverse x-FFT (4-way DIT): d_F -> d_Ax ---------------------
// pass0: z=0: F0->Ax0, z=1: F1->Ax1.  pass1: F0->Ax1.
__global__ void k_inv1(int pass) {
    int k = blockIdx.x;
    int lane = threadIdx.x & 31;
    int wid  = threadIdx.x >> 5;
    int q = lane >> 3;
    int r = lane & 7;
    int bw = blockIdx.y * 32 + wid * 8 + r;
    bool qlo1 = (q < 2);
    bool qodd = (q & 1);
    const __half2* F = (pass == 0 && blockIdx.z == 1) ? d_F1 : d_F0;
    __half2* A = (pass == 1 || blockIdx.z == 1) ? d_Ax1 : d_Ax0;

    int cq = ((q & 1) << 1) | (q >> 1);
    float ar[16], ai[16];
    #pragma unroll
    for (int m = 0; m < 16; m++) {
        float2 v = h2f(F[((size_t)(4*m + cq)*YHN + k)*BWN + bw]);
        ar[m] = v.x; ai[m] = v.y;
    }
    fftreg<1,4>(ar, ai);
    // stage B' (xor8, inverse): q even: u[j] = A + W64^{+2j}B ; q odd: u[16+j] = A - W^{2j}B
    #pragma unroll
    for (int j = 0; j < 16; j++) {
        float br = __shfl_xor_sync(0xffffffffu, ar[j], 8);
        float bi = __shfl_xor_sync(0xffffffffu, ai[j], 8);
        const float c = twcos(2*j), s = twsin(2*j);
        if (!qodd) { ar[j] += br*c - bi*s;  ai[j] += br*s + bi*c; }
        else {
            float tr = ar[j]*c - ai[j]*s, ti = ar[j]*s + ai[j]*c;
            ar[j] = br - tr;  ai[j] = bi - ti;
        }
    }
    // stage A' (xor16): x[i] = u[i] + W64^{+i}v[i]; x[i+32] = u[i] - W^i v[i], i = 16(q&1)+j
    #pragma unroll
    for (int j = 0; j < 16; j++) {
        float br = __shfl_xor_sync(0xffffffffu, ar[j], 16);
        float bi = __shfl_xor_sync(0xffffffffu, ai[j], 16);
        const float cj = twcos(j), sj = twsin(j);
        float c = qodd ? -sj : cj;
        float s = qodd ?  cj : sj;
        if (qlo1) { ar[j] += br*c - bi*s;  ai[j] += br*s + bi*c; }
        else {
            float tr = ar[j]*c - ai[j]*s, ti = ar[j]*s + ai[j]*c;
            ar[j] = br - tr;  ai[j] = bi - ti;
        }
    }
    // thread q holds x[16q + j] -> dense store
    uint2* dst = reinterpret_cast<uint2*>(A + ((size_t)bw*YHN + k)*64 + 16*q);
    #pragma unroll
    for (int j = 0; j < 8; j++) {
        __half2 h0 = __floats2half2_rn(ar[2*j],   ai[2*j]);
        __half2 h1 = __floats2half2_rn(ar[2*j+1], ai[2*j+1]);
        uint2 u;
        u.x = *reinterpret_cast<unsigned int*>(&h0);
        u.y = *reinterpret_cast<unsigned int*>(&h1);
        dst[j] = u;
    }
}

// ---------------- fused: g = sigm(irfft(Ax1))·h, y-rfft(g) -------------------
__global__ void k_fused_zr() {
    int bw = blockIdx.x;
    int lane = threadIdx.x & 31, wid = threadIdx.x >> 5;
    int t = wid*16 + (lane & 15);
    int half = lane >> 4;
    const float sc = 1.f / 2048.f;
    float zr[16], zi[16];
    irfft_build2(d_Ax1 + (size_t)bw * YHN * 64, t, half, zr, zi);
    const float4* hrow = reinterpret_cast<const float4*>(
        d_h + (size_t)bw * TILE + t*64 + 32*half);
    #pragma unroll
    for (int j = 0; j < 8; j++) {
        float4 h4 = hrow[j];
        zr[2*j]   = h4.x * sigm(zr[2*j]*sc);
        zi[2*j]   = h4.y * sigm(zi[2*j]*sc);
        zr[2*j+1] = h4.z * sigm(zr[2*j+1]*sc);
        zi[2*j+1] = h4.w * sigm(zi[2*j+1]*sc);
    }
    rfft_store2(d_A1 + (size_t)bw * YHN * 64, t, half, zr, zi);
}

// ---------------- fused: z = sigm(irfft(Ax0)), h += z(tanh(irfft(Ax1)) - h) --
__global__ void k_fused_h(int last) {
    int bw = blockIdx.x;
    int lane = threadIdx.x & 31, wid = threadIdx.x >> 5;
    int t = wid*16 + (lane & 15);
    int half = lane >> 4;
    const float sc = 1.f / 2048.f;
    float zvr[16], zvi[16];
    irfft_build2(d_Ax0 + (size_t)bw * YHN * 64, t, half, zvr, zvi);
    #pragma unroll
    for (int j = 0; j < 16; j++) { zvr[j] = sigm(zvr[j]*sc); zvi[j] = sigm(zvi[j]*sc); }
    float nr[16], ni[16];
    irfft_build2(d_Ax1 + (size_t)bw * YHN * 64, t, half, nr, ni);
    float4* hrow = reinterpret_cast<float4*>(
        d_h + (size_t)bw * TILE + t*64 + 32*half);
    #pragma unroll
    for (int j = 0; j < 8; j++) {
        float4 h4 = hrow[j];
        float n0 = ftanh(nr[2*j]*sc),   n1 = ftanh(ni[2*j]*sc);
        float n2 = ftanh(nr[2*j+1]*sc), n3 = ftanh(ni[2*j+1]*sc);
        h4.x += zvr[2*j]   * (n0 - h4.x);
        h4.y += zvi[2*j]   * (n1 - h4.y);
        h4.z += zvr[2*j+1] * (n2 - h4.z);
        h4.w += zvi[2*j+1] * (n3 - h4.w);
        hrow[j] = h4;
        nr[2*j] = h4.x; ni[2*j] = h4.y; nr[2*j+1] = h4.z; ni[2*j+1] = h4.w;
    }
    if (!last)
        rfft_store2(d_A1 + (size_t)bw * YHN * 64, t, half, nr, ni);
}

// ---------------- out mapping: y = h @ Wo + bo ------------------------------
__global__ void k_out(const float* __restrict__ Wo, const float* __restrict__ bo,
                      float* __restrict__ out, int t) {
    int b = blockIdx.x;
    int xy = blockIdx.y * 256 + threadIdx.x;
    float acc = bo[0];
    const float* hb = d_h + (size_t)(b*64) * TILE + xy;
    #pragma unroll 8
    for (int w = 0; w < 64; w++)
        acc += hb[(size_t)w * TILE] * __ldg(&Wo[w]);
    out[(size_t)(b*TT + t) * TILE + xy] = acc;
}

// ---------------- launch -----------------------------------------------------
extern "C" void kernel_launch(void* const* d_in, const int* in_sizes, int n_in,
                              void* d_out, int out_size) {
    int iX = 0, iWi = 2, iBi = 3, iWo = 4, iBo = 5, iWz = 6;
    if (n_in == 11) { iWi = 1; iBi = 2; iWo = 3; iBo = 4; iWz = 5; }

    const float* x    = (const float*)d_in[iX];
    const float* Wi   = (const float*)d_in[iWi];
    const float* bi   = (const float*)d_in[iBi];
    const float* Wo   = (const float*)d_in[iWo];
    const float* bo   = (const float*)d_in[iBo];
    float* out = (float*)d_out;

    k_wt_all<<<dim3(33, 64, 3), 256>>>((const float*)d_in[iWz+0], (const float*)d_in[iWz+1],
                                       (const float*)d_in[iWz+2], (const float*)d_in[iWz+3],
                                       (const float*)d_in[iWz+4], (const float*)d_in[iWz+5]);
    k_init_h<<<(BWN*TILE)/256, 256>>>(x, Wi, bi);
    k_fwd1<<<BWN, 64>>>();
    k_fwd2<<<dim3(YHN, 32), 128>>>();

    for (int t = 0; t < TT; t++) {
        k_gemm<<<NF, 128>>>(0);                    // z -> F0, r -> F1
        k_inv1<<<dim3(YHN, 32, 2), 128>>>(0);      // F0->Ax0 (z), F1->Ax1 (r)
        k_fused_zr<<<BWN, 128>>>();                // g = r*h, y-rfft(g) -> A1
        k_fwd2<<<dim3(YHN, 32), 128>>>();          // x-FFT(g) -> Hf
        k_gemm<<<NF, 128>>>(1);                    // nh -> F0
        k_inv1<<<dim3(YHN, 32, 1), 128>>>(1);      // F0 -> Ax1 (nh); Ax0 keeps z
        k_fused_h<<<BWN, 128>>>(t == TT-1);        // z+nh irfft, h update, y-rfft
        if (t < TT-1) k_fwd2<<<dim3(YHN, 32), 128>>>();
        k_out<<<dim3(BB, TILE/256), 256>>>(Wo, bo, out, t);
    }
}

// round 10
// speedup vs baseline: 3.4861x; 1.2690x over previous
#include <cuda_runtime.h>
#include <cuda_fp16.h>
#include <math.h>

#define BB   16
#define WWC  64
#define TT   20
#define YHN  33
#define NF   2112          // 64 * 33
#define BWN  1024          // BB * WWC
#define TILE 4096
#define LDH  72            // H smem row stride in halfs (144B, bank-rotating)
#define LDW  72            // W smem row stride in halfs
#define WFS  9216          // halfs per f per gate: 2 planes * 64 * 72

typedef unsigned int u32;

// ---------------- device scratch ------------------------------------------
static __device__ float  d_h [BWN*TILE];
static __device__ __align__(16) __half2 d_A1 [(size_t)BWN*YHN*64];   // [bw][k][x]
static __device__ __align__(16) __half2 d_Hf [(size_t)NF*BWN];       // [f][bw]
static __device__ __align__(16) __half2 d_F0 [(size_t)NF*BWN];
static __device__ __align__(16) __half2 d_F1 [(size_t)NF*BWN];
static __device__ __align__(16) __half2 d_Ax0[(size_t)BWN*YHN*64];   // [bw][k][x]
static __device__ __align__(16) __half2 d_Ax1[(size_t)BWN*YHN*64];
static __device__ __align__(16) __half  d_Wt [3][(size_t)NF*WFS];    // [f][p][w][o]

// ---------------- mma / ldmatrix helpers -------------------------------------
__device__ __forceinline__ u32 smem_u32(const void* p) {
    return (u32)__cvta_generic_to_shared(p);
}
__device__ __forceinline__ void ldsm_x4(u32& r0, u32& r1, u32& r2,
                                        u32& r3, u32 addr) {
    asm volatile("ldmatrix.sync.aligned.m8n8.x4.shared.b16 {%0,%1,%2,%3},[%4];"
                 : "=r"(r0), "=r"(r1), "=r"(r2), "=r"(r3) : "r"(addr));
}
__device__ __forceinline__ void ldsm_x4t(u32& r0, u32& r1, u32& r2,
                                         u32& r3, u32 addr) {
    asm volatile("ldmatrix.sync.aligned.m8n8.x4.trans.shared.b16 {%0,%1,%2,%3},[%4];"
                 : "=r"(r0), "=r"(r1), "=r"(r2), "=r"(r3) : "r"(addr));
}
__device__ __forceinline__ void mma16816(float* c, const u32* a,
                                         u32 b0, u32 b1) {
    asm volatile(
        "mma.sync.aligned.m16n8k16.row.col.f32.f16.f16.f32 "
        "{%0,%1,%2,%3},{%4,%5,%6,%7},{%8,%9},{%0,%1,%2,%3};"
        : "+f"(c[0]), "+f"(c[1]), "+f"(c[2]), "+f"(c[3])
        : "r"(a[0]), "r"(a[1]), "r"(a[2]), "r"(a[3]), "r"(b0), "r"(b1));
}

// ---------------- compile-time twiddles (units of 2*pi/64) ------------------
__device__ __host__ constexpr float TWQ_(int i) {
    constexpr float q[17] = {
        1.000000000f, 0.995184727f, 0.980785280f, 0.956940336f,
        0.923879533f, 0.881921264f, 0.831469612f, 0.773010453f,
        0.707106781f, 0.634393284f, 0.555570233f, 0.471396737f,
        0.382683432f, 0.290284677f, 0.195090322f, 0.098017140f, 0.f };
    return q[i];
}
__device__ __host__ constexpr float twcos(int j) {
    j &= 63;
    if (j <= 16) return TWQ_(j);
    if (j <= 32) return -TWQ_(32 - j);
    if (j <= 48) return -TWQ_(j - 32);
    return TWQ_(64 - j);
}
__device__ __host__ constexpr float twsin(int j) { return twcos(j + 48); }
__device__ __host__ constexpr int brevN(int n, int bits) {
    int r = 0;
    for (int b = 0; b < bits; b++) r |= ((n >> b) & 1) << (bits - 1 - b);
    return r;
}

// fully unrolled 2^LOGN-pt radix-2 DIT FFT on registers (SGN=-1 fwd, +1 inv)
template<int SGN, int LOGN>
__device__ __forceinline__ void fftreg(float* xr, float* xi) {
    const int N = 1 << LOGN;
    #pragma unroll
    for (int n = 1; n < N; n++) {
        const int r = brevN(n, LOGN);
        if (r > n) {
            float a = xr[n]; xr[n] = xr[r]; xr[r] = a;
            float b = xi[n]; xi[n] = xi[r]; xi[r] = b;
        }
    }
    #pragma unroll
    for (int s = 0; s < LOGN; s++) {
        const int half = 1 << s;
        #pragma unroll
        for (int j = 0; j < N/2; j++) {
            const int k  = j & (half - 1);
            const int g  = j >> s;
            const int i1 = g * (half << 1) + k;
            const int i2 = i1 + half;
            const float wr = twcos(k << (5 - s));
            const float wi = (float)SGN * twsin(k << (5 - s));
            float vr = xr[i2], vi = xi[i2];
            float tr = vr * wr - vi * wi;
            float ti = vr * wi + vi * wr;
            float ur = xr[i1], ui = xi[i1];
            xr[i1] = ur + tr;  xi[i1] = ui + ti;
            xr[i2] = ur - tr;  xi[i2] = ui - ti;
        }
    }
}

__device__ __forceinline__ float sigm(float v) { return 1.f / (1.f + __expf(-v)); }
__device__ __forceinline__ float ftanh(float v) { return 2.f / (1.f + __expf(-2.f*v)) - 1.f; }
__device__ __forceinline__ float2 h2f(__half2 h) { return __half22float2(h); }

// ================= 2-way split packed real-FFT pipeline ======================
__device__ __forceinline__ void irfft_build2(const __half2* __restrict__ A,
                                             int t, int hseg, float* zr, float* zi) {
    if (!hseg) {
        float2 x0  = h2f(A[t]);
        float2 x32 = h2f(A[32*64 + t]);
        float2 x16 = h2f(A[16*64 + t]);
        zr[0] = 0.5f*(x0.x + x32.x);   zi[0] = 0.5f*(x0.x - x32.x);
        zr[8] = x16.x;                 zi[8] = -x16.y;
        #pragma unroll
        for (int k = 2; k <= 14; k += 2) {
            float2 a = h2f(A[k*64 + t]);
            float2 b = h2f(A[(32-k)*64 + t]);
            float Sr = 0.5f*(a.x + b.x), Si = 0.5f*(a.y - b.y);
            float Dr = 0.5f*(a.x - b.x), Di = 0.5f*(a.y + b.y);
            const float c = twcos(k), s = twsin(k);
            float XoR = c*Dr - s*Di;
            float XoI = c*Di + s*Dr;
            zr[k/2]    = Sr - XoI;  zi[k/2]    = Si + XoR;
            zr[16-k/2] = Sr + XoI;  zi[16-k/2] = XoR - Si;
        }
    } else {
        #pragma unroll
        for (int k = 1; k <= 15; k += 2) {
            float2 a = h2f(A[k*64 + t]);
            float2 b = h2f(A[(32-k)*64 + t]);
            float Sr = 0.5f*(a.x + b.x), Si = 0.5f*(a.y - b.y);
            float Dr = 0.5f*(a.x - b.x), Di = 0.5f*(a.y + b.y);
            const float c = twcos(k), s = twsin(k);
            float XoR = c*Dr - s*Di;
            float XoI = c*Di + s*Dr;
            zr[(k-1)/2]      = Sr - XoI;  zi[(k-1)/2]      = Si + XoR;
            zr[15-(k-1)/2]   = Sr + XoI;  zi[15-(k-1)/2]   = XoR - Si;
        }
    }
    fftreg<1,4>(zr, zi);
    #pragma unroll
    for (int j = 0; j < 16; j++) {
        float br = __shfl_xor_sync(0xffffffffu, zr[j], 16);
        float bi = __shfl_xor_sync(0xffffffffu, zi[j], 16);
        const float c = twcos(2*j), s = twsin(2*j);
        if (!hseg) { zr[j] += br*c - bi*s;  zi[j] += br*s + bi*c; }
        else {
            float tr = zr[j]*c - zi[j]*s, ti = zr[j]*s + zi[j]*c;
            zr[j] = br - tr;  zi[j] = bi - ti;
        }
    }
}

__device__ __forceinline__ void rfft_store2(__half2* __restrict__ out,
                                            int t, int hseg, float* zr, float* zi) {
    #pragma unroll
    for (int j = 0; j < 16; j++) {
        float br = __shfl_xor_sync(0xffffffffu, zr[j], 16);
        float bi = __shfl_xor_sync(0xffffffffu, zi[j], 16);
        if (!hseg) { zr[j] += br;  zi[j] += bi; }
        else {
            float dr = br - zr[j], di = bi - zi[j];
            const float c = twcos(2*j), s = twsin(2*j);
            zr[j] = dr*c + di*s;
            zi[j] = di*c - dr*s;
        }
    }
    fftreg<-1,4>(zr, zi);
    if (!hseg) {
        out[0*64 + t]  = __floats2half2_rn(zr[0] + zi[0], 0.f);
        out[32*64 + t] = __floats2half2_rn(zr[0] - zi[0], 0.f);
        out[16*64 + t] = __floats2half2_rn(zr[8], -zi[8]);
        #pragma unroll
        for (int k = 2; k <= 14; k += 2) {
            const int m = k/2, mq = 16 - k/2;
            float XeR = 0.5f*(zr[m] + zr[mq]), XeI = 0.5f*(zi[m] - zi[mq]);
            float XoR = 0.5f*(zi[m] + zi[mq]), XoI = 0.5f*(zr[mq] - zr[m]);
            const float c = twcos(k), s = twsin(k);
            float wXoR = c*XoR + s*XoI;
            float wXoI = c*XoI - s*XoR;
            out[k*64 + t]      = __floats2half2_rn(XeR + wXoR, XeI + wXoI);
            out[(32-k)*64 + t] = __floats2half2_rn(XeR - wXoR, -(XeI - wXoI));
        }
    } else {
        #pragma unroll
        for (int k = 1; k <= 15; k += 2) {
            const int m = (k-1)/2, mq = 15 - (k-1)/2;
            float XeR = 0.5f*(zr[m] + zr[mq]), XeI = 0.5f*(zi[m] - zi[mq]);
            float XoR = 0.5f*(zi[m] + zi[mq]), XoI = 0.5f*(zr[mq] - zr[m]);
            const float c = twcos(k), s = twsin(k);
            float wXoR = c*XoR + s*XoI;
            float wXoI = c*XoI - s*XoR;
            out[k*64 + t]      = __floats2half2_rn(XeR + wXoR, XeI + wXoI);
            out[(32-k)*64 + t] = __floats2half2_rn(XeR - wXoR, -(XeI - wXoI));
        }
    }
}

// ---- single-thread forward rfft (prologue only) ----------------------------
__device__ __forceinline__ void rfft_store1(__half2* __restrict__ out, int t,
                                            float* zr, float* zi) {
    fftreg<-1,5>(zr, zi);
    out[0*64 + t]  = __floats2half2_rn(zr[0] + zi[0], 0.f);
    out[32*64 + t] = __floats2half2_rn(zr[0] - zi[0], 0.f);
    out[16*64 + t] = __floats2half2_rn(zr[16], -zi[16]);
    #pragma unroll
    for (int k = 1; k < 16; k++) {
        const int q = 32 - k;
        float XeR = 0.5f*(zr[k] + zr[q]), XeI = 0.5f*(zi[k] - zi[q]);
        float XoR = 0.5f*(zi[k] + zi[q]), XoI = 0.5f*(zr[q] - zr[k]);
        const float c = twcos(k), s = twsin(k);
        float wXoR = c*XoR + s*XoI;
        float wXoI = c*XoI - s*XoR;
        out[k*64 + t] = __floats2half2_rn(XeR + wXoR, XeI + wXoI);
        out[q*64 + t] = __floats2half2_rn(XeR - wXoR, -(XeI - wXoI));
    }
}

// ---------------- weight transpose: [i][o][f] -> [f][p][w=i][o] fp16 --------
__global__ void k_wt_all(const float* __restrict__ p0r, const float* __restrict__ p0i,
                         const float* __restrict__ p1r, const float* __restrict__ p1i,
                         const float* __restrict__ p2r, const float* __restrict__ p2i) {
    __shared__ float s_r[64*65];
    __shared__ float s_i[64*65];
    int gate = blockIdx.z;
    const float* wr = gate == 0 ? p0r : (gate == 1 ? p1r : p2r);
    const float* wi = gate == 0 ? p0i : (gate == 1 ? p1i : p2i);
    int f0  = blockIdx.x * 64;
    int io0 = blockIdx.y * 64;
    int lane = threadIdx.x & 63;
    int row  = threadIdx.x >> 6;
    #pragma unroll
    for (int r = row; r < 64; r += 4) {
        s_r[r*65 + lane] = wr[(size_t)(io0 + r) * NF + f0 + lane];
        s_i[r*65 + lane] = wi[(size_t)(io0 + r) * NF + f0 + lane];
    }
    __syncthreads();
    __half* out = d_Wt[gate];
    #pragma unroll
    for (int fl = row; fl < 64; fl += 4) {
        size_t base = (size_t)(f0 + fl) * WFS + (size_t)blockIdx.y * LDW + lane;
        out[base]        = __float2half_rn(s_r[lane*65 + fl]);
        out[base + 4608] = __float2half_rn(s_i[lane*65 + fl]);
    }
}

// ---------------- h0 = x @ Wi + bi (CIN=1) ----------------------------------
__global__ void k_init_h(const float* __restrict__ x, const float* __restrict__ Wi,
                         const float* __restrict__ bi) {
    int idx = blockIdx.x * 256 + threadIdx.x;
    int bw = idx >> 12;
    int xy = idx & 4095;
    int b = bw >> 6, w = bw & 63;
    d_h[idx] = x[b * TILE + xy] * Wi[w] + bi[w];
}

// ---------------- prologue: y-rfft of h (runs once) --------------------------
__global__ void k_fwd1() {
    int bw = blockIdx.x, t = threadIdx.x;
    const float4* row = reinterpret_cast<const float4*>(d_h + (size_t)bw * TILE + t*64);
    float zr[32], zi[32];
    #pragma unroll
    for (int j = 0; j < 16; j++) {
        float4 v = row[j];
        zr[2*j] = v.x; zi[2*j] = v.y; zr[2*j+1] = v.z; zi[2*j+1] = v.w;
    }
    rfft_store1(d_A1 + (size_t)bw * YHN * 64, t, zr, zi);
}

// ---------------- x-FFT (4-way DIF): d_A1[bw][k][x] -> d_Hf[f][bw] -----------
__global__ void k_fwd2() {
    int k = blockIdx.x;
    int lane = threadIdx.x & 31;
    int wid  = threadIdx.x >> 5;
    int q = lane >> 3;
    int r = lane & 7;
    int bw = blockIdx.y * 32 + wid * 8 + r;
    bool qlo1 = (q < 2);
    bool qodd = (q & 1);

    float ar[16], ai[16];
    const uint4* src = reinterpret_cast<const uint4*>(
        d_A1 + ((size_t)bw*YHN + k)*64 + 16*q);
    #pragma unroll
    for (int j = 0; j < 4; j++) {
        uint4 v = src[j];
        float2 c0 = h2f(*reinterpret_cast<__half2*>(&v.x));
        float2 c1 = h2f(*reinterpret_cast<__half2*>(&v.y));
        float2 c2 = h2f(*reinterpret_cast<__half2*>(&v.z));
        float2 c3 = h2f(*reinterpret_cast<__half2*>(&v.w));
        ar[4*j+0] = c0.x; ai[4*j+0] = c0.y;
        ar[4*j+1] = c1.x; ai[4*j+1] = c1.y;
        ar[4*j+2] = c2.x; ai[4*j+2] = c2.y;
        ar[4*j+3] = c3.x; ai[4*j+3] = c3.y;
    }
    #pragma unroll
    for (int j = 0; j < 16; j++) {
        float br = __shfl_xor_sync(0xffffffffu, ar[j], 16);
        float bi = __shfl_xor_sync(0xffffffffu, ai[j], 16);
        if (qlo1) { ar[j] += br;  ai[j] += bi; }
        else {
            float dr = br - ar[j], di = bi - ai[j];
            const float cj = twcos(j), sj = twsin(j);
            float c = qodd ? -sj : cj;
            float s = qodd ?  cj : sj;
            ar[j] = dr*c + di*s;
            ai[j] = di*c - dr*s;
        }
    }
    #pragma unroll
    for (int j = 0; j < 16; j++) {
        float br = __shfl_xor_sync(0xffffffffu, ar[j], 8);
        float bi = __shfl_xor_sync(0xffffffffu, ai[j], 8);
        if (!qodd) { ar[j] += br;  ai[j] += bi; }
        else {
            float dr = br - ar[j], di = bi - ai[j];
            const float c = twcos(2*j), s = twsin(2*j);
            ar[j] = dr*c + di*s;
            ai[j] = di*c - dr*s;
        }
    }
    fftreg<-1,4>(ar, ai);
    int cq = ((q & 1) << 1) | (q >> 1);
    #pragma unroll
    for (int m = 0; m < 16; m++)
        d_Hf[((size_t)(4*m + cq)*YHN + k)*BWN + bw] = __floats2half2_rn(ar[m], ai[m]);
}

// ---------------- per-frequency complex GEMM via tensor cores ----------------
// O[b][o] = sum_w H[b][w] * W[w][o] (complex), fp16 in / fp32 accum.
// Or = Hr*Wr + (-Hi)*Wi ; Oi = Hr*Wi + Hi*Wr.
__global__ void k_gemm(int pass) {
    int f = blockIdx.x;
    __shared__ __align__(16) __half sHr[16*LDH];
    __shared__ __align__(16) __half sHi[16*LDH];
    __shared__ __align__(16) __half sW[2*64*LDW];
    int tid = threadIdx.x;             // 128
    int lane = tid & 31, wid = tid >> 5;

    const __half2* Hsrc = d_Hf + (size_t)f * BWN;
    #pragma unroll
    for (int i = tid; i < BWN; i += 128) {
        __half2 v = Hsrc[i];
        int b = i >> 6, w = i & 63;
        sHr[b*LDH + w] = __low2half(v);
        sHi[b*LDH + w] = __high2half(v);
    }

    const int obase = wid * 16;
    const u32 baseHr = smem_u32(sHr);
    const u32 baseHi = smem_u32(sHi);
    const u32 baseW  = smem_u32(sW);
    const int arow = lane & 15, acol = (lane >> 4) * 8;
    const int ngates = (pass == 0) ? 2 : 1;

    for (int g = 0; g < ngates; g++) {
        const __half* Wg = d_Wt[pass == 0 ? g : 2] + (size_t)f * WFS;
        __half2* O = (pass == 0 && g == 1) ? d_F1 : d_F0;

        __syncthreads();
        {
            const uint4* src = reinterpret_cast<const uint4*>(Wg);
            uint4* dst = reinterpret_cast<uint4*>(sW);
            #pragma unroll
            for (int i = tid; i < 1152; i += 128) dst[i] = src[i];
        }
        __syncthreads();

        float cr[2][4] = {{0.f,0.f,0.f,0.f},{0.f,0.f,0.f,0.f}};
        float ci[2][4] = {{0.f,0.f,0.f,0.f},{0.f,0.f,0.f,0.f}};

        #pragma unroll
        for (int kk = 0; kk < 4; kk++) {
            u32 Ar[4], Ai[4], An[4];
            u32 aoff = (u32)((arow*LDH + kk*16 + acol) * 2);
            ldsm_x4(Ar[0], Ar[1], Ar[2], Ar[3], baseHr + aoff);
            ldsm_x4(Ai[0], Ai[1], Ai[2], Ai[3], baseHi + aoff);
            #pragma unroll
            for (int j = 0; j < 4; j++) An[j] = Ai[j] ^ 0x80008000u;

            u32 Br[4], Bi[4];
            u32 boff = (u32)(((kk*16 + (lane & 15))*LDW
                              + obase + (lane >> 4)*8) * 2);
            ldsm_x4t(Br[0], Br[1], Br[2], Br[3], baseW + boff);
            ldsm_x4t(Bi[0], Bi[1], Bi[2], Bi[3], baseW + (u32)(64*LDW*2) + boff);

            #pragma unroll
            for (int nt = 0; nt < 2; nt++) {
                mma16816(cr[nt], Ar, Br[2*nt], Br[2*nt+1]);
                mma16816(cr[nt], An, Bi[2*nt], Bi[2*nt+1]);
                mma16816(ci[nt], Ar, Bi[2*nt], Bi[2*nt+1]);
                mma16816(ci[nt], Ai, Br[2*nt], Br[2*nt+1]);
            }
        }

        __half2* Of = O + (size_t)f * BWN;
        int b0 = lane >> 2, oc = (lane & 3) * 2;
        #pragma unroll
        for (int nt = 0; nt < 2; nt++) {
            int o = obase + nt*8 + oc;
            __half2 p00 = __floats2half2_rn(cr[nt][0], ci[nt][0]);
            __half2 p01 = __floats2half2_rn(cr[nt][1], ci[nt][1]);
            uint2 u0;
            u0.x = *reinterpret_cast<u32*>(&p00);
            u0.y = *reinterpret_cast<u32*>(&p01);
            *reinterpret_cast<uint2*>(Of + b0*64 + o) = u0;
            __half2 p10 = __floats2half2_rn(cr[nt][2], ci[nt][2]);
            __half2 p11 = __floats2half2_rn(cr[nt][3], ci[nt][3]);
            uint2 u1;
            u1.x = *reinterpret_cast<u32*>(&p10);
            u1.y = *reinterpret_cast<u32*>(&p11);
            *reinterpret_cast<uint2*>(Of + (b0+8)*64 + o) = u1;
        }
    }
}

// ---------------- inverse x-FFT (4-way DIT): d_F -> d_Ax ---------------------
__global__ void k_inv1(int pass) {
    int k = blockIdx.x;
    int lane = threadIdx.x & 31;
    int wid  = threadIdx.x >> 5;
    int q = lane >> 3;
    int r = lane & 7;
    int bw = blockIdx.y * 32 + wid * 8 + r;
    bool qlo1 = (q < 2);
    bool qodd = (q & 1);
    const __half2* F = (pass == 0 && blockIdx.z == 1) ? d_F1 : d_F0;
    __half2* A = (pass == 1 || blockIdx.z == 1) ? d_Ax1 : d_Ax0;

    int cq = ((q & 1) << 1) | (q >> 1);
    float ar[16], ai[16];
    #pragma unroll
    for (int m = 0; m < 16; m++) {
        float2 v = h2f(F[((size_t)(4*m + cq)*YHN + k)*BWN + bw]);
        ar[m] = v.x; ai[m] = v.y;
    }
    fftreg<1,4>(ar, ai);
    #pragma unroll
    for (int j = 0; j < 16; j++) {
        float br = __shfl_xor_sync(0xffffffffu, ar[j], 8);
        float bi = __shfl_xor_sync(0xffffffffu, ai[j], 8);
        const float c = twcos(2*j), s = twsin(2*j);
        if (!qodd) { ar[j] += br*c - bi*s;  ai[j] += br*s + bi*c; }
        else {
            float tr = ar[j]*c - ai[j]*s, ti = ar[j]*s + ai[j]*c;
            ar[j] = br - tr;  ai[j] = bi - ti;
        }
    }
    #pragma unroll
    for (int j = 0; j < 16; j++) {
        float br = __shfl_xor_sync(0xffffffffu, ar[j], 16);
        float bi = __shfl_xor_sync(0xffffffffu, ai[j], 16);
        const float cj = twcos(j), sj = twsin(j);
        float c = qodd ? -sj : cj;
        float s = qodd ?  cj : sj;
        if (qlo1) { ar[j] += br*c - bi*s;  ai[j] += br*s + bi*c; }
        else {
            float tr = ar[j]*c - ai[j]*s, ti = ar[j]*s + ai[j]*c;
            ar[j] = br - tr;  ai[j] = bi - ti;
        }
    }
    uint2* dst = reinterpret_cast<uint2*>(A + ((size_t)bw*YHN + k)*64 + 16*q);
    #pragma unroll
    for (int j = 0; j < 8; j++) {
        __half2 h0 = __floats2half2_rn(ar[2*j],   ai[2*j]);
        __half2 h1 = __floats2half2_rn(ar[2*j+1], ai[2*j+1]);
        uint2 u;
        u.x = *reinterpret_cast<u32*>(&h0);
        u.y = *reinterpret_cast<u32*>(&h1);
        dst[j] = u;
    }
}

// ---------------- fused: g = sigm(irfft(Ax1))*h, y-rfft(g) -------------------
__global__ void k_fused_zr() {
    int bw = blockIdx.x;
    int lane = threadIdx.x & 31, wid = threadIdx.x >> 5;
    int t = wid*16 + (lane & 15);
    int hseg = lane >> 4;
    const float sc = 1.f / 2048.f;
    float zr[16], zi[16];
    irfft_build2(d_Ax1 + (size_t)bw * YHN * 64, t, hseg, zr, zi);
    const float4* hrow = reinterpret_cast<const float4*>(
        d_h + (size_t)bw * TILE + t*64 + 32*hseg);
    #pragma unroll
    for (int j = 0; j < 8; j++) {
        float4 h4 = hrow[j];
        zr[2*j]   = h4.x * sigm(zr[2*j]*sc);
        zi[2*j]   = h4.y * sigm(zi[2*j]*sc);
        zr[2*j+1] = h4.z * sigm(zr[2*j+1]*sc);
        zi[2*j+1] = h4.w * sigm(zi[2*j+1]*sc);
    }
    rfft_store2(d_A1 + (size_t)bw * YHN * 64, t, hseg, zr, zi);
}

// ---------------- fused: z = sigm(irfft(Ax0)), h += z(tanh(irfft(Ax1)) - h) --
__global__ void k_fused_h(int last) {
    int bw = blockIdx.x;
    int lane = threadIdx.x & 31, wid = threadIdx.x >> 5;
    int t = wid*16 + (lane & 15);
    int hseg = lane >> 4;
    const float sc = 1.f / 2048.f;
    float zvr[16], zvi[16];
    irfft_build2(d_Ax0 + (size_t)bw * YHN * 64, t, hseg, zvr, zvi);
    #pragma unroll
    for (int j = 0; j < 16; j++) { zvr[j] = sigm(zvr[j]*sc); zvi[j] = sigm(zvi[j]*sc); }
    float nr[16], ni[16];
    irfft_build2(d_Ax1 + (size_t)bw * YHN * 64, t, hseg, nr, ni);
    float4* hrow = reinterpret_cast<float4*>(
        d_h + (size_t)bw * TILE + t*64 + 32*hseg);
    #pragma unroll
    for (int j = 0; j < 8; j++) {
        float4 h4 = hrow[j];
        float n0 = ftanh(nr[2*j]*sc),   n1 = ftanh(ni[2*j]*sc);
        float n2 = ftanh(nr[2*j+1]*sc), n3 = ftanh(ni[2*j+1]*sc);
        h4.x += zvr[2*j]   * (n0 - h4.x);
        h4.y += zvi[2*j]   * (n1 - h4.y);
        h4.z += zvr[2*j+1] * (n2 - h4.z);
        h4.w += zvi[2*j+1] * (n3 - h4.w);
        hrow[j] = h4;
        nr[2*j] = h4.x; ni[2*j] = h4.y; nr[2*j+1] = h4.z; ni[2*j+1] = h4.w;
    }
    if (!last)
        rfft_store2(d_A1 + (size_t)bw * YHN * 64, t, hseg, nr, ni);
}

// ---------------- out mapping: y = h @ Wo + bo ------------------------------
__global__ void k_out(const float* __restrict__ Wo, const float* __restrict__ bo,
                      float* __restrict__ out, int t) {
    int b = blockIdx.x;
    int xy = blockIdx.y * 256 + threadIdx.x;
    float acc = bo[0];
    const float* hb = d_h + (size_t)(b*64) * TILE + xy;
    #pragma unroll 8
    for (int w = 0; w < 64; w++)
        acc += hb[(size_t)w * TILE] * __ldg(&Wo[w]);
    out[(size_t)(b*TT + t) * TILE + xy] = acc;
}

// ---------------- launch -----------------------------------------------------
extern "C" void kernel_launch(void* const* d_in, const int* in_sizes, int n_in,
                              void* d_out, int out_size) {
    int iX = 0, iWi = 2, iBi = 3, iWo = 4, iBo = 5, iWz = 6;
    if (n_in == 11) { iWi = 1; iBi = 2; iWo = 3; iBo = 4; iWz = 5; }

    const float* x    = (const float*)d_in[iX];
    const float* Wi   = (const float*)d_in[iWi];
    const float* bi   = (const float*)d_in[iBi];
    const float* Wo   = (const float*)d_in[iWo];
    const float* bo   = (const float*)d_in[iBo];
    float* out = (float*)d_out;

    k_wt_all<<<dim3(33, 64, 3), 256>>>((const float*)d_in[iWz+0], (const float*)d_in[iWz+1],
                                       (const float*)d_in[iWz+2], (const float*)d_in[iWz+3],
                                       (const float*)d_in[iWz+4], (const float*)d_in[iWz+5]);
    k_init_h<<<(BWN*TILE)/256, 256>>>(x, Wi, bi);
    k_fwd1<<<BWN, 64>>>();
    k_fwd2<<<dim3(YHN, 32), 128>>>();

    for (int t = 0; t < TT; t++) {
        k_gemm<<<NF, 128>>>(0);                    // z -> F0, r -> F1
        k_inv1<<<dim3(YHN, 32, 2), 128>>>(0);      // F0->Ax0 (z), F1->Ax1 (r)
        k_fused_zr<<<BWN, 128>>>();                // g = r*h, y-rfft(g) -> A1
        k_fwd2<<<dim3(YHN, 32), 128>>>();          // x-FFT(g) -> Hf
        k_gemm<<<NF, 128>>>(1);                    // nh -> F0
        k_inv1<<<dim3(YHN, 32, 1), 128>>>(1);      // F0 -> Ax1 (nh); Ax0 keeps z
        k_fused_h<<<BWN, 128>>>(t == TT-1);        // z+nh irfft, h update, y-rfft
        if (t < TT-1) k_fwd2<<<dim3(YHN, 32), 128>>>();
        k_out<<<dim3(BB, TILE/256), 256>>>(Wo, bo, out, t);
    }
}

// round 11
// speedup vs baseline: 3.6657x; 1.0515x over previous
#include <cuda_runtime.h>
#include <cuda_fp16.h>
#include <math.h>

#define BB   16
#define WWC  64
#define TT   20
#define YHN  33
#define NF   2112          // 64 * 33
#define BWN  1024          // BB * WWC
#define TILE 4096
#define LDH  72            // H smem row stride in halfs (144B, bank-rotating)
#define LDW  72            // W smem row stride in halfs
#define WFS  8192          // halfs per f per gate in GLOBAL (compact): 2*64*64

typedef unsigned int u32;

// ---------------- device scratch ------------------------------------------
static __device__ float  d_h [BWN*TILE];
static __device__ __align__(16) __half2 d_A1 [(size_t)BWN*YHN*64];   // [bw][k][x]
static __device__ __align__(16) __half2 d_Hf [(size_t)NF*BWN];       // [f][bw]
static __device__ __align__(16) __half2 d_F0 [(size_t)NF*BWN];
static __device__ __align__(16) __half2 d_F1 [(size_t)NF*BWN];
static __device__ __align__(16) __half2 d_Ax0[(size_t)BWN*YHN*64];   // [bw][k][x]
static __device__ __align__(16) __half2 d_Ax1[(size_t)BWN*YHN*64];
static __device__ __align__(16) __half  d_Wt [3][(size_t)NF*WFS];    // [f][p][w][o] compact

// ---------------- PDL helpers -------------------------------------------------
__device__ __forceinline__ void pdl_wait()    { asm volatile("griddepcontrol.wait;" ::: "memory"); }
__device__ __forceinline__ void pdl_trigger() { asm volatile("griddepcontrol.launch_dependents;"); }

// ---------------- mma / ldmatrix helpers -------------------------------------
__device__ __forceinline__ u32 smem_u32(const void* p) {
    return (u32)__cvta_generic_to_shared(p);
}
__device__ __forceinline__ void ldsm_x4(u32& r0, u32& r1, u32& r2,
                                        u32& r3, u32 addr) {
    asm volatile("ldmatrix.sync.aligned.m8n8.x4.shared.b16 {%0,%1,%2,%3},[%4];"
                 : "=r"(r0), "=r"(r1), "=r"(r2), "=r"(r3) : "r"(addr));
}
__device__ __forceinline__ void ldsm_x4t(u32& r0, u32& r1, u32& r2,
                                         u32& r3, u32 addr) {
    asm volatile("ldmatrix.sync.aligned.m8n8.x4.trans.shared.b16 {%0,%1,%2,%3},[%4];"
                 : "=r"(r0), "=r"(r1), "=r"(r2), "=r"(r3) : "r"(addr));
}
__device__ __forceinline__ void mma16816(float* c, const u32* a,
                                         u32 b0, u32 b1) {
    asm volatile(
        "mma.sync.aligned.m16n8k16.row.col.f32.f16.f16.f32 "
        "{%0,%1,%2,%3},{%4,%5,%6,%7},{%8,%9},{%0,%1,%2,%3};"
        : "+f"(c[0]), "+f"(c[1]), "+f"(c[2]), "+f"(c[3])
        : "r"(a[0]), "r"(a[1]), "r"(a[2]), "r"(a[3]), "r"(b0), "r"(b1));
}

// ---------------- compile-time twiddles (units of 2*pi/64) ------------------
__device__ __host__ constexpr float TWQ_(int i) {
    constexpr float q[17] = {
        1.000000000f, 0.995184727f, 0.980785280f, 0.956940336f,
        0.923879533f, 0.881921264f, 0.831469612f, 0.773010453f,
        0.707106781f, 0.634393284f, 0.555570233f, 0.471396737f,
        0.382683432f, 0.290284677f, 0.195090322f, 0.098017140f, 0.f };
    return q[i];
}
__device__ __host__ constexpr float twcos(int j) {
    j &= 63;
    if (j <= 16) return TWQ_(j);
    if (j <= 32) return -TWQ_(32 - j);
    if (j <= 48) return -TWQ_(j - 32);
    return TWQ_(64 - j);
}
__device__ __host__ constexpr float twsin(int j) { return twcos(j + 48); }
__device__ __host__ constexpr int brevN(int n, int bits) {
    int r = 0;
    for (int b = 0; b < bits; b++) r |= ((n >> b) & 1) << (bits - 1 - b);
    return r;
}

template<int SGN, int LOGN>
__device__ __forceinline__ void fftreg(float* xr, float* xi) {
    const int N = 1 << LOGN;
    #pragma unroll
    for (int n = 1; n < N; n++) {
        const int r = brevN(n, LOGN);
        if (r > n) {
            float a = xr[n]; xr[n] = xr[r]; xr[r] = a;
            float b = xi[n]; xi[n] = xi[r]; xi[r] = b;
        }
    }
    #pragma unroll
    for (int s = 0; s < LOGN; s++) {
        const int half = 1 << s;
        #pragma unroll
        for (int j = 0; j < N/2; j++) {
            const int k  = j & (half - 1);
            const int g  = j >> s;
            const int i1 = g * (half << 1) + k;
            const int i2 = i1 + half;
            const float wr = twcos(k << (5 - s));
            const float wi = (float)SGN * twsin(k << (5 - s));
            float vr = xr[i2], vi = xi[i2];
            float tr = vr * wr - vi * wi;
            float ti = vr * wi + vi * wr;
            float ur = xr[i1], ui = xi[i1];
            xr[i1] = ur + tr;  xi[i1] = ui + ti;
            xr[i2] = ur - tr;  xi[i2] = ui - ti;
        }
    }
}

__device__ __forceinline__ float sigm(float v) { return 1.f / (1.f + __expf(-v)); }
__device__ __forceinline__ float ftanh(float v) { return 2.f / (1.f + __expf(-2.f*v)) - 1.f; }
__device__ __forceinline__ float2 h2f(__half2 h) { return __half22float2(h); }

// ================= 2-way split packed real-FFT pipeline ======================
__device__ __forceinline__ void irfft_build2(const __half2* __restrict__ A,
                                             int t, int hseg, float* zr, float* zi) {
    if (!hseg) {
        float2 x0  = h2f(A[t]);
        float2 x32 = h2f(A[32*64 + t]);
        float2 x16 = h2f(A[16*64 + t]);
        zr[0] = 0.5f*(x0.x + x32.x);   zi[0] = 0.5f*(x0.x - x32.x);
        zr[8] = x16.x;                 zi[8] = -x16.y;
        #pragma unroll
        for (int k = 2; k <= 14; k += 2) {
            float2 a = h2f(A[k*64 + t]);
            float2 b = h2f(A[(32-k)*64 + t]);
            float Sr = 0.5f*(a.x + b.x), Si = 0.5f*(a.y - b.y);
            float Dr = 0.5f*(a.x - b.x), Di = 0.5f*(a.y + b.y);
            const float c = twcos(k), s = twsin(k);
            float XoR = c*Dr - s*Di;
            float XoI = c*Di + s*Dr;
            zr[k/2]    = Sr - XoI;  zi[k/2]    = Si + XoR;
            zr[16-k/2] = Sr + XoI;  zi[16-k/2] = XoR - Si;
        }
    } else {
        #pragma unroll
        for (int k = 1; k <= 15; k += 2) {
            float2 a = h2f(A[k*64 + t]);
            float2 b = h2f(A[(32-k)*64 + t]);
            float Sr = 0.5f*(a.x + b.x), Si = 0.5f*(a.y - b.y);
            float Dr = 0.5f*(a.x - b.x), Di = 0.5f*(a.y + b.y);
            const float c = twcos(k), s = twsin(k);
            float XoR = c*Dr - s*Di;
            float XoI = c*Di + s*Dr;
            zr[(k-1)/2]      = Sr - XoI;  zi[(k-1)/2]      = Si + XoR;
            zr[15-(k-1)/2]   = Sr + XoI;  zi[15-(k-1)/2]   = XoR - Si;
        }
    }
    fftreg<1,4>(zr, zi);
    #pragma unroll
    for (int j = 0; j < 16; j++) {
        float br = __shfl_xor_sync(0xffffffffu, zr[j], 16);
        float bi = __shfl_xor_sync(0xffffffffu, zi[j], 16);
        const float c = twcos(2*j), s = twsin(2*j);
        if (!hseg) { zr[j] += br*c - bi*s;  zi[j] += br*s + bi*c; }
        else {
            float tr = zr[j]*c - zi[j]*s, ti = zr[j]*s + zi[j]*c;
            zr[j] = br - tr;  zi[j] = bi - ti;
        }
    }
}

__device__ __forceinline__ void rfft_store2(__half2* __restrict__ out,
                                            int t, int hseg, float* zr, float* zi) {
    #pragma unroll
    for (int j = 0; j < 16; j++) {
        float br = __shfl_xor_sync(0xffffffffu, zr[j], 16);
        float bi = __shfl_xor_sync(0xffffffffu, zi[j], 16);
        if (!hseg) { zr[j] += br;  zi[j] += bi; }
        else {
            float dr = br - zr[j], di = bi - zi[j];
            const float c = twcos(2*j), s = twsin(2*j);
            zr[j] = dr*c + di*s;
            zi[j] = di*c - dr*s;
        }
    }
    fftreg<-1,4>(zr, zi);
    if (!hseg) {
        out[0*64 + t]  = __floats2half2_rn(zr[0] + zi[0], 0.f);
        out[32*64 + t] = __floats2half2_rn(zr[0] - zi[0], 0.f);
        out[16*64 + t] = __floats2half2_rn(zr[8], -zi[8]);
        #pragma unroll
        for (int k = 2; k <= 14; k += 2) {
            const int m = k/2, mq = 16 - k/2;
            float XeR = 0.5f*(zr[m] + zr[mq]), XeI = 0.5f*(zi[m] - zi[mq]);
            float XoR = 0.5f*(zi[m] + zi[mq]), XoI = 0.5f*(zr[mq] - zr[m]);
            const float c = twcos(k), s = twsin(k);
            float wXoR = c*XoR + s*XoI;
            float wXoI = c*XoI - s*XoR;
            out[k*64 + t]      = __floats2half2_rn(XeR + wXoR, XeI + wXoI);
            out[(32-k)*64 + t] = __floats2half2_rn(XeR - wXoR, -(XeI - wXoI));
        }
    } else {
        #pragma unroll
        for (int k = 1; k <= 15; k += 2) {
            const int m = (k-1)/2, mq = 15 - (k-1)/2;
            float XeR = 0.5f*(zr[m] + zr[mq]), XeI = 0.5f*(zi[m] - zi[mq]);
            float XoR = 0.5f*(zi[m] + zi[mq]), XoI = 0.5f*(zr[mq] - zr[m]);
            const float c = twcos(k), s = twsin(k);
            float wXoR = c*XoR + s*XoI;
            float wXoI = c*XoI - s*XoR;
            out[k*64 + t]      = __floats2half2_rn(XeR + wXoR, XeI + wXoI);
            out[(32-k)*64 + t] = __floats2half2_rn(XeR - wXoR, -(XeI - wXoI));
        }
    }
}

// ---- single-thread forward rfft (prologue only) ----------------------------
__device__ __forceinline__ void rfft_store1(__half2* __restrict__ out, int t,
                                            float* zr, float* zi) {
    fftreg<-1,5>(zr, zi);
    out[0*64 + t]  = __floats2half2_rn(zr[0] + zi[0], 0.f);
    out[32*64 + t] = __floats2half2_rn(zr[0] - zi[0], 0.f);
    out[16*64 + t] = __floats2half2_rn(zr[16], -zi[16]);
    #pragma unroll
    for (int k = 1; k < 16; k++) {
        const int q = 32 - k;
        float XeR = 0.5f*(zr[k] + zr[q]), XeI = 0.5f*(zi[k] - zi[q]);
        float XoR = 0.5f*(zi[k] + zi[q]), XoI = 0.5f*(zr[q] - zr[k]);
        const float c = twcos(k), s = twsin(k);
        float wXoR = c*XoR + s*XoI;
        float wXoI = c*XoI - s*XoR;
        out[k*64 + t] = __floats2half2_rn(XeR + wXoR, XeI + wXoI);
        out[q*64 + t] = __floats2half2_rn(XeR - wXoR, -(XeI - wXoI));
    }
}

// ---------------- weight transpose: [i][o][f] -> [f][p][w=i][o] compact fp16 -
__global__ void k_wt_all(const float* __restrict__ p0r, const float* __restrict__ p0i,
                         const float* __restrict__ p1r, const float* __restrict__ p1i,
                         const float* __restrict__ p2r, const float* __restrict__ p2i) {
    __shared__ float s_r[64*65];
    __shared__ float s_i[64*65];
    int gate = blockIdx.z;
    const float* wr = gate == 0 ? p0r : (gate == 1 ? p1r : p2r);
    const float* wi = gate == 0 ? p0i : (gate == 1 ? p1i : p2i);
    int f0  = blockIdx.x * 64;
    int io0 = blockIdx.y * 64;
    int lane = threadIdx.x & 63;
    int row  = threadIdx.x >> 6;
    #pragma unroll
    for (int r = row; r < 64; r += 4) {
        s_r[r*65 + lane] = wr[(size_t)(io0 + r) * NF + f0 + lane];
        s_i[r*65 + lane] = wi[(size_t)(io0 + r) * NF + f0 + lane];
    }
    __syncthreads();
    __half* out = d_Wt[gate];
    #pragma unroll
    for (int fl = row; fl < 64; fl += 4) {
        size_t base = (size_t)(f0 + fl) * WFS + (size_t)blockIdx.y * 64 + lane;
        out[base]        = __float2half_rn(s_r[lane*65 + fl]);
        out[base + 4096] = __float2half_rn(s_i[lane*65 + fl]);
    }
}

// ---------------- h0 = x @ Wi + bi (CIN=1) ----------------------------------
__global__ void k_init_h(const float* __restrict__ x, const float* __restrict__ Wi,
                         const float* __restrict__ bi) {
    int idx = blockIdx.x * 256 + threadIdx.x;
    int bw = idx >> 12;
    int xy = idx & 4095;
    int b = bw >> 6, w = bw & 63;
    d_h[idx] = x[b * TILE + xy] * Wi[w] + bi[w];
}

// ---------------- prologue: y-rfft of h (runs once) --------------------------
__global__ void k_fwd1() {
    int bw = blockIdx.x, t = threadIdx.x;
    const float4* row = reinterpret_cast<const float4*>(d_h + (size_t)bw * TILE + t*64);
    float zr[32], zi[32];
    #pragma unroll
    for (int j = 0; j < 16; j++) {
        float4 v = row[j];
        zr[2*j] = v.x; zi[2*j] = v.y; zr[2*j+1] = v.z; zi[2*j+1] = v.w;
    }
    rfft_store1(d_A1 + (size_t)bw * YHN * 64, t, zr, zi);
}

// ---------------- x-FFT (4-way DIF): d_A1[bw][k][x] -> d_Hf[f][bw] -----------
__global__ void k_fwd2() {
    pdl_wait();
    int k = blockIdx.x;
    int lane = threadIdx.x & 31;
    int wid  = threadIdx.x >> 5;
    int q = lane >> 3;
    int r = lane & 7;
    int bw = blockIdx.y * 32 + wid * 8 + r;
    bool qlo1 = (q < 2);
    bool qodd = (q & 1);

    float ar[16], ai[16];
    const uint4* src = reinterpret_cast<const uint4*>(
        d_A1 + ((size_t)bw*YHN + k)*64 + 16*q);
    #pragma unroll
    for (int j = 0; j < 4; j++) {
        uint4 v = src[j];
        float2 c0 = h2f(*reinterpret_cast<__half2*>(&v.x));
        float2 c1 = h2f(*reinterpret_cast<__half2*>(&v.y));
        float2 c2 = h2f(*reinterpret_cast<__half2*>(&v.z));
        float2 c3 = h2f(*reinterpret_cast<__half2*>(&v.w));
        ar[4*j+0] = c0.x; ai[4*j+0] = c0.y;
        ar[4*j+1] = c1.x; ai[4*j+1] = c1.y;
        ar[4*j+2] = c2.x; ai[4*j+2] = c2.y;
        ar[4*j+3] = c3.x; ai[4*j+3] = c3.y;
    }
    #pragma unroll
    for (int j = 0; j < 16; j++) {
        float br = __shfl_xor_sync(0xffffffffu, ar[j], 16);
        float bi = __shfl_xor_sync(0xffffffffu, ai[j], 16);
        if (qlo1) { ar[j] += br;  ai[j] += bi; }
        else {
            float dr = br - ar[j], di = bi - ai[j];
            const float cj = twcos(j), sj = twsin(j);
            float c = qodd ? -sj : cj;
            float s = qodd ?  cj : sj;
            ar[j] = dr*c + di*s;
            ai[j] = di*c - dr*s;
        }
    }
    #pragma unroll
    for (int j = 0; j < 16; j++) {
        float br = __shfl_xor_sync(0xffffffffu, ar[j], 8);
        float bi = __shfl_xor_sync(0xffffffffu, ai[j], 8);
        if (!qodd) { ar[j] += br;  ai[j] += bi; }
        else {
            float dr = br - ar[j], di = bi - ai[j];
            const float c = twcos(2*j), s = twsin(2*j);
            ar[j] = dr*c + di*s;
            ai[j] = di*c - dr*s;
        }
    }
    fftreg<-1,4>(ar, ai);
    pdl_trigger();
    int cq = ((q & 1) << 1) | (q >> 1);
    #pragma unroll
    for (int m = 0; m < 16; m++)
        d_Hf[((size_t)(4*m + cq)*YHN + k)*BWN + bw] = __floats2half2_rn(ar[m], ai[m]);
}

// ---------------- per-frequency complex GEMM via tensor cores ----------------
__global__ void k_gemm(int pass) {
    pdl_wait();
    int f = blockIdx.x;
    __shared__ __align__(16) __half sHr[16*LDH];
    __shared__ __align__(16) __half sHi[16*LDH];
    __shared__ __align__(16) __half sW[2*64*LDW];
    int tid = threadIdx.x;             // 128
    int lane = tid & 31, wid = tid >> 5;

    const __half2* Hsrc = d_Hf + (size_t)f * BWN;
    #pragma unroll
    for (int i = tid; i < BWN; i += 128) {
        __half2 v = Hsrc[i];
        int b = i >> 6, w = i & 63;
        sHr[b*LDH + w] = __low2half(v);
        sHi[b*LDH + w] = __high2half(v);
    }

    const int obase = wid * 16;
    const u32 baseHr = smem_u32(sHr);
    const u32 baseHi = smem_u32(sHi);
    const u32 baseW  = smem_u32(sW);
    const int arow = lane & 15, acol = (lane >> 4) * 8;
    const int ngates = (pass == 0) ? 2 : 1;

    for (int g = 0; g < ngates; g++) {
        const __half* Wg = d_Wt[pass == 0 ? g : 2] + (size_t)f * WFS;
        __half2* O = (pass == 0 && g == 1) ? d_F1 : d_F0;

        __syncthreads();
        {
            // compact global [128 rows x 64 halfs] -> padded smem rows of 72
            const uint4* src = reinterpret_cast<const uint4*>(Wg);
            uint4* dst = reinterpret_cast<uint4*>(sW);
            #pragma unroll
            for (int i = tid; i < 1024; i += 128) dst[(i >> 3)*9 + (i & 7)] = src[i];
        }
        __syncthreads();

        float cr[2][4] = {{0.f,0.f,0.f,0.f},{0.f,0.f,0.f,0.f}};
        float ci[2][4] = {{0.f,0.f,0.f,0.f},{0.f,0.f,0.f,0.f}};

        #pragma unroll
        for (int kk = 0; kk < 4; kk++) {
            u32 Ar[4], Ai[4], An[4];
            u32 aoff = (u32)((arow*LDH + kk*16 + acol) * 2);
            ldsm_x4(Ar[0], Ar[1], Ar[2], Ar[3], baseHr + aoff);
            ldsm_x4(Ai[0], Ai[1], Ai[2], Ai[3], baseHi + aoff);
            #pragma unroll
            for (int j = 0; j < 4; j++) An[j] = Ai[j] ^ 0x80008000u;

            u32 Br[4], Bi[4];
            u32 boff = (u32)(((kk*16 + (lane & 15))*LDW
                              + obase + (lane >> 4)*8) * 2);
            ldsm_x4t(Br[0], Br[1], Br[2], Br[3], baseW + boff);
            ldsm_x4t(Bi[0], Bi[1], Bi[2], Bi[3], baseW + (u32)(64*LDW*2) + boff);

            #pragma unroll
            for (int nt = 0; nt < 2; nt++) {
                mma16816(cr[nt], Ar, Br[2*nt], Br[2*nt+1]);
                mma16816(cr[nt], An, Bi[2*nt], Bi[2*nt+1]);
                mma16816(ci[nt], Ar, Bi[2*nt], Bi[2*nt+1]);
                mma16816(ci[nt], Ai, Br[2*nt], Br[2*nt+1]);
            }
        }

        if (g == ngates - 1) pdl_trigger();
        __half2* Of = O + (size_t)f * BWN;
        int b0 = lane >> 2, oc = (lane & 3) * 2;
        #pragma unroll
        for (int nt = 0; nt < 2; nt++) {
            int o = obase + nt*8 + oc;
            __half2 p00 = __floats2half2_rn(cr[nt][0], ci[nt][0]);
            __half2 p01 = __floats2half2_rn(cr[nt][1], ci[nt][1]);
            uint2 u0;
            u0.x = *reinterpret_cast<u32*>(&p00);
            u0.y = *reinterpret_cast<u32*>(&p01);
            *reinterpret_cast<uint2*>(Of + b0*64 + o) = u0;
            __half2 p10 = __floats2half2_rn(cr[nt][2], ci[nt][2]);
            __half2 p11 = __floats2half2_rn(cr[nt][3], ci[nt][3]);
            uint2 u1;
            u1.x = *reinterpret_cast<u32*>(&p10);
            u1.y = *reinterpret_cast<u32*>(&p11);
            *reinterpret_cast<uint2*>(Of + (b0+8)*64 + o) = u1;
        }
    }
}

// ---------------- inverse x-FFT (4-way DIT): d_F -> d_Ax ---------------------
__global__ void k_inv1(int pass) {
    pdl_wait();
    int k = blockIdx.x;
    int lane = threadIdx.x & 31;
    int wid  = threadIdx.x >> 5;
    int q = lane >> 3;
    int r = lane & 7;
    int bw = blockIdx.y * 32 + wid * 8 + r;
    bool qlo1 = (q < 2);
    bool qodd = (q & 1);
    const __half2* F = (pass == 0 && blockIdx.z == 1) ? d_F1 : d_F0;
    __half2* A = (pass == 1 || blockIdx.z == 1) ? d_Ax1 : d_Ax0;

    int cq = ((q & 1) << 1) | (q >> 1);
    float ar[16], ai[16];
    #pragma unroll
    for (int m = 0; m < 16; m++) {
        float2 v = h2f(F[((size_t)(4*m + cq)*YHN + k)*BWN + bw]);
        ar[m] = v.x; ai[m] = v.y;
    }
    fftreg<1,4>(ar, ai);
    #pragma unroll
    for (int j = 0; j < 16; j++) {
        float br = __shfl_xor_sync(0xffffffffu, ar[j], 8);
        float bi = __shfl_xor_sync(0xffffffffu, ai[j], 8);
        const float c = twcos(2*j), s = twsin(2*j);
        if (!qodd) { ar[j] += br*c - bi*s;  ai[j] += br*s + bi*c; }
        else {
            float tr = ar[j]*c - ai[j]*s, ti = ar[j]*s + ai[j]*c;
            ar[j] = br - tr;  ai[j] = bi - ti;
        }
    }
    #pragma unroll
    for (int j = 0; j < 16; j++) {
        float br = __shfl_xor_sync(0xffffffffu, ar[j], 16);
        float bi = __shfl_xor_sync(0xffffffffu, ai[j], 16);
        const float cj = twcos(j), sj = twsin(j);
        float c = qodd ? -sj : cj;
        float s = qodd ?  cj : sj;
        if (qlo1) { ar[j] += br*c - bi*s;  ai[j] += br*s + bi*c; }
        else {
            float tr = ar[j]*c - ai[j]*s, ti = ar[j]*s + ai[j]*c;
            ar[j] = br - tr;  ai[j] = bi - ti;
        }
    }
    pdl_trigger();
    uint2* dst = reinterpret_cast<uint2*>(A + ((size_t)bw*YHN + k)*64 + 16*q);
    #pragma unroll
    for (int j = 0; j < 8; j++) {
        __half2 h0 = __floats2half2_rn(ar[2*j],   ai[2*j]);
        __half2 h1 = __floats2half2_rn(ar[2*j+1], ai[2*j+1]);
        uint2 u;
        u.x = *reinterpret_cast<u32*>(&h0);
        u.y = *reinterpret_cast<u32*>(&h1);
        dst[j] = u;
    }
}

// ---------------- fused: g = sigm(irfft(Ax1))*h, y-rfft(g) -------------------
__global__ void k_fused_zr() {
    pdl_wait();
    int bw = blockIdx.x;
    int lane = threadIdx.x & 31, wid = threadIdx.x >> 5;
    int t = wid*16 + (lane & 15);
    int hseg = lane >> 4;
    const float sc = 1.f / 2048.f;
    float zr[16], zi[16];
    irfft_build2(d_Ax1 + (size_t)bw * YHN * 64, t, hseg, zr, zi);
    const float4* hrow = reinterpret_cast<const float4*>(
        d_h + (size_t)bw * TILE + t*64 + 32*hseg);
    #pragma unroll
    for (int j = 0; j < 8; j++) {
        float4 h4 = hrow[j];
        zr[2*j]   = h4.x * sigm(zr[2*j]*sc);
        zi[2*j]   = h4.y * sigm(zi[2*j]*sc);
        zr[2*j+1] = h4.z * sigm(zr[2*j+1]*sc);
        zi[2*j+1] = h4.w * sigm(zi[2*j+1]*sc);
    }
    pdl_trigger();
    rfft_store2(d_A1 + (size_t)bw * YHN * 64, t, hseg, zr, zi);
}

// ---------------- fused: z = sigm(irfft(Ax0)), h += z(tanh(irfft(Ax1)) - h) --
__global__ void k_fused_h(int last) {
    pdl_wait();
    int bw = blockIdx.x;
    int lane = threadIdx.x & 31, wid = threadIdx.x >> 5;
    int t = wid*16 + (lane & 15);
    int hseg = lane >> 4;
    const float sc = 1.f / 2048.f;
    float zvr[16], zvi[16];
    irfft_build2(d_Ax0 + (size_t)bw * YHN * 64, t, hseg, zvr, zvi);
    #pragma unroll
    for (int j = 0; j < 16; j++) { zvr[j] = sigm(zvr[j]*sc); zvi[j] = sigm(zvi[j]*sc); }
    float nr[16], ni[16];
    irfft_build2(d_Ax1 + (size_t)bw * YHN * 64, t, hseg, nr, ni);
    pdl_trigger();
    float4* hrow = reinterpret_cast<float4*>(
        d_h + (size_t)bw * TILE + t*64 + 32*hseg);
    #pragma unroll
    for (int j = 0; j < 8; j++) {
        float4 h4 = hrow[j];
        float n0 = ftanh(nr[2*j]*sc),   n1 = ftanh(ni[2*j]*sc);
        float n2 = ftanh(nr[2*j+1]*sc), n3 = ftanh(ni[2*j+1]*sc);
        h4.x += zvr[2*j]   * (n0 - h4.x);
        h4.y += zvi[2*j]   * (n1 - h4.y);
        h4.z += zvr[2*j+1] * (n2 - h4.z);
        h4.w += zvi[2*j+1] * (n3 - h4.w);
        hrow[j] = h4;
        nr[2*j] = h4.x; ni[2*j] = h4.y; nr[2*j+1] = h4.z; ni[2*j+1] = h4.w;
    }
    if (!last)
        rfft_store2(d_A1 + (size_t)bw * YHN * 64, t, hseg, nr, ni);
}

// ---------------- out mapping: y = h @ Wo + bo (4-way w-split) ---------------
__global__ void k_out(const float* __restrict__ Wo, const float* __restrict__ bo,
                      float* __restrict__ out, int t) {
    __shared__ float sp[3*256];
    pdl_wait();
    int b = blockIdx.x;
    int xyl = threadIdx.x & 255;
    int xy = blockIdx.y * 256 + xyl;
    int wq = threadIdx.x >> 8;       // 0..3
    float acc = 0.f;
    const float* hb = d_h + (size_t)(b*64 + wq*16) * TILE + xy;
    #pragma unroll
    for (int w = 0; w < 16; w++)
        acc += hb[(size_t)w * TILE] * __ldg(&Wo[wq*16 + w]);
    if (wq > 0) sp[(wq-1)*256 + xyl] = acc;
    __syncthreads();
    pdl_trigger();
    if (wq == 0) {
        acc += sp[xyl] + sp[256 + xyl] + sp[512 + xyl] + bo[0];
        out[(size_t)(b*TT + t) * TILE + xy] = acc;
    }
}

// ---------------- PDL launch helper ------------------------------------------
template<typename... A, typename... B>
static inline void pdl_launch(void(*kern)(A...), dim3 grid, dim3 block, B... args) {
    cudaLaunchConfig_t cfg = {};
    cfg.gridDim = grid;
    cfg.blockDim = block;
    cfg.stream = 0;
    cudaLaunchAttribute at[1];
    at[0].id = cudaLaunchAttributeProgrammaticStreamSerialization;
    at[0].val.programmaticStreamSerializationAllowed = 1;
    cfg.attrs = at;
    cfg.numAttrs = 1;
    cudaLaunchKernelEx(&cfg, kern, (A)args...);
}

// ---------------- launch -----------------------------------------------------
extern "C" void kernel_launch(void* const* d_in, const int* in_sizes, int n_in,
                              void* d_out, int out_size) {
    int iX = 0, iWi = 2, iBi = 3, iWo = 4, iBo = 5, iWz = 6;
    if (n_in == 11) { iWi = 1; iBi = 2; iWo = 3; iBo = 4; iWz = 5; }

    const float* x    = (const float*)d_in[iX];
    const float* Wi   = (const float*)d_in[iWi];
    const float* bi   = (const float*)d_in[iBi];
    const float* Wo   = (const float*)d_in[iWo];
    const float* bo   = (const float*)d_in[iBo];
    float* out = (float*)d_out;

    k_wt_all<<<dim3(33, 64, 3), 256>>>((const float*)d_in[iWz+0], (const float*)d_in[iWz+1],
                                       (const float*)d_in[iWz+2], (const float*)d_in[iWz+3],
                                       (const float*)d_in[iWz+4], (const float*)d_in[iWz+5]);
    k_init_h<<<(BWN*TILE)/256, 256>>>(x, Wi, bi);
    k_fwd1<<<BWN, 64>>>();
    k_fwd2<<<dim3(YHN, 32), 128>>>();

    for (int t = 0; t < TT; t++) {
        pdl_launch(k_gemm, dim3(NF), dim3(128), 0);              // z->F0, r->F1
        pdl_launch(k_inv1, dim3(YHN, 32, 2), dim3(128), 0);      // F0->Ax0, F1->Ax1
        pdl_launch(k_fused_zr, dim3(BWN), dim3(128));            // g = r*h, y-rfft
        pdl_launch(k_fwd2, dim3(YHN, 32), dim3(128));            // x-FFT(g) -> Hf
        pdl_launch(k_gemm, dim3(NF), dim3(128), 1);              // nh -> F0
        pdl_launch(k_inv1, dim3(YHN, 32, 1), dim3(128), 1);      // F0 -> Ax1
        pdl_launch(k_fused_h, dim3(BWN), dim3(128), (int)(t == TT-1));
        if (t < TT-1) pdl_launch(k_fwd2, dim3(YHN, 32), dim3(128));
        pdl_launch(k_out, dim3(BB, TILE/256), dim3(1024), Wo, bo, out, t);
    }
}